// round 1
// baseline (speedup 1.0000x reference)
#include <cuda_runtime.h>
#include <math.h>

// Problem constants
#define BATCH 32
#define SEQ   512
#define CDIM  512
#define NHEAD 8
#define DHEAD 64
#define MROWS (BATCH * SEQ)        // 16384
#define FFNDIM (4 * CDIM)          // 2048

// Scratch (allocation-free rule: __device__ globals)
__device__ float g_h  [MROWS * CDIM];   // ln1 out
__device__ float g_q  [MROWS * CDIM];   // q in [ (b*T+t), h*64+d ] layout
__device__ float g_k  [MROWS * CDIM];
__device__ float g_v  [MROWS * CDIM];
__device__ float g_o  [MROWS * CDIM];   // attention out (heads concat)
__device__ float g_h2 [MROWS * CDIM];   // ln2 out
__device__ float g_ffn[MROWS * FFNDIM]; // relu(h2@w1+b1)

// ---------------------------------------------------------------------------
// LayerNorm: one block per row (C=512), 128 threads, float4 per thread
// ---------------------------------------------------------------------------
__global__ void __launch_bounds__(128) ln_kernel(
    const float* __restrict__ x, const float* __restrict__ g,
    const float* __restrict__ b, float* __restrict__ out)
{
    const int row = blockIdx.x;
    const int tid = threadIdx.x;
    const float* xr = x + (size_t)row * CDIM;

    float4 v = *reinterpret_cast<const float4*>(&xr[tid * 4]);
    float s  = v.x + v.y + v.z + v.w;
    float ss = v.x*v.x + v.y*v.y + v.z*v.z + v.w*v.w;

    #pragma unroll
    for (int off = 16; off > 0; off >>= 1) {
        s  += __shfl_xor_sync(0xffffffffu, s,  off);
        ss += __shfl_xor_sync(0xffffffffu, ss, off);
    }
    __shared__ float sm[4], sm2[4];
    const int wid = tid >> 5, lane = tid & 31;
    if (lane == 0) { sm[wid] = s; sm2[wid] = ss; }
    __syncthreads();
    s  = sm[0] + sm[1] + sm[2] + sm[3];
    ss = sm2[0] + sm2[1] + sm2[2] + sm2[3];

    const float mu   = s * (1.0f / CDIM);
    const float var  = ss * (1.0f / CDIM) - mu * mu;
    const float rstd = rsqrtf(var + 1e-5f);

    float4 gg = *reinterpret_cast<const float4*>(&g[tid * 4]);
    float4 bb = *reinterpret_cast<const float4*>(&b[tid * 4]);
    float4 o;
    o.x = (v.x - mu) * rstd * gg.x + bb.x;
    o.y = (v.y - mu) * rstd * gg.y + bb.y;
    o.z = (v.z - mu) * rstd * gg.z + bb.z;
    o.w = (v.w - mu) * rstd * gg.w + bb.w;
    *reinterpret_cast<float4*>(&out[(size_t)row * CDIM + tid * 4]) = o;
}

// ---------------------------------------------------------------------------
// SGEMM: C[M,N] = A[M,K] @ B[K,N] (+bias)(+residual)(relu)
// BM=BN=128, BK=16, 256 threads, 8x8 microtile.
// HEADB: B is wq/wk/wv with layout [H, C, D] -> element(k,n) =
//        B[(n>>6)*C*64 + k*64 + (n&63)]
// ---------------------------------------------------------------------------
template<bool HEADB, bool BIAS, bool RELU, bool RES>
__global__ void __launch_bounds__(256) gemm128(
    const float* __restrict__ A, const float* __restrict__ B,
    const float* __restrict__ bias, const float* __restrict__ res,
    float* __restrict__ C, int M, int N, int K)
{
    constexpr int BM = 128, BN = 128, BK = 16;
    __shared__ float As[BK][BM];
    __shared__ float Bs[BK][BN];

    const int tid = threadIdx.x;
    const int m0 = blockIdx.y * BM;
    const int n0 = blockIdx.x * BN;
    const int tx = tid & 15;
    const int ty = tid >> 4;

    float acc[8][8];
    #pragma unroll
    for (int i = 0; i < 8; i++)
        #pragma unroll
        for (int j = 0; j < 8; j++) acc[i][j] = 0.0f;

    for (int k0 = 0; k0 < K; k0 += BK) {
        // Load A tile (128x16) -> As transposed
        #pragma unroll
        for (int r = 0; r < 2; r++) {
            int lin = tid + r * 256;          // 0..511 float4s
            int row = lin >> 2;               // 0..127
            int kc  = (lin & 3) * 4;          // 0,4,8,12
            float4 v = *reinterpret_cast<const float4*>(
                &A[(size_t)(m0 + row) * K + k0 + kc]);
            As[kc + 0][row] = v.x;
            As[kc + 1][row] = v.y;
            As[kc + 2][row] = v.z;
            As[kc + 3][row] = v.w;
        }
        // Load B tile (16x128)
        #pragma unroll
        for (int r = 0; r < 2; r++) {
            int lin  = tid + r * 256;
            int krow = lin >> 5;              // 0..15
            int nc   = (lin & 31) * 4;        // 0..124
            int n    = n0 + nc;
            float4 v;
            if (HEADB) {
                v = *reinterpret_cast<const float4*>(
                    &B[(size_t)(n >> 6) * (CDIM * DHEAD) +
                       (size_t)(k0 + krow) * DHEAD + (n & 63)]);
            } else {
                v = *reinterpret_cast<const float4*>(
                    &B[(size_t)(k0 + krow) * N + n]);
            }
            *reinterpret_cast<float4*>(&Bs[krow][nc]) = v;
        }
        __syncthreads();

        #pragma unroll
        for (int kk = 0; kk < BK; kk++) {
            float a[8], b[8];
            *reinterpret_cast<float4*>(&a[0]) =
                *reinterpret_cast<const float4*>(&As[kk][ty * 8]);
            *reinterpret_cast<float4*>(&a[4]) =
                *reinterpret_cast<const float4*>(&As[kk][ty * 8 + 4]);
            *reinterpret_cast<float4*>(&b[0]) =
                *reinterpret_cast<const float4*>(&Bs[kk][tx * 8]);
            *reinterpret_cast<float4*>(&b[4]) =
                *reinterpret_cast<const float4*>(&Bs[kk][tx * 8 + 4]);
            #pragma unroll
            for (int i = 0; i < 8; i++)
                #pragma unroll
                for (int j = 0; j < 8; j++)
                    acc[i][j] = fmaf(a[i], b[j], acc[i][j]);
        }
        __syncthreads();
    }

    // Epilogue
    #pragma unroll
    for (int i = 0; i < 8; i++) {
        const int row = m0 + ty * 8 + i;
        #pragma unroll
        for (int j = 0; j < 8; j += 4) {
            const int col = n0 + tx * 8 + j;
            float4 v = make_float4(acc[i][j], acc[i][j+1], acc[i][j+2], acc[i][j+3]);
            if (BIAS) {
                float4 bb = *reinterpret_cast<const float4*>(&bias[col]);
                v.x += bb.x; v.y += bb.y; v.z += bb.z; v.w += bb.w;
            }
            if (RES) {
                float4 rr = *reinterpret_cast<const float4*>(
                    &res[(size_t)row * N + col]);
                v.x += rr.x; v.y += rr.y; v.z += rr.z; v.w += rr.w;
            }
            if (RELU) {
                v.x = fmaxf(v.x, 0.0f); v.y = fmaxf(v.y, 0.0f);
                v.z = fmaxf(v.z, 0.0f); v.w = fmaxf(v.w, 0.0f);
            }
            *reinterpret_cast<float4*>(&C[(size_t)row * N + col]) = v;
        }
    }
}

// ---------------------------------------------------------------------------
// Causal attention (flash-style online softmax).
// grid = (T/128, B*H), block = 128. One thread = one query row.
// K/V tiles of 32 keys staged in smem; score/ov reads are smem broadcasts.
// ---------------------------------------------------------------------------
#define KT 32
__global__ void __launch_bounds__(128) attn_kernel(
    const float* __restrict__ q, const float* __restrict__ k,
    const float* __restrict__ v, float* __restrict__ o)
{
    const int qt  = blockIdx.x;             // 0..3
    const int bh  = blockIdx.y;             // 0..255
    const int b   = bh >> 3;
    const int h   = bh & 7;
    const int tid = threadIdx.x;
    const int t   = qt * 128 + tid;

    const float scale = 0.04419417382415922f;   // 1/sqrt(512)

    const float* qrow  = q + ((size_t)(b * SEQ + t)) * CDIM + h * DHEAD;
    const float* kbase = k + ((size_t)b * SEQ) * CDIM + h * DHEAD;
    const float* vbase = v + ((size_t)b * SEQ) * CDIM + h * DHEAD;

    float qr[DHEAD];
    #pragma unroll
    for (int d4 = 0; d4 < 16; d4++) {
        float4 t4 = *reinterpret_cast<const float4*>(&qrow[d4 * 4]);
        qr[d4*4+0] = t4.x; qr[d4*4+1] = t4.y; qr[d4*4+2] = t4.z; qr[d4*4+3] = t4.w;
    }

    float oacc[DHEAD];
    #pragma unroll
    for (int d = 0; d < DHEAD; d++) oacc[d] = 0.0f;
    float m = -INFINITY, l = 0.0f;

    __shared__ float ks[KT][DHEAD];
    __shared__ float vs[KT][DHEAD];

    const int tmax = qt * 128 + 127;
    for (int j0 = 0; j0 <= tmax; j0 += KT) {
        // Cooperative tile load (coalesced float4)
        #pragma unroll
        for (int r = 0; r < 4; r++) {
            int lin = (r * 128 + tid) * 4;      // 0..2047
            int j = lin >> 6, d = lin & 63;
            *reinterpret_cast<float4*>(&ks[j][d]) =
                *reinterpret_cast<const float4*>(&kbase[(size_t)(j0 + j) * CDIM + d]);
            *reinterpret_cast<float4*>(&vs[j][d]) =
                *reinterpret_cast<const float4*>(&vbase[(size_t)(j0 + j) * CDIM + d]);
        }
        __syncthreads();

        if (j0 <= t) {
            float s[KT];
            float tile_max = -INFINITY;
            #pragma unroll
            for (int j = 0; j < KT; j++) {
                float acc = 0.0f;
                #pragma unroll
                for (int d4 = 0; d4 < 16; d4++) {
                    float4 kk = *reinterpret_cast<const float4*>(&ks[j][d4 * 4]);
                    acc = fmaf(qr[d4*4+0], kk.x, acc);
                    acc = fmaf(qr[d4*4+1], kk.y, acc);
                    acc = fmaf(qr[d4*4+2], kk.z, acc);
                    acc = fmaf(qr[d4*4+3], kk.w, acc);
                }
                s[j] = (j0 + j <= t) ? acc * scale : -INFINITY;
                tile_max = fmaxf(tile_max, s[j]);
            }
            const float mnew = fmaxf(m, tile_max);
            const float c = __expf(m - mnew);   // exp(-inf)=0 on first tile
            m = mnew;
            l *= c;
            #pragma unroll
            for (int d = 0; d < DHEAD; d++) oacc[d] *= c;

            #pragma unroll
            for (int j = 0; j < KT; j++) {
                const float p = __expf(s[j] - m);
                l += p;
                #pragma unroll
                for (int d4 = 0; d4 < 16; d4++) {
                    float4 vv = *reinterpret_cast<const float4*>(&vs[j][d4 * 4]);
                    oacc[d4*4+0] = fmaf(p, vv.x, oacc[d4*4+0]);
                    oacc[d4*4+1] = fmaf(p, vv.y, oacc[d4*4+1]);
                    oacc[d4*4+2] = fmaf(p, vv.z, oacc[d4*4+2]);
                    oacc[d4*4+3] = fmaf(p, vv.w, oacc[d4*4+3]);
                }
            }
        }
        __syncthreads();
    }

    const float inv = 1.0f / l;
    float* orow = o + ((size_t)(b * SEQ + t)) * CDIM + h * DHEAD;
    #pragma unroll
    for (int d4 = 0; d4 < 16; d4++) {
        float4 w = make_float4(oacc[d4*4+0] * inv, oacc[d4*4+1] * inv,
                               oacc[d4*4+2] * inv, oacc[d4*4+3] * inv);
        *reinterpret_cast<float4*>(&orow[d4 * 4]) = w;
    }
}

// ---------------------------------------------------------------------------
// Launch. Inputs (metadata order):
// 0:x 1:wq 2:wk 3:wv 4:w_proj 5:b_proj 6:w1 7:b1 8:w2 9:b2
// 10:ln1_g 11:ln1_b 12:ln2_g 13:ln2_b
// ---------------------------------------------------------------------------
extern "C" void kernel_launch(void* const* d_in, const int* in_sizes, int n_in,
                              void* d_out, int out_size)
{
    const float* x      = (const float*)d_in[0];
    const float* wq     = (const float*)d_in[1];
    const float* wk     = (const float*)d_in[2];
    const float* wv     = (const float*)d_in[3];
    const float* w_proj = (const float*)d_in[4];
    const float* b_proj = (const float*)d_in[5];
    const float* w1     = (const float*)d_in[6];
    const float* b1     = (const float*)d_in[7];
    const float* w2     = (const float*)d_in[8];
    const float* b2     = (const float*)d_in[9];
    const float* ln1_g  = (const float*)d_in[10];
    const float* ln1_b  = (const float*)d_in[11];
    const float* ln2_g  = (const float*)d_in[12];
    const float* ln2_b  = (const float*)d_in[13];
    float* out = (float*)d_out;

    float *h, *qb, *kb, *vb, *ob, *h2, *ffn;
    cudaGetSymbolAddress((void**)&h,   g_h);
    cudaGetSymbolAddress((void**)&qb,  g_q);
    cudaGetSymbolAddress((void**)&kb,  g_k);
    cudaGetSymbolAddress((void**)&vb,  g_v);
    cudaGetSymbolAddress((void**)&ob,  g_o);
    cudaGetSymbolAddress((void**)&h2,  g_h2);
    cudaGetSymbolAddress((void**)&ffn, g_ffn);

    const int M = MROWS;

    // ln1
    ln_kernel<<<M, 128>>>(x, ln1_g, ln1_b, h);

    // q, k, v projections (head-interleaved weights read in place)
    gemm128<true,  false, false, false><<<dim3(CDIM/128, M/128), 256>>>(
        h, wq, nullptr, nullptr, qb, M, CDIM, CDIM);
    gemm128<true,  false, false, false><<<dim3(CDIM/128, M/128), 256>>>(
        h, wk, nullptr, nullptr, kb, M, CDIM, CDIM);
    gemm128<true,  false, false, false><<<dim3(CDIM/128, M/128), 256>>>(
        h, wv, nullptr, nullptr, vb, M, CDIM, CDIM);

    // causal attention
    attn_kernel<<<dim3(SEQ/128, BATCH*NHEAD), 128>>>(qb, kb, vb, ob);

    // x2 = x + o @ w_proj + b_proj  -> out
    gemm128<false, true,  false, true ><<<dim3(CDIM/128, M/128), 256>>>(
        ob, w_proj, b_proj, x, out, M, CDIM, CDIM);

    // ln2
    ln_kernel<<<M, 128>>>(out, ln2_g, ln2_b, h2);

    // ffn1 = relu(h2 @ w1 + b1)
    gemm128<false, true,  true,  false><<<dim3(FFNDIM/128, M/128), 256>>>(
        h2, w1, b1, nullptr, ffn, M, FFNDIM, CDIM);

    // out = out + ffn1 @ w2 + b2
    gemm128<false, true,  false, true ><<<dim3(CDIM/128, M/128), 256>>>(
        ffn, w2, b2, out, out, M, CDIM, FFNDIM);
}

// round 2
// speedup vs baseline: 2.0531x; 2.0531x over previous
#include <cuda_runtime.h>
#include <math.h>
#include <stdint.h>

// Problem constants
#define BATCH 32
#define SEQ   512
#define CDIM  512
#define NHEAD 8
#define DHEAD 64
#define MROWS (BATCH * SEQ)        // 16384
#define FFNDIM (4 * CDIM)          // 2048

// Scratch (allocation-free rule: __device__ globals)
__device__ float g_h  [MROWS * CDIM];   // ln1 out
__device__ float g_q  [MROWS * CDIM];
__device__ float g_k  [MROWS * CDIM];
__device__ float g_v  [MROWS * CDIM];
__device__ float g_o  [MROWS * CDIM];
__device__ float g_h2 [MROWS * CDIM];
__device__ float g_ffn[MROWS * FFNDIM];

// ---------------------------------------------------------------------------
// Helpers: tf32 round + mma
// ---------------------------------------------------------------------------
__device__ __forceinline__ float to_tf32(float x) {
    float r;
    asm("cvt.rna.tf32.f32 %0, %1;" : "=f"(r) : "f"(x));
    return r;
}

__device__ __forceinline__ void mma_tf32(float* c, const uint32_t* a, const uint32_t* b) {
    asm volatile(
        "mma.sync.aligned.m16n8k8.row.col.f32.tf32.tf32.f32 "
        "{%0,%1,%2,%3},{%4,%5,%6,%7},{%8,%9},{%0,%1,%2,%3};"
        : "+f"(c[0]), "+f"(c[1]), "+f"(c[2]), "+f"(c[3])
        : "r"(a[0]), "r"(a[1]), "r"(a[2]), "r"(a[3]),
          "r"(b[0]), "r"(b[1]));
}

// ---------------------------------------------------------------------------
// LayerNorm: one block per row (C=512), 128 threads, float4 per thread
// ---------------------------------------------------------------------------
__global__ void __launch_bounds__(128) ln_kernel(
    const float* __restrict__ x, const float* __restrict__ g,
    const float* __restrict__ b, float* __restrict__ out)
{
    const int row = blockIdx.x;
    const int tid = threadIdx.x;
    const float* xr = x + (size_t)row * CDIM;

    float4 v = *reinterpret_cast<const float4*>(&xr[tid * 4]);
    float s  = v.x + v.y + v.z + v.w;
    float ss = v.x*v.x + v.y*v.y + v.z*v.z + v.w*v.w;

    #pragma unroll
    for (int off = 16; off > 0; off >>= 1) {
        s  += __shfl_xor_sync(0xffffffffu, s,  off);
        ss += __shfl_xor_sync(0xffffffffu, ss, off);
    }
    __shared__ float sm[4], sm2[4];
    const int wid = tid >> 5, lane = tid & 31;
    if (lane == 0) { sm[wid] = s; sm2[wid] = ss; }
    __syncthreads();
    s  = sm[0] + sm[1] + sm[2] + sm[3];
    ss = sm2[0] + sm2[1] + sm2[2] + sm2[3];

    const float mu   = s * (1.0f / CDIM);
    const float var  = ss * (1.0f / CDIM) - mu * mu;
    const float rstd = rsqrtf(var + 1e-5f);

    float4 gg = *reinterpret_cast<const float4*>(&g[tid * 4]);
    float4 bb = *reinterpret_cast<const float4*>(&b[tid * 4]);
    float4 o;
    o.x = (v.x - mu) * rstd * gg.x + bb.x;
    o.y = (v.y - mu) * rstd * gg.y + bb.y;
    o.z = (v.z - mu) * rstd * gg.z + bb.z;
    o.w = (v.w - mu) * rstd * gg.w + bb.w;
    *reinterpret_cast<float4*>(&out[(size_t)row * CDIM + tid * 4]) = o;
}

// ---------------------------------------------------------------------------
// tf32 tensor-core GEMM: C[M,N] = A[M,K] @ B[K,N] (+bias)(+res)(relu)
// BM=BN=128, BK=16, 256 threads = 8 warps (4 along M x 2 along N).
// Warp tile 32x64 -> 2x8 mma(m16n8k8) tiles, 64 acc regs/thread.
// Smem k-major with +8 pad: fragment loads are bank-conflict free.
// HEADB: B is wq/wk/wv [H, C, D]: element(k,n) = B[(n>>6)*C*64 + k*64 + (n&63)]
// ---------------------------------------------------------------------------
template<bool HEADB, bool BIAS, bool RELU, bool RES>
__global__ void __launch_bounds__(256, 2) gemm_tf32(
    const float* __restrict__ A, const float* __restrict__ B,
    const float* __restrict__ bias, const float* __restrict__ res,
    float* __restrict__ C, int M, int N, int K)
{
    constexpr int BM = 128, BN = 128, BK = 16;
    constexpr int LDA = BM + 8;   // 136 floats per k-row
    constexpr int LDB = BN + 8;

    __shared__ float As[BK * LDA];
    __shared__ float Bs[BK * LDB];

    const int tid  = threadIdx.x;
    const int wid  = tid >> 5;
    const int lane = tid & 31;
    const int g    = lane >> 2;   // group id 0..7
    const int tg   = lane & 3;    // thread-in-group 0..3

    const int m0 = blockIdx.y * BM;
    const int n0 = blockIdx.x * BN;
    const int wm = (wid & 3) * 32;   // warp M offset within tile
    const int wn = (wid >> 2) * 64;  // warp N offset within tile

    float acc[2][8][4];
    #pragma unroll
    for (int mt = 0; mt < 2; mt++)
        #pragma unroll
        for (int nt = 0; nt < 8; nt++)
            #pragma unroll
            for (int i = 0; i < 4; i++) acc[mt][nt][i] = 0.0f;

    // Global-load index mapping (2 float4 from A, 2 from B per thread per tile)
    // A: lin = tid + r*256: row = lin>>2 (0..127), kc = (lin&3)*4
    // B: lin = tid + r*256: krow = lin>>5 (0..15), nc = (lin&31)*4
    const int a_row0 = tid >> 2,        a_kc = (tid & 3) * 4;
    const int b_kr0  = tid >> 5,        b_nc = (tid & 31) * 4;

    for (int k0 = 0; k0 < K; k0 += BK) {
        // ---- prefetch globals into registers ----
        float4 av[2], bv[2];
        #pragma unroll
        for (int r = 0; r < 2; r++) {
            av[r] = *reinterpret_cast<const float4*>(
                &A[(size_t)(m0 + a_row0 + r * 64) * K + k0 + a_kc]);
            int n = n0 + b_nc;
            if (HEADB) {
                bv[r] = *reinterpret_cast<const float4*>(
                    &B[(size_t)(n >> 6) * (CDIM * DHEAD) +
                       (size_t)(k0 + b_kr0 + r * 8) * DHEAD + (n & 63)]);
            } else {
                bv[r] = *reinterpret_cast<const float4*>(
                    &B[(size_t)(k0 + b_kr0 + r * 8) * N + n]);
            }
        }

        __syncthreads();   // previous tile fully consumed

        // ---- store to smem with tf32 rounding ----
        #pragma unroll
        for (int r = 0; r < 2; r++) {
            const int arow = a_row0 + r * 64;
            As[(a_kc + 0) * LDA + arow] = to_tf32(av[r].x);
            As[(a_kc + 1) * LDA + arow] = to_tf32(av[r].y);
            As[(a_kc + 2) * LDA + arow] = to_tf32(av[r].z);
            As[(a_kc + 3) * LDA + arow] = to_tf32(av[r].w);
            const int bkr = b_kr0 + r * 8;
            Bs[bkr * LDB + b_nc + 0] = to_tf32(bv[r].x);
            Bs[bkr * LDB + b_nc + 1] = to_tf32(bv[r].y);
            Bs[bkr * LDB + b_nc + 2] = to_tf32(bv[r].z);
            Bs[bkr * LDB + b_nc + 3] = to_tf32(bv[r].w);
        }

        __syncthreads();

        // ---- compute: 2 k-steps of 8 ----
        #pragma unroll
        for (int ks = 0; ks < 2; ks++) {
            const int kb = ks * 8;
            uint32_t af[2][4], bf[8][2];
            #pragma unroll
            for (int mt = 0; mt < 2; mt++) {
                const int mrow = wm + mt * 16 + g;
                af[mt][0] = __float_as_uint(As[(kb + tg)     * LDA + mrow]);
                af[mt][1] = __float_as_uint(As[(kb + tg)     * LDA + mrow + 8]);
                af[mt][2] = __float_as_uint(As[(kb + tg + 4) * LDA + mrow]);
                af[mt][3] = __float_as_uint(As[(kb + tg + 4) * LDA + mrow + 8]);
            }
            #pragma unroll
            for (int nt = 0; nt < 8; nt++) {
                const int ncol = wn + nt * 8 + g;
                bf[nt][0] = __float_as_uint(Bs[(kb + tg)     * LDB + ncol]);
                bf[nt][1] = __float_as_uint(Bs[(kb + tg + 4) * LDB + ncol]);
            }
            #pragma unroll
            for (int mt = 0; mt < 2; mt++)
                #pragma unroll
                for (int nt = 0; nt < 8; nt++)
                    mma_tf32(acc[mt][nt], af[mt], bf[nt]);
        }
    }

    // ---- epilogue ----
    #pragma unroll
    for (int mt = 0; mt < 2; mt++) {
        #pragma unroll
        for (int nt = 0; nt < 8; nt++) {
            const int col = n0 + wn + nt * 8 + 2 * tg;
            float2 bb = make_float2(0.f, 0.f);
            if (BIAS) bb = *reinterpret_cast<const float2*>(&bias[col]);
            #pragma unroll
            for (int half = 0; half < 2; half++) {
                const int row = m0 + wm + mt * 16 + g + half * 8;
                float2 v = make_float2(acc[mt][nt][half * 2 + 0],
                                       acc[mt][nt][half * 2 + 1]);
                if (BIAS) { v.x += bb.x; v.y += bb.y; }
                if (RES) {
                    float2 rr = *reinterpret_cast<const float2*>(
                        &res[(size_t)row * N + col]);
                    v.x += rr.x; v.y += rr.y;
                }
                if (RELU) { v.x = fmaxf(v.x, 0.f); v.y = fmaxf(v.y, 0.f); }
                *reinterpret_cast<float2*>(&C[(size_t)row * N + col]) = v;
            }
        }
    }
}

// ---------------------------------------------------------------------------
// Causal attention (flash-style online softmax), fp32.
// grid = (T/128, B*H), block = 128. One thread = one query row.
// ---------------------------------------------------------------------------
#define KT 32
__global__ void __launch_bounds__(128) attn_kernel(
    const float* __restrict__ q, const float* __restrict__ k,
    const float* __restrict__ v, float* __restrict__ o)
{
    const int qt  = blockIdx.x;
    const int bh  = blockIdx.y;
    const int b   = bh >> 3;
    const int h   = bh & 7;
    const int tid = threadIdx.x;
    const int t   = qt * 128 + tid;

    const float scale = 0.04419417382415922f;   // 1/sqrt(512)

    const float* qrow  = q + ((size_t)(b * SEQ + t)) * CDIM + h * DHEAD;
    const float* kbase = k + ((size_t)b * SEQ) * CDIM + h * DHEAD;
    const float* vbase = v + ((size_t)b * SEQ) * CDIM + h * DHEAD;

    float qr[DHEAD];
    #pragma unroll
    for (int d4 = 0; d4 < 16; d4++) {
        float4 t4 = *reinterpret_cast<const float4*>(&qrow[d4 * 4]);
        qr[d4*4+0] = t4.x; qr[d4*4+1] = t4.y; qr[d4*4+2] = t4.z; qr[d4*4+3] = t4.w;
    }

    float oacc[DHEAD];
    #pragma unroll
    for (int d = 0; d < DHEAD; d++) oacc[d] = 0.0f;
    float m = -INFINITY, l = 0.0f;

    __shared__ float ks[KT][DHEAD];
    __shared__ float vs[KT][DHEAD];

    const int tmax = qt * 128 + 127;
    for (int j0 = 0; j0 <= tmax; j0 += KT) {
        #pragma unroll
        for (int r = 0; r < 4; r++) {
            int lin = (r * 128 + tid) * 4;
            int j = lin >> 6, d = lin & 63;
            *reinterpret_cast<float4*>(&ks[j][d]) =
                *reinterpret_cast<const float4*>(&kbase[(size_t)(j0 + j) * CDIM + d]);
            *reinterpret_cast<float4*>(&vs[j][d]) =
                *reinterpret_cast<const float4*>(&vbase[(size_t)(j0 + j) * CDIM + d]);
        }
        __syncthreads();

        if (j0 <= t) {
            float s[KT];
            float tile_max = -INFINITY;
            #pragma unroll
            for (int j = 0; j < KT; j++) {
                float acc = 0.0f;
                #pragma unroll
                for (int d4 = 0; d4 < 16; d4++) {
                    float4 kk = *reinterpret_cast<const float4*>(&ks[j][d4 * 4]);
                    acc = fmaf(qr[d4*4+0], kk.x, acc);
                    acc = fmaf(qr[d4*4+1], kk.y, acc);
                    acc = fmaf(qr[d4*4+2], kk.z, acc);
                    acc = fmaf(qr[d4*4+3], kk.w, acc);
                }
                s[j] = (j0 + j <= t) ? acc * scale : -INFINITY;
                tile_max = fmaxf(tile_max, s[j]);
            }
            const float mnew = fmaxf(m, tile_max);
            const float c = __expf(m - mnew);
            m = mnew;
            l *= c;
            #pragma unroll
            for (int d = 0; d < DHEAD; d++) oacc[d] *= c;

            #pragma unroll
            for (int j = 0; j < KT; j++) {
                const float p = __expf(s[j] - m);
                l += p;
                #pragma unroll
                for (int d4 = 0; d4 < 16; d4++) {
                    float4 vv = *reinterpret_cast<const float4*>(&vs[j][d4 * 4]);
                    oacc[d4*4+0] = fmaf(p, vv.x, oacc[d4*4+0]);
                    oacc[d4*4+1] = fmaf(p, vv.y, oacc[d4*4+1]);
                    oacc[d4*4+2] = fmaf(p, vv.z, oacc[d4*4+2]);
                    oacc[d4*4+3] = fmaf(p, vv.w, oacc[d4*4+3]);
                }
            }
        }
        __syncthreads();
    }

    const float inv = 1.0f / l;
    float* orow = o + ((size_t)(b * SEQ + t)) * CDIM + h * DHEAD;
    #pragma unroll
    for (int d4 = 0; d4 < 16; d4++) {
        float4 w = make_float4(oacc[d4*4+0] * inv, oacc[d4*4+1] * inv,
                               oacc[d4*4+2] * inv, oacc[d4*4+3] * inv);
        *reinterpret_cast<float4*>(&orow[d4 * 4]) = w;
    }
}

// ---------------------------------------------------------------------------
// Launch. Inputs (metadata order):
// 0:x 1:wq 2:wk 3:wv 4:w_proj 5:b_proj 6:w1 7:b1 8:w2 9:b2
// 10:ln1_g 11:ln1_b 12:ln2_g 13:ln2_b
// ---------------------------------------------------------------------------
extern "C" void kernel_launch(void* const* d_in, const int* in_sizes, int n_in,
                              void* d_out, int out_size)
{
    const float* x      = (const float*)d_in[0];
    const float* wq     = (const float*)d_in[1];
    const float* wk     = (const float*)d_in[2];
    const float* wv     = (const float*)d_in[3];
    const float* w_proj = (const float*)d_in[4];
    const float* b_proj = (const float*)d_in[5];
    const float* w1     = (const float*)d_in[6];
    const float* b1     = (const float*)d_in[7];
    const float* w2     = (const float*)d_in[8];
    const float* b2     = (const float*)d_in[9];
    const float* ln1_g  = (const float*)d_in[10];
    const float* ln1_b  = (const float*)d_in[11];
    const float* ln2_g  = (const float*)d_in[12];
    const float* ln2_b  = (const float*)d_in[13];
    float* out = (float*)d_out;

    float *h, *qb, *kb, *vb, *ob, *h2, *ffn;
    cudaGetSymbolAddress((void**)&h,   g_h);
    cudaGetSymbolAddress((void**)&qb,  g_q);
    cudaGetSymbolAddress((void**)&kb,  g_k);
    cudaGetSymbolAddress((void**)&vb,  g_v);
    cudaGetSymbolAddress((void**)&ob,  g_o);
    cudaGetSymbolAddress((void**)&h2,  g_h2);
    cudaGetSymbolAddress((void**)&ffn, g_ffn);

    const int M = MROWS;

    // ln1
    ln_kernel<<<M, 128>>>(x, ln1_g, ln1_b, h);

    // q, k, v projections (head-interleaved weights read in place)
    gemm_tf32<true,  false, false, false><<<dim3(CDIM/128, M/128), 256>>>(
        h, wq, nullptr, nullptr, qb, M, CDIM, CDIM);
    gemm_tf32<true,  false, false, false><<<dim3(CDIM/128, M/128), 256>>>(
        h, wk, nullptr, nullptr, kb, M, CDIM, CDIM);
    gemm_tf32<true,  false, false, false><<<dim3(CDIM/128, M/128), 256>>>(
        h, wv, nullptr, nullptr, vb, M, CDIM, CDIM);

    // causal attention
    attn_kernel<<<dim3(SEQ/128, BATCH*NHEAD), 128>>>(qb, kb, vb, ob);

    // x2 = x + o @ w_proj + b_proj  -> out
    gemm_tf32<false, true,  false, true ><<<dim3(CDIM/128, M/128), 256>>>(
        ob, w_proj, b_proj, x, out, M, CDIM, CDIM);

    // ln2
    ln_kernel<<<M, 128>>>(out, ln2_g, ln2_b, h2);

    // ffn1 = relu(h2 @ w1 + b1)
    gemm_tf32<false, true,  true,  false><<<dim3(FFNDIM/128, M/128), 256>>>(
        h2, w1, b1, nullptr, ffn, M, FFNDIM, CDIM);

    // out = out + ffn1 @ w2 + b2
    gemm_tf32<false, true,  false, true ><<<dim3(CDIM/128, M/128), 256>>>(
        ffn, w2, b2, out, out, M, CDIM, FFNDIM);
}

// round 3
// speedup vs baseline: 2.0637x; 1.0052x over previous
#include <cuda_runtime.h>
#include <math.h>
#include <stdint.h>

// Problem constants
#define BATCH 32
#define SEQ   512
#define CDIM  512
#define NHEAD 8
#define DHEAD 64
#define MROWS (BATCH * SEQ)        // 16384
#define FFNDIM (4 * CDIM)          // 2048

// Scratch (allocation-free rule: __device__ globals)
__device__ float g_h  [MROWS * CDIM];   // ln1 out
__device__ float g_q  [MROWS * CDIM];
__device__ float g_k  [MROWS * CDIM];
__device__ float g_v  [MROWS * CDIM];
__device__ float g_o  [MROWS * CDIM];
__device__ float g_h2 [MROWS * CDIM];
__device__ float g_ffn[MROWS * FFNDIM];

// ---------------------------------------------------------------------------
// Helpers: tf32 round + mma
// ---------------------------------------------------------------------------
__device__ __forceinline__ float to_tf32(float x) {
    float r;
    asm("cvt.rna.tf32.f32 %0, %1;" : "=f"(r) : "f"(x));
    return r;
}

__device__ __forceinline__ void mma_tf32(float* c, const uint32_t* a, const uint32_t* b) {
    asm volatile(
        "mma.sync.aligned.m16n8k8.row.col.f32.tf32.tf32.f32 "
        "{%0,%1,%2,%3},{%4,%5,%6,%7},{%8,%9},{%0,%1,%2,%3};"
        : "+f"(c[0]), "+f"(c[1]), "+f"(c[2]), "+f"(c[3])
        : "r"(a[0]), "r"(a[1]), "r"(a[2]), "r"(a[3]),
          "r"(b[0]), "r"(b[1]));
}

// ---------------------------------------------------------------------------
// LayerNorm: one block per row (C=512), 128 threads, float4 per thread
// ---------------------------------------------------------------------------
__global__ void __launch_bounds__(128) ln_kernel(
    const float* __restrict__ x, const float* __restrict__ g,
    const float* __restrict__ b, float* __restrict__ out)
{
    const int row = blockIdx.x;
    const int tid = threadIdx.x;
    const float* xr = x + (size_t)row * CDIM;

    float4 v = *reinterpret_cast<const float4*>(&xr[tid * 4]);
    float s  = v.x + v.y + v.z + v.w;
    float ss = v.x*v.x + v.y*v.y + v.z*v.z + v.w*v.w;

    #pragma unroll
    for (int off = 16; off > 0; off >>= 1) {
        s  += __shfl_xor_sync(0xffffffffu, s,  off);
        ss += __shfl_xor_sync(0xffffffffu, ss, off);
    }
    __shared__ float sm[4], sm2[4];
    const int wid = tid >> 5, lane = tid & 31;
    if (lane == 0) { sm[wid] = s; sm2[wid] = ss; }
    __syncthreads();
    s  = sm[0] + sm[1] + sm[2] + sm[3];
    ss = sm2[0] + sm2[1] + sm2[2] + sm2[3];

    const float mu   = s * (1.0f / CDIM);
    const float var  = ss * (1.0f / CDIM) - mu * mu;
    const float rstd = rsqrtf(var + 1e-5f);

    float4 gg = *reinterpret_cast<const float4*>(&g[tid * 4]);
    float4 bb = *reinterpret_cast<const float4*>(&b[tid * 4]);
    float4 o;
    o.x = (v.x - mu) * rstd * gg.x + bb.x;
    o.y = (v.y - mu) * rstd * gg.y + bb.y;
    o.z = (v.z - mu) * rstd * gg.z + bb.z;
    o.w = (v.w - mu) * rstd * gg.w + bb.w;
    *reinterpret_cast<float4*>(&out[(size_t)row * CDIM + tid * 4]) = o;
}

// ---------------------------------------------------------------------------
// tf32 tensor-core GEMM: C[M,N] = A[M,K] @ B[K,N] (+bias)(+res)(relu)
// BM=BN=128, BK=16, 256 threads = 8 warps (4 along M x 2 along N).
// Warp tile 32x64 -> 2x8 mma(m16n8k8) tiles, 64 acc regs/thread.
// Smem k-major with +8 pad: fragment loads are bank-conflict free.
// HEADB: B is wq/wk/wv [H, C, D]: element(k,n) = B[(n>>6)*C*64 + k*64 + (n&63)]
// ---------------------------------------------------------------------------
template<bool HEADB, bool BIAS, bool RELU, bool RES>
__global__ void __launch_bounds__(256, 2) gemm_tf32(
    const float* __restrict__ A, const float* __restrict__ B,
    const float* __restrict__ bias, const float* __restrict__ res,
    float* __restrict__ C, int M, int N, int K)
{
    constexpr int BM = 128, BN = 128, BK = 16;
    constexpr int LDA = BM + 8;   // 136 floats per k-row
    constexpr int LDB = BN + 8;

    __shared__ float As[BK * LDA];
    __shared__ float Bs[BK * LDB];

    const int tid  = threadIdx.x;
    const int wid  = tid >> 5;
    const int lane = tid & 31;
    const int g    = lane >> 2;   // group id 0..7
    const int tg   = lane & 3;    // thread-in-group 0..3

    const int m0 = blockIdx.y * BM;
    const int n0 = blockIdx.x * BN;
    const int wm = (wid & 3) * 32;   // warp M offset within tile
    const int wn = (wid >> 2) * 64;  // warp N offset within tile

    float acc[2][8][4];
    #pragma unroll
    for (int mt = 0; mt < 2; mt++)
        #pragma unroll
        for (int nt = 0; nt < 8; nt++)
            #pragma unroll
            for (int i = 0; i < 4; i++) acc[mt][nt][i] = 0.0f;

    // Global-load index mapping (2 float4 from A, 2 from B per thread per tile)
    // A: lin = tid + r*256: row = lin>>2 (0..127), kc = (lin&3)*4
    // B: lin = tid + r*256: krow = lin>>5 (0..15), nc = (lin&31)*4
    const int a_row0 = tid >> 2,        a_kc = (tid & 3) * 4;
    const int b_kr0  = tid >> 5,        b_nc = (tid & 31) * 4;

    for (int k0 = 0; k0 < K; k0 += BK) {
        // ---- prefetch globals into registers ----
        float4 av[2], bv[2];
        #pragma unroll
        for (int r = 0; r < 2; r++) {
            av[r] = *reinterpret_cast<const float4*>(
                &A[(size_t)(m0 + a_row0 + r * 64) * K + k0 + a_kc]);
            int n = n0 + b_nc;
            if (HEADB) {
                bv[r] = *reinterpret_cast<const float4*>(
                    &B[(size_t)(n >> 6) * (CDIM * DHEAD) +
                       (size_t)(k0 + b_kr0 + r * 8) * DHEAD + (n & 63)]);
            } else {
                bv[r] = *reinterpret_cast<const float4*>(
                    &B[(size_t)(k0 + b_kr0 + r * 8) * N + n]);
            }
        }

        __syncthreads();   // previous tile fully consumed

        // ---- store to smem with tf32 rounding ----
        #pragma unroll
        for (int r = 0; r < 2; r++) {
            const int arow = a_row0 + r * 64;
            As[(a_kc + 0) * LDA + arow] = to_tf32(av[r].x);
            As[(a_kc + 1) * LDA + arow] = to_tf32(av[r].y);
            As[(a_kc + 2) * LDA + arow] = to_tf32(av[r].z);
            As[(a_kc + 3) * LDA + arow] = to_tf32(av[r].w);
            const int bkr = b_kr0 + r * 8;
            Bs[bkr * LDB + b_nc + 0] = to_tf32(bv[r].x);
            Bs[bkr * LDB + b_nc + 1] = to_tf32(bv[r].y);
            Bs[bkr * LDB + b_nc + 2] = to_tf32(bv[r].z);
            Bs[bkr * LDB + b_nc + 3] = to_tf32(bv[r].w);
        }

        __syncthreads();

        // ---- compute: 2 k-steps of 8 ----
        #pragma unroll
        for (int ks = 0; ks < 2; ks++) {
            const int kb = ks * 8;
            uint32_t af[2][4], bf[8][2];
            #pragma unroll
            for (int mt = 0; mt < 2; mt++) {
                const int mrow = wm + mt * 16 + g;
                af[mt][0] = __float_as_uint(As[(kb + tg)     * LDA + mrow]);
                af[mt][1] = __float_as_uint(As[(kb + tg)     * LDA + mrow + 8]);
                af[mt][2] = __float_as_uint(As[(kb + tg + 4) * LDA + mrow]);
                af[mt][3] = __float_as_uint(As[(kb + tg + 4) * LDA + mrow + 8]);
            }
            #pragma unroll
            for (int nt = 0; nt < 8; nt++) {
                const int ncol = wn + nt * 8 + g;
                bf[nt][0] = __float_as_uint(Bs[(kb + tg)     * LDB + ncol]);
                bf[nt][1] = __float_as_uint(Bs[(kb + tg + 4) * LDB + ncol]);
            }
            #pragma unroll
            for (int mt = 0; mt < 2; mt++)
                #pragma unroll
                for (int nt = 0; nt < 8; nt++)
                    mma_tf32(acc[mt][nt], af[mt], bf[nt]);
        }
    }

    // ---- epilogue ----
    #pragma unroll
    for (int mt = 0; mt < 2; mt++) {
        #pragma unroll
        for (int nt = 0; nt < 8; nt++) {
            const int col = n0 + wn + nt * 8 + 2 * tg;
            float2 bb = make_float2(0.f, 0.f);
            if (BIAS) bb = *reinterpret_cast<const float2*>(&bias[col]);
            #pragma unroll
            for (int half = 0; half < 2; half++) {
                const int row = m0 + wm + mt * 16 + g + half * 8;
                float2 v = make_float2(acc[mt][nt][half * 2 + 0],
                                       acc[mt][nt][half * 2 + 1]);
                if (BIAS) { v.x += bb.x; v.y += bb.y; }
                if (RES) {
                    float2 rr = *reinterpret_cast<const float2*>(
                        &res[(size_t)row * N + col]);
                    v.x += rr.x; v.y += rr.y;
                }
                if (RELU) { v.x = fmaxf(v.x, 0.f); v.y = fmaxf(v.y, 0.f); }
                *reinterpret_cast<float2*>(&C[(size_t)row * N + col]) = v;
            }
        }
    }
}

// ---------------------------------------------------------------------------
// Causal attention (flash-style online softmax), fp32.
// grid = (T/128, B*H), block = 128. One thread = one query row.
// ---------------------------------------------------------------------------
#define KT 32
__global__ void __launch_bounds__(128) attn_kernel(
    const float* __restrict__ q, const float* __restrict__ k,
    const float* __restrict__ v, float* __restrict__ o)
{
    const int qt  = blockIdx.x;
    const int bh  = blockIdx.y;
    const int b   = bh >> 3;
    const int h   = bh & 7;
    const int tid = threadIdx.x;
    const int t   = qt * 128 + tid;

    const float scale = 0.04419417382415922f;   // 1/sqrt(512)

    const float* qrow  = q + ((size_t)(b * SEQ + t)) * CDIM + h * DHEAD;
    const float* kbase = k + ((size_t)b * SEQ) * CDIM + h * DHEAD;
    const float* vbase = v + ((size_t)b * SEQ) * CDIM + h * DHEAD;

    float qr[DHEAD];
    #pragma unroll
    for (int d4 = 0; d4 < 16; d4++) {
        float4 t4 = *reinterpret_cast<const float4*>(&qrow[d4 * 4]);
        qr[d4*4+0] = t4.x; qr[d4*4+1] = t4.y; qr[d4*4+2] = t4.z; qr[d4*4+3] = t4.w;
    }

    float oacc[DHEAD];
    #pragma unroll
    for (int d = 0; d < DHEAD; d++) oacc[d] = 0.0f;
    float m = -INFINITY, l = 0.0f;

    __shared__ float ks[KT][DHEAD];
    __shared__ float vs[KT][DHEAD];

    const int tmax = qt * 128 + 127;
    for (int j0 = 0; j0 <= tmax; j0 += KT) {
        #pragma unroll
        for (int r = 0; r < 4; r++) {
            int lin = (r * 128 + tid) * 4;
            int j = lin >> 6, d = lin & 63;
            *reinterpret_cast<float4*>(&ks[j][d]) =
                *reinterpret_cast<const float4*>(&kbase[(size_t)(j0 + j) * CDIM + d]);
            *reinterpret_cast<float4*>(&vs[j][d]) =
                *reinterpret_cast<const float4*>(&vbase[(size_t)(j0 + j) * CDIM + d]);
        }
        __syncthreads();

        if (j0 <= t) {
            float s[KT];
            float tile_max = -INFINITY;
            #pragma unroll
            for (int j = 0; j < KT; j++) {
                float acc = 0.0f;
                #pragma unroll
                for (int d4 = 0; d4 < 16; d4++) {
                    float4 kk = *reinterpret_cast<const float4*>(&ks[j][d4 * 4]);
                    acc = fmaf(qr[d4*4+0], kk.x, acc);
                    acc = fmaf(qr[d4*4+1], kk.y, acc);
                    acc = fmaf(qr[d4*4+2], kk.z, acc);
                    acc = fmaf(qr[d4*4+3], kk.w, acc);
                }
                s[j] = (j0 + j <= t) ? acc * scale : -INFINITY;
                tile_max = fmaxf(tile_max, s[j]);
            }
            const float mnew = fmaxf(m, tile_max);
            const float c = __expf(m - mnew);
            m = mnew;
            l *= c;
            #pragma unroll
            for (int d = 0; d < DHEAD; d++) oacc[d] *= c;

            #pragma unroll
            for (int j = 0; j < KT; j++) {
                const float p = __expf(s[j] - m);
                l += p;
                #pragma unroll
                for (int d4 = 0; d4 < 16; d4++) {
                    float4 vv = *reinterpret_cast<const float4*>(&vs[j][d4 * 4]);
                    oacc[d4*4+0] = fmaf(p, vv.x, oacc[d4*4+0]);
                    oacc[d4*4+1] = fmaf(p, vv.y, oacc[d4*4+1]);
                    oacc[d4*4+2] = fmaf(p, vv.z, oacc[d4*4+2]);
                    oacc[d4*4+3] = fmaf(p, vv.w, oacc[d4*4+3]);
                }
            }
        }
        __syncthreads();
    }

    const float inv = 1.0f / l;
    float* orow = o + ((size_t)(b * SEQ + t)) * CDIM + h * DHEAD;
    #pragma unroll
    for (int d4 = 0; d4 < 16; d4++) {
        float4 w = make_float4(oacc[d4*4+0] * inv, oacc[d4*4+1] * inv,
                               oacc[d4*4+2] * inv, oacc[d4*4+3] * inv);
        *reinterpret_cast<float4*>(&orow[d4 * 4]) = w;
    }
}

// ---------------------------------------------------------------------------
// Launch. Inputs (metadata order):
// 0:x 1:wq 2:wk 3:wv 4:w_proj 5:b_proj 6:w1 7:b1 8:w2 9:b2
// 10:ln1_g 11:ln1_b 12:ln2_g 13:ln2_b
// ---------------------------------------------------------------------------
extern "C" void kernel_launch(void* const* d_in, const int* in_sizes, int n_in,
                              void* d_out, int out_size)
{
    const float* x      = (const float*)d_in[0];
    const float* wq     = (const float*)d_in[1];
    const float* wk     = (const float*)d_in[2];
    const float* wv     = (const float*)d_in[3];
    const float* w_proj = (const float*)d_in[4];
    const float* b_proj = (const float*)d_in[5];
    const float* w1     = (const float*)d_in[6];
    const float* b1     = (const float*)d_in[7];
    const float* w2     = (const float*)d_in[8];
    const float* b2     = (const float*)d_in[9];
    const float* ln1_g  = (const float*)d_in[10];
    const float* ln1_b  = (const float*)d_in[11];
    const float* ln2_g  = (const float*)d_in[12];
    const float* ln2_b  = (const float*)d_in[13];
    float* out = (float*)d_out;

    float *h, *qb, *kb, *vb, *ob, *h2, *ffn;
    cudaGetSymbolAddress((void**)&h,   g_h);
    cudaGetSymbolAddress((void**)&qb,  g_q);
    cudaGetSymbolAddress((void**)&kb,  g_k);
    cudaGetSymbolAddress((void**)&vb,  g_v);
    cudaGetSymbolAddress((void**)&ob,  g_o);
    cudaGetSymbolAddress((void**)&h2,  g_h2);
    cudaGetSymbolAddress((void**)&ffn, g_ffn);

    const int M = MROWS;

    // ln1
    ln_kernel<<<M, 128>>>(x, ln1_g, ln1_b, h);

    // q, k, v projections (head-interleaved weights read in place)
    gemm_tf32<true,  false, false, false><<<dim3(CDIM/128, M/128), 256>>>(
        h, wq, nullptr, nullptr, qb, M, CDIM, CDIM);
    gemm_tf32<true,  false, false, false><<<dim3(CDIM/128, M/128), 256>>>(
        h, wk, nullptr, nullptr, kb, M, CDIM, CDIM);
    gemm_tf32<true,  false, false, false><<<dim3(CDIM/128, M/128), 256>>>(
        h, wv, nullptr, nullptr, vb, M, CDIM, CDIM);

    // causal attention
    attn_kernel<<<dim3(SEQ/128, BATCH*NHEAD), 128>>>(qb, kb, vb, ob);

    // x2 = x + o @ w_proj + b_proj  -> out
    gemm_tf32<false, true,  false, true ><<<dim3(CDIM/128, M/128), 256>>>(
        ob, w_proj, b_proj, x, out, M, CDIM, CDIM);

    // ln2
    ln_kernel<<<M, 128>>>(out, ln2_g, ln2_b, h2);

    // ffn1 = relu(h2 @ w1 + b1)
    gemm_tf32<false, true,  true,  false><<<dim3(FFNDIM/128, M/128), 256>>>(
        h2, w1, b1, nullptr, ffn, M, FFNDIM, CDIM);

    // out = out + ffn1 @ w2 + b2
    gemm_tf32<false, true,  false, true ><<<dim3(CDIM/128, M/128), 256>>>(
        ffn, w2, b2, out, out, M, CDIM, FFNDIM);
}

// round 4
// speedup vs baseline: 2.3703x; 1.1486x over previous
#include <cuda_runtime.h>
#include <math.h>
#include <stdint.h>

// Problem constants
#define BATCH 32
#define SEQ   512
#define CDIM  512
#define NHEAD 8
#define DHEAD 64
#define MROWS (BATCH * SEQ)        // 16384
#define FFNDIM (4 * CDIM)          // 2048
#define QKVN  (3 * CDIM)           // 1536

// Scratch (allocation-free rule: __device__ globals)
__device__ float g_h   [MROWS * CDIM];    // ln1 out (tf32-rounded)
__device__ float g_qkv [MROWS * QKVN];    // fused q|k|v, row stride 1536
__device__ float g_o   [MROWS * CDIM];    // attn out (tf32-rounded)
__device__ float g_h2  [MROWS * CDIM];    // ln2 out (tf32-rounded)
__device__ float g_ffn [MROWS * FFNDIM];  // relu(h2@w1+b1) (tf32-rounded)
// tf32-rounded / repacked weights
__device__ float g_wqkv[CDIM * QKVN];     // [k][p*512 + h*64 + d]
__device__ float g_wp  [CDIM * CDIM];
__device__ float g_w1  [CDIM * FFNDIM];
__device__ float g_w2  [FFNDIM * CDIM];

// ---------------------------------------------------------------------------
// Helpers
// ---------------------------------------------------------------------------
__device__ __forceinline__ float to_tf32(float x) {
    float r;
    asm("cvt.rna.tf32.f32 %0, %1;" : "=f"(r) : "f"(x));
    return r;
}

__device__ __forceinline__ void mma_tf32(float* c, const uint32_t* a, const uint32_t* b) {
    asm volatile(
        "mma.sync.aligned.m16n8k8.row.col.f32.tf32.tf32.f32 "
        "{%0,%1,%2,%3},{%4,%5,%6,%7},{%8,%9},{%0,%1,%2,%3};"
        : "+f"(c[0]), "+f"(c[1]), "+f"(c[2]), "+f"(c[3])
        : "r"(a[0]), "r"(a[1]), "r"(a[2]), "r"(a[3]),
          "r"(b[0]), "r"(b[1]));
}

__device__ __forceinline__ uint32_t smem_u32(const void* p) {
    return (uint32_t)__cvta_generic_to_shared(p);
}
__device__ __forceinline__ void cp16(uint32_t dst, const float* src) {
    asm volatile("cp.async.cg.shared.global [%0], [%1], 16;" :: "r"(dst), "l"(src));
}
__device__ __forceinline__ void cp_commit() {
    asm volatile("cp.async.commit_group;");
}
template<int N>
__device__ __forceinline__ void cp_wait() {
    asm volatile("cp.async.wait_group %0;" :: "n"(N));
}

// ---------------------------------------------------------------------------
// Weight prep: tf32-round (+ repack qkv head-interleave into flat [K,1536])
// ---------------------------------------------------------------------------
__global__ void __launch_bounds__(256) prep_qkv(
    const float* __restrict__ wq, const float* __restrict__ wk,
    const float* __restrict__ wv, float* __restrict__ dst)
{
    int idx = blockIdx.x * 256 + threadIdx.x;      // 512*1536 total
    int n = idx % QKVN, k = idx / QKVN;
    const float* w = (n < 512) ? wq : (n < 1024 ? wk : wv);
    int nn = n & 511, h = nn >> 6, d = nn & 63;
    dst[idx] = to_tf32(w[(h * CDIM + k) * DHEAD + d]);
}

__global__ void __launch_bounds__(256) prep_w(
    const float* __restrict__ src, float* __restrict__ dst)
{
    int idx = blockIdx.x * 256 + threadIdx.x;
    dst[idx] = to_tf32(src[idx]);
}

// ---------------------------------------------------------------------------
// LayerNorm: one block per row (C=512), 128 threads, tf32-rounded output
// ---------------------------------------------------------------------------
__global__ void __launch_bounds__(128) ln_kernel(
    const float* __restrict__ x, const float* __restrict__ g,
    const float* __restrict__ b, float* __restrict__ out)
{
    const int row = blockIdx.x;
    const int tid = threadIdx.x;
    const float* xr = x + (size_t)row * CDIM;

    float4 v = *reinterpret_cast<const float4*>(&xr[tid * 4]);
    float s  = v.x + v.y + v.z + v.w;
    float ss = v.x*v.x + v.y*v.y + v.z*v.z + v.w*v.w;

    #pragma unroll
    for (int off = 16; off > 0; off >>= 1) {
        s  += __shfl_xor_sync(0xffffffffu, s,  off);
        ss += __shfl_xor_sync(0xffffffffu, ss, off);
    }
    __shared__ float sm[4], sm2[4];
    const int wid = tid >> 5, lane = tid & 31;
    if (lane == 0) { sm[wid] = s; sm2[wid] = ss; }
    __syncthreads();
    s  = sm[0] + sm[1] + sm[2] + sm[3];
    ss = sm2[0] + sm2[1] + sm2[2] + sm2[3];

    const float mu   = s * (1.0f / CDIM);
    const float var  = ss * (1.0f / CDIM) - mu * mu;
    const float rstd = rsqrtf(var + 1e-5f);

    float4 gg = *reinterpret_cast<const float4*>(&g[tid * 4]);
    float4 bb = *reinterpret_cast<const float4*>(&b[tid * 4]);
    float4 o;
    o.x = to_tf32((v.x - mu) * rstd * gg.x + bb.x);
    o.y = to_tf32((v.y - mu) * rstd * gg.y + bb.y);
    o.z = to_tf32((v.z - mu) * rstd * gg.z + bb.z);
    o.w = to_tf32((v.w - mu) * rstd * gg.w + bb.w);
    *reinterpret_cast<float4*>(&out[(size_t)row * CDIM + tid * 4]) = o;
}

// ---------------------------------------------------------------------------
// tf32 tensor-core GEMM, cp.async double-buffered.
// BM=BN=128, BK=16, 128 threads = 4 warps (2x2), warp tile 64x64.
// A smem: m-major rows of 16 k, row stride 20 floats (bank-conflict-free frags)
// B smem: k-major rows of 128 n, row stride 136 floats
// All operands pre-rounded to tf32 -> raw-bit mma == cvt.rna semantics.
// ---------------------------------------------------------------------------
template<bool BIAS, bool RELU, bool RES, bool OUTCVT>
__global__ void __launch_bounds__(128, 2) gemm_tc(
    const float* __restrict__ A, const float* __restrict__ B,
    const float* __restrict__ bias, const float* __restrict__ res,
    float* __restrict__ C, int M, int N, int K)
{
    constexpr int BM = 128, BN = 128, BK = 16;
    constexpr int LDAS = 20;    // floats per A smem row
    constexpr int LDBS = 136;   // floats per B smem k-row

    __shared__ float As[2][BM * LDAS];
    __shared__ float Bs[2][BK * LDBS];

    const int tid  = threadIdx.x;
    const int wid  = tid >> 5;
    const int lane = tid & 31;
    const int g    = lane >> 2;
    const int tg   = lane & 3;

    const int m0 = blockIdx.y * BM;
    const int n0 = blockIdx.x * BN;
    const int wm = (wid & 1) * 64;
    const int wn = (wid >> 1) * 64;

    const int a_r  = tid >> 2;           // +32*i -> row
    const int a_kc = (tid & 3) * 4;
    const int b_kr = tid >> 5;           // +4*i  -> k row
    const int b_nc = (tid & 31) * 4;

    float acc[4][8][4];
    #pragma unroll
    for (int mt = 0; mt < 4; mt++)
        #pragma unroll
        for (int nt = 0; nt < 8; nt++)
            #pragma unroll
            for (int i = 0; i < 4; i++) acc[mt][nt][i] = 0.0f;

    auto issue_tile = [&](int buf, int k0) {
        #pragma unroll
        for (int i = 0; i < 4; i++) {
            const int row = a_r + 32 * i;
            cp16(smem_u32(&As[buf][row * LDAS + a_kc]),
                 &A[(size_t)(m0 + row) * K + k0 + a_kc]);
            const int kr = b_kr + 4 * i;
            cp16(smem_u32(&Bs[buf][kr * LDBS + b_nc]),
                 &B[(size_t)(k0 + kr) * N + n0 + b_nc]);
        }
        cp_commit();
    };

    issue_tile(0, 0);
    const int NIT = K / BK;

    for (int it = 0; it < NIT; it++) {
        if (it + 1 < NIT) {
            issue_tile((it + 1) & 1, (it + 1) * BK);
            cp_wait<1>();
        } else {
            cp_wait<0>();
        }
        __syncthreads();

        const float* Ab = As[it & 1];
        const float* Bb = Bs[it & 1];

        #pragma unroll
        for (int ks = 0; ks < 2; ks++) {
            const int kb = ks * 8;
            uint32_t af[4][4], bf[8][2];
            #pragma unroll
            for (int mt = 0; mt < 4; mt++) {
                const int mr = wm + mt * 16 + g;
                af[mt][0] = __float_as_uint(Ab[(mr    ) * LDAS + kb + tg]);
                af[mt][1] = __float_as_uint(Ab[(mr + 8) * LDAS + kb + tg]);
                af[mt][2] = __float_as_uint(Ab[(mr    ) * LDAS + kb + tg + 4]);
                af[mt][3] = __float_as_uint(Ab[(mr + 8) * LDAS + kb + tg + 4]);
            }
            #pragma unroll
            for (int nt = 0; nt < 8; nt++) {
                const int nc = wn + nt * 8 + g;
                bf[nt][0] = __float_as_uint(Bb[(kb + tg    ) * LDBS + nc]);
                bf[nt][1] = __float_as_uint(Bb[(kb + tg + 4) * LDBS + nc]);
            }
            #pragma unroll
            for (int mt = 0; mt < 4; mt++)
                #pragma unroll
                for (int nt = 0; nt < 8; nt++)
                    mma_tf32(acc[mt][nt], af[mt], bf[nt]);
        }
        __syncthreads();
    }

    // Epilogue
    #pragma unroll
    for (int mt = 0; mt < 4; mt++) {
        #pragma unroll
        for (int nt = 0; nt < 8; nt++) {
            const int col = n0 + wn + nt * 8 + 2 * tg;
            float2 bb = make_float2(0.f, 0.f);
            if (BIAS) bb = *reinterpret_cast<const float2*>(&bias[col]);
            #pragma unroll
            for (int half = 0; half < 2; half++) {
                const int row = m0 + wm + mt * 16 + g + half * 8;
                float2 v = make_float2(acc[mt][nt][half * 2 + 0],
                                       acc[mt][nt][half * 2 + 1]);
                if (BIAS) { v.x += bb.x; v.y += bb.y; }
                if (RES) {
                    float2 rr = *reinterpret_cast<const float2*>(
                        &res[(size_t)row * N + col]);
                    v.x += rr.x; v.y += rr.y;
                }
                if (RELU) { v.x = fmaxf(v.x, 0.f); v.y = fmaxf(v.y, 0.f); }
                if (OUTCVT) { v.x = to_tf32(v.x); v.y = to_tf32(v.y); }
                *reinterpret_cast<float2*>(&C[(size_t)row * N + col]) = v;
            }
        }
    }
}

// ---------------------------------------------------------------------------
// Causal attention (flash-style online softmax), fp32.
// Reads fused qkv buffer (row stride 1536; q/k/v at +0/+512/+1024).
// tf32-rounds the output (it feeds the proj GEMM).
// ---------------------------------------------------------------------------
#define KT 32
__global__ void __launch_bounds__(128) attn_kernel(
    const float* __restrict__ qkv, float* __restrict__ o)
{
    const int qt  = blockIdx.x;
    const int bh  = blockIdx.y;
    const int b   = bh >> 3;
    const int h   = bh & 7;
    const int tid = threadIdx.x;
    const int t   = qt * 128 + tid;

    const float scale = 0.04419417382415922f;   // 1/sqrt(512)

    const float* qrow  = qkv + ((size_t)(b * SEQ + t)) * QKVN + h * DHEAD;
    const float* kbase = qkv + ((size_t)b * SEQ) * QKVN + 512  + h * DHEAD;
    const float* vbase = qkv + ((size_t)b * SEQ) * QKVN + 1024 + h * DHEAD;

    float qr[DHEAD];
    #pragma unroll
    for (int d4 = 0; d4 < 16; d4++) {
        float4 t4 = *reinterpret_cast<const float4*>(&qrow[d4 * 4]);
        qr[d4*4+0] = t4.x; qr[d4*4+1] = t4.y; qr[d4*4+2] = t4.z; qr[d4*4+3] = t4.w;
    }

    float oacc[DHEAD];
    #pragma unroll
    for (int d = 0; d < DHEAD; d++) oacc[d] = 0.0f;
    float m = -INFINITY, l = 0.0f;

    __shared__ float ks[KT][DHEAD];
    __shared__ float vs[KT][DHEAD];

    const int tmax = qt * 128 + 127;
    for (int j0 = 0; j0 <= tmax; j0 += KT) {
        #pragma unroll
        for (int r = 0; r < 4; r++) {
            int lin = (r * 128 + tid) * 4;
            int j = lin >> 6, d = lin & 63;
            *reinterpret_cast<float4*>(&ks[j][d]) =
                *reinterpret_cast<const float4*>(&kbase[(size_t)(j0 + j) * QKVN + d]);
            *reinterpret_cast<float4*>(&vs[j][d]) =
                *reinterpret_cast<const float4*>(&vbase[(size_t)(j0 + j) * QKVN + d]);
        }
        __syncthreads();

        if (j0 <= t) {
            float s[KT];
            float tile_max = -INFINITY;
            #pragma unroll
            for (int j = 0; j < KT; j++) {
                float acc = 0.0f;
                #pragma unroll
                for (int d4 = 0; d4 < 16; d4++) {
                    float4 kk = *reinterpret_cast<const float4*>(&ks[j][d4 * 4]);
                    acc = fmaf(qr[d4*4+0], kk.x, acc);
                    acc = fmaf(qr[d4*4+1], kk.y, acc);
                    acc = fmaf(qr[d4*4+2], kk.z, acc);
                    acc = fmaf(qr[d4*4+3], kk.w, acc);
                }
                s[j] = (j0 + j <= t) ? acc * scale : -INFINITY;
                tile_max = fmaxf(tile_max, s[j]);
            }
            const float mnew = fmaxf(m, tile_max);
            const float c = __expf(m - mnew);
            m = mnew;
            l *= c;
            #pragma unroll
            for (int d = 0; d < DHEAD; d++) oacc[d] *= c;

            #pragma unroll
            for (int j = 0; j < KT; j++) {
                const float p = __expf(s[j] - m);
                l += p;
                #pragma unroll
                for (int d4 = 0; d4 < 16; d4++) {
                    float4 vv = *reinterpret_cast<const float4*>(&vs[j][d4 * 4]);
                    oacc[d4*4+0] = fmaf(p, vv.x, oacc[d4*4+0]);
                    oacc[d4*4+1] = fmaf(p, vv.y, oacc[d4*4+1]);
                    oacc[d4*4+2] = fmaf(p, vv.z, oacc[d4*4+2]);
                    oacc[d4*4+3] = fmaf(p, vv.w, oacc[d4*4+3]);
                }
            }
        }
        __syncthreads();
    }

    const float inv = 1.0f / l;
    float* orow = o + ((size_t)(b * SEQ + t)) * CDIM + h * DHEAD;
    #pragma unroll
    for (int d4 = 0; d4 < 16; d4++) {
        float4 w = make_float4(to_tf32(oacc[d4*4+0] * inv), to_tf32(oacc[d4*4+1] * inv),
                               to_tf32(oacc[d4*4+2] * inv), to_tf32(oacc[d4*4+3] * inv));
        *reinterpret_cast<float4*>(&orow[d4 * 4]) = w;
    }
}

// ---------------------------------------------------------------------------
// Launch. Inputs (metadata order):
// 0:x 1:wq 2:wk 3:wv 4:w_proj 5:b_proj 6:w1 7:b1 8:w2 9:b2
// 10:ln1_g 11:ln1_b 12:ln2_g 13:ln2_b
// ---------------------------------------------------------------------------
extern "C" void kernel_launch(void* const* d_in, const int* in_sizes, int n_in,
                              void* d_out, int out_size)
{
    const float* x      = (const float*)d_in[0];
    const float* wq     = (const float*)d_in[1];
    const float* wk     = (const float*)d_in[2];
    const float* wv     = (const float*)d_in[3];
    const float* w_proj = (const float*)d_in[4];
    const float* b_proj = (const float*)d_in[5];
    const float* w1     = (const float*)d_in[6];
    const float* b1     = (const float*)d_in[7];
    const float* w2     = (const float*)d_in[8];
    const float* b2     = (const float*)d_in[9];
    const float* ln1_g  = (const float*)d_in[10];
    const float* ln1_b  = (const float*)d_in[11];
    const float* ln2_g  = (const float*)d_in[12];
    const float* ln2_b  = (const float*)d_in[13];
    float* out = (float*)d_out;

    float *h, *qkv, *ob, *h2, *ffn, *w_qkv, *w_p, *w_1, *w_2;
    cudaGetSymbolAddress((void**)&h,     g_h);
    cudaGetSymbolAddress((void**)&qkv,   g_qkv);
    cudaGetSymbolAddress((void**)&ob,    g_o);
    cudaGetSymbolAddress((void**)&h2,    g_h2);
    cudaGetSymbolAddress((void**)&ffn,   g_ffn);
    cudaGetSymbolAddress((void**)&w_qkv, g_wqkv);
    cudaGetSymbolAddress((void**)&w_p,   g_wp);
    cudaGetSymbolAddress((void**)&w_1,   g_w1);
    cudaGetSymbolAddress((void**)&w_2,   g_w2);

    const int M = MROWS;

    // Weight prep (tf32 round + qkv repack). ~13MB traffic, a few microseconds.
    prep_qkv<<<(CDIM * QKVN) / 256, 256>>>(wq, wk, wv, w_qkv);
    prep_w<<<(CDIM * CDIM) / 256, 256>>>(w_proj, w_p);
    prep_w<<<(CDIM * FFNDIM) / 256, 256>>>(w1, w_1);
    prep_w<<<(FFNDIM * CDIM) / 256, 256>>>(w2, w_2);

    // ln1 (tf32-rounded out)
    ln_kernel<<<M, 128>>>(x, ln1_g, ln1_b, h);

    // fused qkv projection: [M,1536] = h @ w_qkv
    gemm_tc<false, false, false, false><<<dim3(QKVN/128, M/128), 128>>>(
        h, w_qkv, nullptr, nullptr, qkv, M, QKVN, CDIM);

    // causal attention (tf32-rounded out)
    attn_kernel<<<dim3(SEQ/128, BATCH*NHEAD), 128>>>(qkv, ob);

    // x2 = x + o @ w_proj + b_proj -> out
    gemm_tc<true, false, true, false><<<dim3(CDIM/128, M/128), 128>>>(
        ob, w_p, b_proj, x, out, M, CDIM, CDIM);

    // ln2 (tf32-rounded out)
    ln_kernel<<<M, 128>>>(out, ln2_g, ln2_b, h2);

    // ffn1 = relu(h2 @ w1 + b1), tf32-rounded out
    gemm_tc<true, true, false, true><<<dim3(FFNDIM/128, M/128), 128>>>(
        h2, w_1, b1, nullptr, ffn, M, FFNDIM, CDIM);

    // out = out + ffn1 @ w2 + b2
    gemm_tc<true, false, true, false><<<dim3(CDIM/128, M/128), 128>>>(
        ffn, w_2, b2, out, out, M, CDIM, FFNDIM);
}

// round 5
// speedup vs baseline: 3.3927x; 1.4313x over previous
#include <cuda_runtime.h>
#include <math.h>
#include <stdint.h>

// Problem constants
#define BATCH 32
#define SEQ   512
#define CDIM  512
#define NHEAD 8
#define DHEAD 64
#define MROWS (BATCH * SEQ)        // 16384
#define FFNDIM (4 * CDIM)          // 2048
#define QKVN  (3 * CDIM)           // 1536

// Scratch (allocation-free rule: __device__ globals)
__device__ float g_h   [MROWS * CDIM];    // ln1 out (tf32-rounded)
__device__ float g_qkv [MROWS * QKVN];    // fused q|k|v, row stride 1536 (tf32)
__device__ float g_o   [MROWS * CDIM];    // attn out (tf32-rounded)
__device__ float g_h2  [MROWS * CDIM];    // ln2 out (tf32-rounded)
__device__ float g_ffn [MROWS * FFNDIM];  // relu(h2@w1+b1) (tf32-rounded)
// tf32-rounded / repacked weights
__device__ float g_wqkv[CDIM * QKVN];     // [k][p*512 + h*64 + d]
__device__ float g_wp  [CDIM * CDIM];
__device__ float g_w1  [CDIM * FFNDIM];
__device__ float g_w2  [FFNDIM * CDIM];

// ---------------------------------------------------------------------------
// Helpers
// ---------------------------------------------------------------------------
__device__ __forceinline__ float to_tf32(float x) {
    float r;
    asm("cvt.rna.tf32.f32 %0, %1;" : "=f"(r) : "f"(x));
    return r;
}

__device__ __forceinline__ void mma_tf32(float* c, const uint32_t* a, const uint32_t* b) {
    asm volatile(
        "mma.sync.aligned.m16n8k8.row.col.f32.tf32.tf32.f32 "
        "{%0,%1,%2,%3},{%4,%5,%6,%7},{%8,%9},{%0,%1,%2,%3};"
        : "+f"(c[0]), "+f"(c[1]), "+f"(c[2]), "+f"(c[3])
        : "r"(a[0]), "r"(a[1]), "r"(a[2]), "r"(a[3]),
          "r"(b[0]), "r"(b[1]));
}

__device__ __forceinline__ uint32_t smem_u32(const void* p) {
    return (uint32_t)__cvta_generic_to_shared(p);
}
__device__ __forceinline__ void cp16(uint32_t dst, const float* src) {
    asm volatile("cp.async.cg.shared.global [%0], [%1], 16;" :: "r"(dst), "l"(src));
}
__device__ __forceinline__ void cp_commit() {
    asm volatile("cp.async.commit_group;");
}
template<int N>
__device__ __forceinline__ void cp_wait() {
    asm volatile("cp.async.wait_group %0;" :: "n"(N));
}

// ---------------------------------------------------------------------------
// Weight prep: tf32-round (+ repack qkv head-interleave into flat [K,1536])
// ---------------------------------------------------------------------------
__global__ void __launch_bounds__(256) prep_qkv(
    const float* __restrict__ wq, const float* __restrict__ wk,
    const float* __restrict__ wv, float* __restrict__ dst)
{
    int idx = blockIdx.x * 256 + threadIdx.x;      // 512*1536 total
    int n = idx % QKVN, k = idx / QKVN;
    const float* w = (n < 512) ? wq : (n < 1024 ? wk : wv);
    int nn = n & 511, h = nn >> 6, d = nn & 63;
    dst[idx] = to_tf32(w[(h * CDIM + k) * DHEAD + d]);
}

__global__ void __launch_bounds__(256) prep_w(
    const float* __restrict__ src, float* __restrict__ dst)
{
    int idx = blockIdx.x * 256 + threadIdx.x;
    dst[idx] = to_tf32(src[idx]);
}

// ---------------------------------------------------------------------------
// LayerNorm: one block per row (C=512), 128 threads, tf32-rounded output
// ---------------------------------------------------------------------------
__global__ void __launch_bounds__(128) ln_kernel(
    const float* __restrict__ x, const float* __restrict__ g,
    const float* __restrict__ b, float* __restrict__ out)
{
    const int row = blockIdx.x;
    const int tid = threadIdx.x;
    const float* xr = x + (size_t)row * CDIM;

    float4 v = *reinterpret_cast<const float4*>(&xr[tid * 4]);
    float s  = v.x + v.y + v.z + v.w;
    float ss = v.x*v.x + v.y*v.y + v.z*v.z + v.w*v.w;

    #pragma unroll
    for (int off = 16; off > 0; off >>= 1) {
        s  += __shfl_xor_sync(0xffffffffu, s,  off);
        ss += __shfl_xor_sync(0xffffffffu, ss, off);
    }
    __shared__ float sm[4], sm2[4];
    const int wid = tid >> 5, lane = tid & 31;
    if (lane == 0) { sm[wid] = s; sm2[wid] = ss; }
    __syncthreads();
    s  = sm[0] + sm[1] + sm[2] + sm[3];
    ss = sm2[0] + sm2[1] + sm2[2] + sm2[3];

    const float mu   = s * (1.0f / CDIM);
    const float var  = ss * (1.0f / CDIM) - mu * mu;
    const float rstd = rsqrtf(var + 1e-5f);

    float4 gg = *reinterpret_cast<const float4*>(&g[tid * 4]);
    float4 bb = *reinterpret_cast<const float4*>(&b[tid * 4]);
    float4 o;
    o.x = to_tf32((v.x - mu) * rstd * gg.x + bb.x);
    o.y = to_tf32((v.y - mu) * rstd * gg.y + bb.y);
    o.z = to_tf32((v.z - mu) * rstd * gg.z + bb.z);
    o.w = to_tf32((v.w - mu) * rstd * gg.w + bb.w);
    *reinterpret_cast<float4*>(&out[(size_t)row * CDIM + tid * 4]) = o;
}

// ---------------------------------------------------------------------------
// tf32 tensor-core GEMM, cp.async double-buffered.
// BM=BN=128, BK=16, 128 threads = 4 warps (2x2), warp tile 64x64.
// ---------------------------------------------------------------------------
template<bool BIAS, bool RELU, bool RES, bool OUTCVT>
__global__ void __launch_bounds__(128, 2) gemm_tc(
    const float* __restrict__ A, const float* __restrict__ B,
    const float* __restrict__ bias, const float* __restrict__ res,
    float* __restrict__ C, int M, int N, int K)
{
    constexpr int BM = 128, BN = 128, BK = 16;
    constexpr int LDAS = 20;
    constexpr int LDBS = 136;

    __shared__ float As[2][BM * LDAS];
    __shared__ float Bs[2][BK * LDBS];

    const int tid  = threadIdx.x;
    const int wid  = tid >> 5;
    const int lane = tid & 31;
    const int g    = lane >> 2;
    const int tg   = lane & 3;

    const int m0 = blockIdx.y * BM;
    const int n0 = blockIdx.x * BN;
    const int wm = (wid & 1) * 64;
    const int wn = (wid >> 1) * 64;

    const int a_r  = tid >> 2;
    const int a_kc = (tid & 3) * 4;
    const int b_kr = tid >> 5;
    const int b_nc = (tid & 31) * 4;

    float acc[4][8][4];
    #pragma unroll
    for (int mt = 0; mt < 4; mt++)
        #pragma unroll
        for (int nt = 0; nt < 8; nt++)
            #pragma unroll
            for (int i = 0; i < 4; i++) acc[mt][nt][i] = 0.0f;

    auto issue_tile = [&](int buf, int k0) {
        #pragma unroll
        for (int i = 0; i < 4; i++) {
            const int row = a_r + 32 * i;
            cp16(smem_u32(&As[buf][row * LDAS + a_kc]),
                 &A[(size_t)(m0 + row) * K + k0 + a_kc]);
            const int kr = b_kr + 4 * i;
            cp16(smem_u32(&Bs[buf][kr * LDBS + b_nc]),
                 &B[(size_t)(k0 + kr) * N + n0 + b_nc]);
        }
        cp_commit();
    };

    issue_tile(0, 0);
    const int NIT = K / BK;

    for (int it = 0; it < NIT; it++) {
        if (it + 1 < NIT) {
            issue_tile((it + 1) & 1, (it + 1) * BK);
            cp_wait<1>();
        } else {
            cp_wait<0>();
        }
        __syncthreads();

        const float* Ab = As[it & 1];
        const float* Bb = Bs[it & 1];

        #pragma unroll
        for (int ks = 0; ks < 2; ks++) {
            const int kb = ks * 8;
            uint32_t af[4][4], bf[8][2];
            #pragma unroll
            for (int mt = 0; mt < 4; mt++) {
                const int mr = wm + mt * 16 + g;
                af[mt][0] = __float_as_uint(Ab[(mr    ) * LDAS + kb + tg]);
                af[mt][1] = __float_as_uint(Ab[(mr + 8) * LDAS + kb + tg]);
                af[mt][2] = __float_as_uint(Ab[(mr    ) * LDAS + kb + tg + 4]);
                af[mt][3] = __float_as_uint(Ab[(mr + 8) * LDAS + kb + tg + 4]);
            }
            #pragma unroll
            for (int nt = 0; nt < 8; nt++) {
                const int nc = wn + nt * 8 + g;
                bf[nt][0] = __float_as_uint(Bb[(kb + tg    ) * LDBS + nc]);
                bf[nt][1] = __float_as_uint(Bb[(kb + tg + 4) * LDBS + nc]);
            }
            #pragma unroll
            for (int mt = 0; mt < 4; mt++)
                #pragma unroll
                for (int nt = 0; nt < 8; nt++)
                    mma_tf32(acc[mt][nt], af[mt], bf[nt]);
        }
        __syncthreads();
    }

    #pragma unroll
    for (int mt = 0; mt < 4; mt++) {
        #pragma unroll
        for (int nt = 0; nt < 8; nt++) {
            const int col = n0 + wn + nt * 8 + 2 * tg;
            float2 bb = make_float2(0.f, 0.f);
            if (BIAS) bb = *reinterpret_cast<const float2*>(&bias[col]);
            #pragma unroll
            for (int half = 0; half < 2; half++) {
                const int row = m0 + wm + mt * 16 + g + half * 8;
                float2 v = make_float2(acc[mt][nt][half * 2 + 0],
                                       acc[mt][nt][half * 2 + 1]);
                if (BIAS) { v.x += bb.x; v.y += bb.y; }
                if (RES) {
                    float2 rr = *reinterpret_cast<const float2*>(
                        &res[(size_t)row * N + col]);
                    v.x += rr.x; v.y += rr.y;
                }
                if (RELU) { v.x = fmaxf(v.x, 0.f); v.y = fmaxf(v.y, 0.f); }
                if (OUTCVT) { v.x = to_tf32(v.x); v.y = to_tf32(v.y); }
                *reinterpret_cast<float2*>(&C[(size_t)row * N + col]) = v;
            }
        }
    }
}

// ---------------------------------------------------------------------------
// Tensor-core causal flash attention (tf32 mma).
// Block = 128 threads (4 warps), 64-query tile of one (b,h).
// grid = (8 [qt, reversed], B*H). Dynamic smem:
//   Qs[64][68] | Ks[2][64][68] | Vs[2][64][72] | Ps[4][16][68]
// Warp w owns query rows w*16..w*16+15. Q fragments hoisted to registers.
// ---------------------------------------------------------------------------
#define LQ 68
#define LV 72
#define QS_F (64 * LQ)           // 4352
#define KS_F (64 * LQ)           // 4352
#define VS_F (64 * LV)           // 4608
#define PS_F (16 * LQ)           // per warp: 1088
#define ATTN_SMEM_BYTES ((QS_F + 2*KS_F + 2*VS_F + 4*PS_F) * 4)

__global__ void __launch_bounds__(128) attn_tc(
    const float* __restrict__ qkv, float* __restrict__ o)
{
    extern __shared__ float smp[];
    float* Qs = smp;                      // QS_F
    float* Ks = Qs + QS_F;                // 2 * KS_F
    float* Vs = Ks + 2 * KS_F;            // 2 * VS_F
    float* Ps = Vs + 2 * VS_F;            // 4 * PS_F

    const int qt  = (int)gridDim.x - 1 - (int)blockIdx.x;   // heavy blocks first
    const int bh  = blockIdx.y;
    const int b   = bh >> 3;
    const int h   = bh & 7;
    const int tid = threadIdx.x;
    const int w   = tid >> 5;
    const int lane = tid & 31;
    const int g    = lane >> 2;
    const int tg   = lane & 3;
    const int q0  = qt * 64;

    const float scale = 0.04419417382415922f;   // 1/sqrt(512)

    const float* qbase = qkv + ((size_t)(b * SEQ + q0)) * QKVN + h * DHEAD;
    const float* kbase = qkv + ((size_t)b * SEQ) * QKVN + 512  + h * DHEAD;
    const float* vbase = qkv + ((size_t)b * SEQ) * QKVN + 1024 + h * DHEAD;

    // ---- load Q tile (64x64) into smem ----
    #pragma unroll
    for (int i = 0; i < 8; i++) {
        int lin = tid + i * 128;              // float4 index, 1024 total
        int row = lin >> 4, col = (lin & 15) * 4;
        *reinterpret_cast<float4*>(&Qs[row * LQ + col]) =
            *reinterpret_cast<const float4*>(&qbase[(size_t)row * QKVN + col]);
    }
    __syncthreads();

    // ---- hoist Q A-fragments: 8 k-steps x 4 regs ----
    uint32_t qf[8][4];
    {
        const int mr = w * 16 + g;
        #pragma unroll
        for (int kb = 0; kb < 8; kb++) {
            qf[kb][0] = __float_as_uint(Qs[(mr    ) * LQ + kb * 8 + tg]);
            qf[kb][1] = __float_as_uint(Qs[(mr + 8) * LQ + kb * 8 + tg]);
            qf[kb][2] = __float_as_uint(Qs[(mr    ) * LQ + kb * 8 + tg + 4]);
            qf[kb][3] = __float_as_uint(Qs[(mr + 8) * LQ + kb * 8 + tg + 4]);
        }
    }

    // ---- K/V tile loader (cp.async) ----
    auto issue_kv = [&](int buf, int j0) {
        float* Kb = Ks + buf * KS_F;
        float* Vb = Vs + buf * VS_F;
        #pragma unroll
        for (int i = 0; i < 8; i++) {
            int lin = tid + i * 128;
            int row = lin >> 4, col = (lin & 15) * 4;
            cp16(smem_u32(&Kb[row * LQ + col]),
                 &kbase[(size_t)(j0 + row) * QKVN + col]);
            cp16(smem_u32(&Vb[row * LV + col]),
                 &vbase[(size_t)(j0 + row) * QKVN + col]);
        }
        cp_commit();
    };

    float oacc[8][4];
    #pragma unroll
    for (int nt = 0; nt < 8; nt++)
        #pragma unroll
        for (int i = 0; i < 4; i++) oacc[nt][i] = 0.0f;
    float m_lo = -INFINITY, m_hi = -INFINITY;
    float l_lo = 0.0f, l_hi = 0.0f;

    float* Pw = Ps + w * PS_F;
    const int ntiles = qt + 1;

    issue_kv(0, 0);

    for (int it = 0; it < ntiles; it++) {
        if (it + 1 < ntiles) {
            issue_kv((it + 1) & 1, (it + 1) * 64);
            cp_wait<1>();
        } else {
            cp_wait<0>();
        }
        __syncthreads();

        const float* Kb = Ks + (it & 1) * KS_F;
        const float* Vb = Vs + (it & 1) * VS_F;

        // ---- S = Q @ K^T (16 queries x 64 keys per warp) ----
        float sacc[8][4];
        #pragma unroll
        for (int nt = 0; nt < 8; nt++)
            #pragma unroll
            for (int i = 0; i < 4; i++) sacc[nt][i] = 0.0f;

        #pragma unroll
        for (int kb = 0; kb < 8; kb++) {
            uint32_t bf[8][2];
            #pragma unroll
            for (int nt = 0; nt < 8; nt++) {
                bf[nt][0] = __float_as_uint(Kb[(nt * 8 + g) * LQ + kb * 8 + tg]);
                bf[nt][1] = __float_as_uint(Kb[(nt * 8 + g) * LQ + kb * 8 + tg + 4]);
            }
            #pragma unroll
            for (int nt = 0; nt < 8; nt++)
                mma_tf32(sacc[nt], qf[kb], bf[nt]);
        }

        // ---- scale + causal mask (only the diagonal tile) ----
        const int j0 = it * 64;
        const bool diag = (it == ntiles - 1) && (j0 == q0);
        const int qr_lo = q0 + w * 16 + g;
        const int qr_hi = qr_lo + 8;
        #pragma unroll
        for (int nt = 0; nt < 8; nt++) {
            const int c0 = j0 + nt * 8 + 2 * tg;
            sacc[nt][0] = (diag && c0     > qr_lo) ? -INFINITY : sacc[nt][0] * scale;
            sacc[nt][1] = (diag && c0 + 1 > qr_lo) ? -INFINITY : sacc[nt][1] * scale;
            sacc[nt][2] = (diag && c0     > qr_hi) ? -INFINITY : sacc[nt][2] * scale;
            sacc[nt][3] = (diag && c0 + 1 > qr_hi) ? -INFINITY : sacc[nt][3] * scale;
        }

        // ---- online softmax ----
        float mx_lo = -INFINITY, mx_hi = -INFINITY;
        #pragma unroll
        for (int nt = 0; nt < 8; nt++) {
            mx_lo = fmaxf(mx_lo, fmaxf(sacc[nt][0], sacc[nt][1]));
            mx_hi = fmaxf(mx_hi, fmaxf(sacc[nt][2], sacc[nt][3]));
        }
        mx_lo = fmaxf(mx_lo, __shfl_xor_sync(0xffffffffu, mx_lo, 1));
        mx_lo = fmaxf(mx_lo, __shfl_xor_sync(0xffffffffu, mx_lo, 2));
        mx_hi = fmaxf(mx_hi, __shfl_xor_sync(0xffffffffu, mx_hi, 1));
        mx_hi = fmaxf(mx_hi, __shfl_xor_sync(0xffffffffu, mx_hi, 2));

        const float mn_lo = fmaxf(m_lo, mx_lo);
        const float mn_hi = fmaxf(m_hi, mx_hi);
        const float c_lo = __expf(m_lo - mn_lo);
        const float c_hi = __expf(m_hi - mn_hi);
        m_lo = mn_lo; m_hi = mn_hi;

        float ts_lo = 0.0f, ts_hi = 0.0f;
        #pragma unroll
        for (int nt = 0; nt < 8; nt++) {
            float p0 = __expf(sacc[nt][0] - m_lo);
            float p1 = __expf(sacc[nt][1] - m_lo);
            float p2 = __expf(sacc[nt][2] - m_hi);
            float p3 = __expf(sacc[nt][3] - m_hi);
            ts_lo += p0 + p1;
            ts_hi += p2 + p3;
            // store P (tf32) into per-warp smem for the PV mma
            Pw[(g    ) * LQ + nt * 8 + 2 * tg    ] = to_tf32(p0);
            Pw[(g    ) * LQ + nt * 8 + 2 * tg + 1] = to_tf32(p1);
            Pw[(g + 8) * LQ + nt * 8 + 2 * tg    ] = to_tf32(p2);
            Pw[(g + 8) * LQ + nt * 8 + 2 * tg + 1] = to_tf32(p3);
        }
        ts_lo += __shfl_xor_sync(0xffffffffu, ts_lo, 1);
        ts_lo += __shfl_xor_sync(0xffffffffu, ts_lo, 2);
        ts_hi += __shfl_xor_sync(0xffffffffu, ts_hi, 1);
        ts_hi += __shfl_xor_sync(0xffffffffu, ts_hi, 2);
        l_lo = l_lo * c_lo + ts_lo;
        l_hi = l_hi * c_hi + ts_hi;

        // rescale O accumulators
        #pragma unroll
        for (int nt = 0; nt < 8; nt++) {
            oacc[nt][0] *= c_lo; oacc[nt][1] *= c_lo;
            oacc[nt][2] *= c_hi; oacc[nt][3] *= c_hi;
        }
        __syncwarp();

        // ---- O += P @ V ----
        #pragma unroll
        for (int kt = 0; kt < 8; kt++) {
            uint32_t af[4];
            af[0] = __float_as_uint(Pw[(g    ) * LQ + kt * 8 + tg]);
            af[1] = __float_as_uint(Pw[(g + 8) * LQ + kt * 8 + tg]);
            af[2] = __float_as_uint(Pw[(g    ) * LQ + kt * 8 + tg + 4]);
            af[3] = __float_as_uint(Pw[(g + 8) * LQ + kt * 8 + tg + 4]);
            #pragma unroll
            for (int nt = 0; nt < 8; nt++) {
                uint32_t bf[2];
                bf[0] = __float_as_uint(Vb[(kt * 8 + tg    ) * LV + nt * 8 + g]);
                bf[1] = __float_as_uint(Vb[(kt * 8 + tg + 4) * LV + nt * 8 + g]);
                mma_tf32(oacc[nt], af, bf);
            }
        }
        __syncthreads();
    }

    // ---- finalize + write (tf32-rounded; feeds proj GEMM) ----
    const float inv_lo = 1.0f / l_lo;
    const float inv_hi = 1.0f / l_hi;
    const int qr = q0 + w * 16 + g;
    float* orow_lo = o + ((size_t)(b * SEQ + qr    )) * CDIM + h * DHEAD;
    float* orow_hi = o + ((size_t)(b * SEQ + qr + 8)) * CDIM + h * DHEAD;
    #pragma unroll
    for (int nt = 0; nt < 8; nt++) {
        const int col = nt * 8 + 2 * tg;
        float2 vlo = make_float2(to_tf32(oacc[nt][0] * inv_lo),
                                 to_tf32(oacc[nt][1] * inv_lo));
        float2 vhi = make_float2(to_tf32(oacc[nt][2] * inv_hi),
                                 to_tf32(oacc[nt][3] * inv_hi));
        *reinterpret_cast<float2*>(&orow_lo[col]) = vlo;
        *reinterpret_cast<float2*>(&orow_hi[col]) = vhi;
    }
}

// ---------------------------------------------------------------------------
// Launch. Inputs (metadata order):
// 0:x 1:wq 2:wk 3:wv 4:w_proj 5:b_proj 6:w1 7:b1 8:w2 9:b2
// 10:ln1_g 11:ln1_b 12:ln2_g 13:ln2_b
// ---------------------------------------------------------------------------
extern "C" void kernel_launch(void* const* d_in, const int* in_sizes, int n_in,
                              void* d_out, int out_size)
{
    const float* x      = (const float*)d_in[0];
    const float* wq     = (const float*)d_in[1];
    const float* wk     = (const float*)d_in[2];
    const float* wv     = (const float*)d_in[3];
    const float* w_proj = (const float*)d_in[4];
    const float* b_proj = (const float*)d_in[5];
    const float* w1     = (const float*)d_in[6];
    const float* b1     = (const float*)d_in[7];
    const float* w2     = (const float*)d_in[8];
    const float* b2     = (const float*)d_in[9];
    const float* ln1_g  = (const float*)d_in[10];
    const float* ln1_b  = (const float*)d_in[11];
    const float* ln2_g  = (const float*)d_in[12];
    const float* ln2_b  = (const float*)d_in[13];
    float* out = (float*)d_out;

    float *h, *qkv, *ob, *h2, *ffn, *w_qkv, *w_p, *w_1, *w_2;
    cudaGetSymbolAddress((void**)&h,     g_h);
    cudaGetSymbolAddress((void**)&qkv,   g_qkv);
    cudaGetSymbolAddress((void**)&ob,    g_o);
    cudaGetSymbolAddress((void**)&h2,    g_h2);
    cudaGetSymbolAddress((void**)&ffn,   g_ffn);
    cudaGetSymbolAddress((void**)&w_qkv, g_wqkv);
    cudaGetSymbolAddress((void**)&w_p,   g_wp);
    cudaGetSymbolAddress((void**)&w_1,   g_w1);
    cudaGetSymbolAddress((void**)&w_2,   g_w2);

    static bool attrs_set = false;
    if (!attrs_set) {
        cudaFuncSetAttribute(attn_tc,
            cudaFuncAttributeMaxDynamicSharedMemorySize, ATTN_SMEM_BYTES);
        attrs_set = true;
    }

    const int M = MROWS;

    // Weight prep (tf32 round + qkv repack)
    prep_qkv<<<(CDIM * QKVN) / 256, 256>>>(wq, wk, wv, w_qkv);
    prep_w<<<(CDIM * CDIM) / 256, 256>>>(w_proj, w_p);
    prep_w<<<(CDIM * FFNDIM) / 256, 256>>>(w1, w_1);
    prep_w<<<(FFNDIM * CDIM) / 256, 256>>>(w2, w_2);

    // ln1 (tf32-rounded out)
    ln_kernel<<<M, 128>>>(x, ln1_g, ln1_b, h);

    // fused qkv projection (tf32-rounded out -> attention operands are tf32)
    gemm_tc<false, false, false, true><<<dim3(QKVN/128, M/128), 128>>>(
        h, w_qkv, nullptr, nullptr, qkv, M, QKVN, CDIM);

    // tensor-core causal attention (tf32-rounded out)
    attn_tc<<<dim3(SEQ/64, BATCH*NHEAD), 128, ATTN_SMEM_BYTES>>>(qkv, ob);

    // x2 = x + o @ w_proj + b_proj -> out
    gemm_tc<true, false, true, false><<<dim3(CDIM/128, M/128), 128>>>(
        ob, w_p, b_proj, x, out, M, CDIM, CDIM);

    // ln2 (tf32-rounded out)
    ln_kernel<<<M, 128>>>(out, ln2_g, ln2_b, h2);

    // ffn1 = relu(h2 @ w1 + b1), tf32-rounded out
    gemm_tc<true, true, false, true><<<dim3(FFNDIM/128, M/128), 128>>>(
        h2, w_1, b1, nullptr, ffn, M, FFNDIM, CDIM);

    // out = out + ffn1 @ w2 + b2
    gemm_tc<true, false, true, false><<<dim3(CDIM/128, M/128), 128>>>(
        ffn, w_2, b2, out, out, M, CDIM, FFNDIM);
}

// round 7
// speedup vs baseline: 5.7209x; 1.6862x over previous
#include <cuda_runtime.h>
#include <cuda_fp16.h>
#include <math.h>
#include <stdint.h>

// Problem constants
#define BATCH 32
#define SEQ   512
#define CDIM  512
#define NHEAD 8
#define DHEAD 64
#define MROWS (BATCH * SEQ)        // 16384
#define FFNDIM (4 * CDIM)          // 2048
#define QKVN  (3 * CDIM)           // 1536

// Scratch (allocation-free rule: __device__ globals)
__device__ __half g_h   [MROWS * CDIM];    // ln1 out (fp16)
__device__ float  g_qkv [MROWS * QKVN];    // fused q|k|v (fp32, feeds tf32 attn)
__device__ __half g_o   [MROWS * CDIM];    // attn out (fp16)
__device__ __half g_h2  [MROWS * CDIM];    // ln2 out (fp16)
__device__ __half g_ffn [MROWS * FFNDIM];  // relu(h2@w1+b1) (fp16)
// fp16 weights, TRANSPOSED to [N][K] (K contiguous)
__device__ __half g_wqkv[QKVN * CDIM];
__device__ __half g_wp  [CDIM * CDIM];
__device__ __half g_w1  [FFNDIM * CDIM];
__device__ __half g_w2  [CDIM * FFNDIM];

// ---------------------------------------------------------------------------
// PTX helpers
// ---------------------------------------------------------------------------
__device__ __forceinline__ float to_tf32(float x) {
    float r; asm("cvt.rna.tf32.f32 %0, %1;" : "=f"(r) : "f"(x)); return r;
}
__device__ __forceinline__ void mma_tf32(float* c, const uint32_t* a, const uint32_t* b) {
    asm volatile(
        "mma.sync.aligned.m16n8k8.row.col.f32.tf32.tf32.f32 "
        "{%0,%1,%2,%3},{%4,%5,%6,%7},{%8,%9},{%0,%1,%2,%3};"
        : "+f"(c[0]), "+f"(c[1]), "+f"(c[2]), "+f"(c[3])
        : "r"(a[0]), "r"(a[1]), "r"(a[2]), "r"(a[3]), "r"(b[0]), "r"(b[1]));
}
__device__ __forceinline__ void mma_f16(float* c, const uint32_t* a, const uint32_t* b) {
    asm volatile(
        "mma.sync.aligned.m16n8k16.row.col.f32.f16.f16.f32 "
        "{%0,%1,%2,%3},{%4,%5,%6,%7},{%8,%9},{%0,%1,%2,%3};"
        : "+f"(c[0]), "+f"(c[1]), "+f"(c[2]), "+f"(c[3])
        : "r"(a[0]), "r"(a[1]), "r"(a[2]), "r"(a[3]), "r"(b[0]), "r"(b[1]));
}
__device__ __forceinline__ uint32_t smem_u32(const void* p) {
    return (uint32_t)__cvta_generic_to_shared(p);
}
__device__ __forceinline__ void cp16(uint32_t dst, const void* src) {
    asm volatile("cp.async.cg.shared.global [%0], [%1], 16;" :: "r"(dst), "l"(src));
}
__device__ __forceinline__ void cp_commit() { asm volatile("cp.async.commit_group;"); }
template<int N> __device__ __forceinline__ void cp_wait() {
    asm volatile("cp.async.wait_group %0;" :: "n"(N));
}

// ---------------------------------------------------------------------------
// Weight prep: tiled transpose W[K][N] -> Wt[N][K] (fp16)
// ---------------------------------------------------------------------------
__global__ void __launch_bounds__(256) prep_wT(
    const float* __restrict__ W, __half* __restrict__ Wt, int K, int N)
{
    __shared__ float sm[32][33];
    const int tx = threadIdx.x, ty = threadIdx.y;
    const int k0 = blockIdx.x * 32, n0 = blockIdx.y * 32;
    #pragma unroll
    for (int i = 0; i < 4; i++)
        sm[ty + 8 * i][tx] = W[(size_t)(k0 + ty + 8 * i) * N + n0 + tx];
    __syncthreads();
    #pragma unroll
    for (int i = 0; i < 4; i++)
        Wt[(size_t)(n0 + ty + 8 * i) * K + k0 + tx] =
            __float2half_rn(sm[tx][ty + 8 * i]);
}

// qkv fused: col n -> (part p, head h, d); source w[(h*C + k)*64 + d]
__global__ void __launch_bounds__(256) prep_qkvT(
    const float* __restrict__ wq, const float* __restrict__ wk,
    const float* __restrict__ wv, __half* __restrict__ Wt)
{
    __shared__ float sm[32][33];
    const int tx = threadIdx.x, ty = threadIdx.y;
    const int k0 = blockIdx.x * 32, n0 = blockIdx.y * 32;
    const int part = n0 >> 9, hh = (n0 >> 6) & 7, d0 = n0 & 32;
    const float* w = (part == 0) ? wq : (part == 1 ? wk : wv);
    #pragma unroll
    for (int i = 0; i < 4; i++)
        sm[ty + 8 * i][tx] =
            w[((size_t)(hh * CDIM + k0 + ty + 8 * i)) * 64 + d0 + tx];
    __syncthreads();
    #pragma unroll
    for (int i = 0; i < 4; i++)
        Wt[(size_t)(n0 + ty + 8 * i) * CDIM + k0 + tx] =
            __float2half_rn(sm[tx][ty + 8 * i]);
}

// ---------------------------------------------------------------------------
// LayerNorm: one block per row (C=512), 128 threads, fp16 output
// ---------------------------------------------------------------------------
__global__ void __launch_bounds__(128) ln_kernel(
    const float* __restrict__ x, const float* __restrict__ g,
    const float* __restrict__ b, __half* __restrict__ out)
{
    const int row = blockIdx.x;
    const int tid = threadIdx.x;
    const float* xr = x + (size_t)row * CDIM;

    float4 v = *reinterpret_cast<const float4*>(&xr[tid * 4]);
    float s  = v.x + v.y + v.z + v.w;
    float ss = v.x*v.x + v.y*v.y + v.z*v.z + v.w*v.w;
    #pragma unroll
    for (int off = 16; off > 0; off >>= 1) {
        s  += __shfl_xor_sync(0xffffffffu, s,  off);
        ss += __shfl_xor_sync(0xffffffffu, ss, off);
    }
    __shared__ float sm[4], sm2[4];
    const int wid = tid >> 5, lane = tid & 31;
    if (lane == 0) { sm[wid] = s; sm2[wid] = ss; }
    __syncthreads();
    s  = sm[0] + sm[1] + sm[2] + sm[3];
    ss = sm2[0] + sm2[1] + sm2[2] + sm2[3];

    const float mu   = s * (1.0f / CDIM);
    const float var  = ss * (1.0f / CDIM) - mu * mu;
    const float rstd = rsqrtf(var + 1e-5f);

    float4 gg = *reinterpret_cast<const float4*>(&g[tid * 4]);
    float4 bb = *reinterpret_cast<const float4*>(&b[tid * 4]);
    __half2 h0 = __floats2half2_rn((v.x - mu) * rstd * gg.x + bb.x,
                                   (v.y - mu) * rstd * gg.y + bb.y);
    __half2 h1 = __floats2half2_rn((v.z - mu) * rstd * gg.z + bb.z,
                                   (v.w - mu) * rstd * gg.w + bb.w);
    __half2* op = reinterpret_cast<__half2*>(out + (size_t)row * CDIM + tid * 4);
    op[0] = h0; op[1] = h1;
}

// ---------------------------------------------------------------------------
// fp16 tensor-core GEMM: C[M,N] = A[M,K] @ Wt[N,K]^T (+bias)(+res)(relu)
// BM=BN=128, BK=64, 128 threads = 4 warps (2x2), warp tile 64x64.
// A smem [128][72] halves, B smem [128][72] halves (both K-contiguous rows,
// stride 72 halves = 144B -> fragment LDS.32 pattern 4g+tg is conflict-free).
// cp.async double-buffered. Accum fp32; OutT = float or __half.
// ---------------------------------------------------------------------------
#define FBM 128
#define FBK 64
#define LDH 72                              // halves per smem row
#define TILE_H (FBM * LDH)                  // 9216 halves per tile
#define GSMEM_BYTES (2 * 2 * TILE_H * 2 + 512 + 256)

template<typename OutT, bool BIAS, bool RELU, bool RES>
__global__ void __launch_bounds__(128, 2) gemm_f16(
    const __half* __restrict__ A, const __half* __restrict__ Bw,
    const float* __restrict__ bias, const float* __restrict__ res,
    OutT* __restrict__ C, int M, int N, int K)
{
    extern __shared__ char dsm[];
    __half* As = reinterpret_cast<__half*>(dsm);            // 2 * TILE_H
    __half* Bs = As + 2 * TILE_H;                           // 2 * TILE_H
    float* bias_s = reinterpret_cast<float*>(Bs + 2 * TILE_H);

    const int tid  = threadIdx.x;
    const int w    = tid >> 5;
    const int lane = tid & 31;
    const int g    = lane >> 2;
    const int tg   = lane & 3;

    const int m0 = blockIdx.y * FBM;
    const int n0 = blockIdx.x * FBM;
    const int wm = (w & 1) * 64;
    const int wn = (w >> 1) * 64;

    if (BIAS) bias_s[tid] = bias[n0 + tid];

    float acc[4][8][4];
    #pragma unroll
    for (int mt = 0; mt < 4; mt++)
        #pragma unroll
        for (int nt = 0; nt < 8; nt++)
            #pragma unroll
            for (int i = 0; i < 4; i++) acc[mt][nt][i] = 0.0f;

    const uint32_t as_base = smem_u32(As);
    const uint32_t bs_base = smem_u32(Bs);

    auto load_tile = [&](int buf, int k0) {
        const uint32_t a_s = as_base + buf * TILE_H * 2;
        const uint32_t b_s = bs_base + buf * TILE_H * 2;
        #pragma unroll
        for (int j = 0; j < 8; j++) {
            int c = tid + 128 * j;          // 1024 chunks of 16B
            int row = c >> 3, ch = c & 7;   // 8 chunks per 64-half row
            cp16(a_s + row * (LDH * 2) + ch * 16,
                 A + (size_t)(m0 + row) * K + k0 + ch * 8);
            cp16(b_s + row * (LDH * 2) + ch * 16,
                 Bw + (size_t)(n0 + row) * K + k0 + ch * 8);
        }
        cp_commit();
    };

    const int NIT = K / FBK;
    load_tile(0, 0);
    if (NIT > 1) load_tile(1, FBK);

    for (int it = 0; it < NIT; it++) {
        const int buf = it & 1;
        if (it + 1 < NIT) cp_wait<1>(); else cp_wait<0>();
        __syncthreads();

        const __half* Ab = As + buf * TILE_H;
        const __half* Bb = Bs + buf * TILE_H;

        #pragma unroll
        for (int ks = 0; ks < 4; ks++) {
            const int kb = ks * 16;
            uint32_t af[4][4], bf[8][2];
            #pragma unroll
            for (int mt = 0; mt < 4; mt++) {
                const int mr = wm + mt * 16 + g;
                af[mt][0] = *reinterpret_cast<const uint32_t*>(&Ab[(mr    ) * LDH + kb + 2 * tg]);
                af[mt][1] = *reinterpret_cast<const uint32_t*>(&Ab[(mr + 8) * LDH + kb + 2 * tg]);
                af[mt][2] = *reinterpret_cast<const uint32_t*>(&Ab[(mr    ) * LDH + kb + 2 * tg + 8]);
                af[mt][3] = *reinterpret_cast<const uint32_t*>(&Ab[(mr + 8) * LDH + kb + 2 * tg + 8]);
            }
            #pragma unroll
            for (int nt = 0; nt < 8; nt++) {
                const int nc = wn + nt * 8 + g;
                bf[nt][0] = *reinterpret_cast<const uint32_t*>(&Bb[nc * LDH + kb + 2 * tg]);
                bf[nt][1] = *reinterpret_cast<const uint32_t*>(&Bb[nc * LDH + kb + 2 * tg + 8]);
            }
            #pragma unroll
            for (int mt = 0; mt < 4; mt++)
                #pragma unroll
                for (int nt = 0; nt < 8; nt++)
                    mma_f16(acc[mt][nt], af[mt], bf[nt]);
        }
        __syncthreads();

        if (it + 2 < NIT) load_tile(buf, (it + 2) * FBK);
    }

    // Epilogue
    #pragma unroll
    for (int mt = 0; mt < 4; mt++) {
        #pragma unroll
        for (int nt = 0; nt < 8; nt++) {
            const int col = n0 + wn + nt * 8 + 2 * tg;
            float2 bb = make_float2(0.f, 0.f);
            if (BIAS) {
                bb.x = bias_s[wn + nt * 8 + 2 * tg];
                bb.y = bias_s[wn + nt * 8 + 2 * tg + 1];
            }
            #pragma unroll
            for (int half_i = 0; half_i < 2; half_i++) {
                const int row = m0 + wm + mt * 16 + g + half_i * 8;
                float2 v = make_float2(acc[mt][nt][half_i * 2 + 0],
                                       acc[mt][nt][half_i * 2 + 1]);
                if (BIAS) { v.x += bb.x; v.y += bb.y; }
                if (RES) {
                    float2 rr = *reinterpret_cast<const float2*>(
                        &res[(size_t)row * N + col]);
                    v.x += rr.x; v.y += rr.y;
                }
                if (RELU) { v.x = fmaxf(v.x, 0.f); v.y = fmaxf(v.y, 0.f); }
                if (sizeof(OutT) == 2) {
                    *reinterpret_cast<__half2*>(
                        reinterpret_cast<__half*>(C) + (size_t)row * N + col) =
                        __floats2half2_rn(v.x, v.y);
                } else {
                    *reinterpret_cast<float2*>(
                        reinterpret_cast<float*>(C) + (size_t)row * N + col) = v;
                }
            }
        }
    }
}

// ---------------------------------------------------------------------------
// Tensor-core causal flash attention (tf32 mma.sync), fp16 output.
// ---------------------------------------------------------------------------
#define LQ 68
#define LV 72
#define QS_F (64 * LQ)
#define KS_F (64 * LQ)
#define VS_F (64 * LV)
#define PS_F (16 * LQ)
#define ATTN_SMEM_BYTES ((QS_F + 2*KS_F + 2*VS_F + 4*PS_F) * 4)

__global__ void __launch_bounds__(128) attn_tc(
    const float* __restrict__ qkv, __half* __restrict__ o)
{
    extern __shared__ float smp[];
    float* Qs = smp;
    float* Ks = Qs + QS_F;
    float* Vs = Ks + 2 * KS_F;
    float* Ps = Vs + 2 * VS_F;

    const int qt  = (int)gridDim.x - 1 - (int)blockIdx.x;
    const int bh  = blockIdx.y;
    const int b   = bh >> 3;
    const int h   = bh & 7;
    const int tid = threadIdx.x;
    const int w   = tid >> 5;
    const int lane = tid & 31;
    const int g    = lane >> 2;
    const int tg   = lane & 3;
    const int q0  = qt * 64;

    const float scale = 0.04419417382415922f;   // 1/sqrt(512)

    const float* qbase = qkv + ((size_t)(b * SEQ + q0)) * QKVN + h * DHEAD;
    const float* kbase = qkv + ((size_t)b * SEQ) * QKVN + 512  + h * DHEAD;
    const float* vbase = qkv + ((size_t)b * SEQ) * QKVN + 1024 + h * DHEAD;

    #pragma unroll
    for (int i = 0; i < 8; i++) {
        int lin = tid + i * 128;
        int row = lin >> 4, col = (lin & 15) * 4;
        *reinterpret_cast<float4*>(&Qs[row * LQ + col]) =
            *reinterpret_cast<const float4*>(&qbase[(size_t)row * QKVN + col]);
    }
    __syncthreads();

    uint32_t qf[8][4];
    {
        const int mr = w * 16 + g;
        #pragma unroll
        for (int kb = 0; kb < 8; kb++) {
            qf[kb][0] = __float_as_uint(Qs[(mr    ) * LQ + kb * 8 + tg]);
            qf[kb][1] = __float_as_uint(Qs[(mr + 8) * LQ + kb * 8 + tg]);
            qf[kb][2] = __float_as_uint(Qs[(mr    ) * LQ + kb * 8 + tg + 4]);
            qf[kb][3] = __float_as_uint(Qs[(mr + 8) * LQ + kb * 8 + tg + 4]);
        }
    }

    auto issue_kv = [&](int buf, int j0) {
        float* Kb = Ks + buf * KS_F;
        float* Vb = Vs + buf * VS_F;
        #pragma unroll
        for (int i = 0; i < 8; i++) {
            int lin = tid + i * 128;
            int row = lin >> 4, col = (lin & 15) * 4;
            cp16(smem_u32(&Kb[row * LQ + col]),
                 &kbase[(size_t)(j0 + row) * QKVN + col]);
            cp16(smem_u32(&Vb[row * LV + col]),
                 &vbase[(size_t)(j0 + row) * QKVN + col]);
        }
        cp_commit();
    };

    float oacc[8][4];
    #pragma unroll
    for (int nt = 0; nt < 8; nt++)
        #pragma unroll
        for (int i = 0; i < 4; i++) oacc[nt][i] = 0.0f;
    float m_lo = -INFINITY, m_hi = -INFINITY;
    float l_lo = 0.0f, l_hi = 0.0f;

    float* Pw = Ps + w * PS_F;
    const int ntiles = qt + 1;

    issue_kv(0, 0);

    for (int it = 0; it < ntiles; it++) {
        if (it + 1 < ntiles) {
            issue_kv((it + 1) & 1, (it + 1) * 64);
            cp_wait<1>();
        } else {
            cp_wait<0>();
        }
        __syncthreads();

        const float* Kb = Ks + (it & 1) * KS_F;
        const float* Vb = Vs + (it & 1) * VS_F;

        float sacc[8][4];
        #pragma unroll
        for (int nt = 0; nt < 8; nt++)
            #pragma unroll
            for (int i = 0; i < 4; i++) sacc[nt][i] = 0.0f;

        #pragma unroll
        for (int kb = 0; kb < 8; kb++) {
            uint32_t bf[8][2];
            #pragma unroll
            for (int nt = 0; nt < 8; nt++) {
                bf[nt][0] = __float_as_uint(Kb[(nt * 8 + g) * LQ + kb * 8 + tg]);
                bf[nt][1] = __float_as_uint(Kb[(nt * 8 + g) * LQ + kb * 8 + tg + 4]);
            }
            #pragma unroll
            for (int nt = 0; nt < 8; nt++)
                mma_tf32(sacc[nt], qf[kb], bf[nt]);
        }

        const int j0 = it * 64;
        const bool diag = (it == ntiles - 1) && (j0 == q0);
        const int qr_lo = q0 + w * 16 + g;
        const int qr_hi = qr_lo + 8;
        #pragma unroll
        for (int nt = 0; nt < 8; nt++) {
            const int c0 = j0 + nt * 8 + 2 * tg;
            sacc[nt][0] = (diag && c0     > qr_lo) ? -INFINITY : sacc[nt][0] * scale;
            sacc[nt][1] = (diag && c0 + 1 > qr_lo) ? -INFINITY : sacc[nt][1] * scale;
            sacc[nt][2] = (diag && c0     > qr_hi) ? -INFINITY : sacc[nt][2] * scale;
            sacc[nt][3] = (diag && c0 + 1 > qr_hi) ? -INFINITY : sacc[nt][3] * scale;
        }

        float mx_lo = -INFINITY, mx_hi = -INFINITY;
        #pragma unroll
        for (int nt = 0; nt < 8; nt++) {
            mx_lo = fmaxf(mx_lo, fmaxf(sacc[nt][0], sacc[nt][1]));
            mx_hi = fmaxf(mx_hi, fmaxf(sacc[nt][2], sacc[nt][3]));
        }
        mx_lo = fmaxf(mx_lo, __shfl_xor_sync(0xffffffffu, mx_lo, 1));
        mx_lo = fmaxf(mx_lo, __shfl_xor_sync(0xffffffffu, mx_lo, 2));
        mx_hi = fmaxf(mx_hi, __shfl_xor_sync(0xffffffffu, mx_hi, 1));
        mx_hi = fmaxf(mx_hi, __shfl_xor_sync(0xffffffffu, mx_hi, 2));

        const float mn_lo = fmaxf(m_lo, mx_lo);
        const float mn_hi = fmaxf(m_hi, mx_hi);
        const float c_lo = __expf(m_lo - mn_lo);
        const float c_hi = __expf(m_hi - mn_hi);
        m_lo = mn_lo; m_hi = mn_hi;

        float ts_lo = 0.0f, ts_hi = 0.0f;
        #pragma unroll
        for (int nt = 0; nt < 8; nt++) {
            float p0 = __expf(sacc[nt][0] - m_lo);
            float p1 = __expf(sacc[nt][1] - m_lo);
            float p2 = __expf(sacc[nt][2] - m_hi);
            float p3 = __expf(sacc[nt][3] - m_hi);
            ts_lo += p0 + p1;
            ts_hi += p2 + p3;
            Pw[(g    ) * LQ + nt * 8 + 2 * tg    ] = to_tf32(p0);
            Pw[(g    ) * LQ + nt * 8 + 2 * tg + 1] = to_tf32(p1);
            Pw[(g + 8) * LQ + nt * 8 + 2 * tg    ] = to_tf32(p2);
            Pw[(g + 8) * LQ + nt * 8 + 2 * tg + 1] = to_tf32(p3);
        }
        ts_lo += __shfl_xor_sync(0xffffffffu, ts_lo, 1);
        ts_lo += __shfl_xor_sync(0xffffffffu, ts_lo, 2);
        ts_hi += __shfl_xor_sync(0xffffffffu, ts_hi, 1);
        ts_hi += __shfl_xor_sync(0xffffffffu, ts_hi, 2);
        l_lo = l_lo * c_lo + ts_lo;
        l_hi = l_hi * c_hi + ts_hi;

        #pragma unroll
        for (int nt = 0; nt < 8; nt++) {
            oacc[nt][0] *= c_lo; oacc[nt][1] *= c_lo;
            oacc[nt][2] *= c_hi; oacc[nt][3] *= c_hi;
        }
        __syncwarp();

        #pragma unroll
        for (int kt = 0; kt < 8; kt++) {
            uint32_t af[4];
            af[0] = __float_as_uint(Pw[(g    ) * LQ + kt * 8 + tg]);
            af[1] = __float_as_uint(Pw[(g + 8) * LQ + kt * 8 + tg]);
            af[2] = __float_as_uint(Pw[(g    ) * LQ + kt * 8 + tg + 4]);
            af[3] = __float_as_uint(Pw[(g + 8) * LQ + kt * 8 + tg + 4]);
            #pragma unroll
            for (int nt = 0; nt < 8; nt++) {
                uint32_t bf[2];
                bf[0] = __float_as_uint(Vb[(kt * 8 + tg    ) * LV + nt * 8 + g]);
                bf[1] = __float_as_uint(Vb[(kt * 8 + tg + 4) * LV + nt * 8 + g]);
                mma_tf32(oacc[nt], af, bf);
            }
        }
        __syncthreads();
    }

    const float inv_lo = 1.0f / l_lo;
    const float inv_hi = 1.0f / l_hi;
    const int qr = q0 + w * 16 + g;
    __half* orow_lo = o + ((size_t)(b * SEQ + qr    )) * CDIM + h * DHEAD;
    __half* orow_hi = o + ((size_t)(b * SEQ + qr + 8)) * CDIM + h * DHEAD;
    #pragma unroll
    for (int nt = 0; nt < 8; nt++) {
        const int col = nt * 8 + 2 * tg;
        *reinterpret_cast<__half2*>(&orow_lo[col]) =
            __floats2half2_rn(oacc[nt][0] * inv_lo, oacc[nt][1] * inv_lo);
        *reinterpret_cast<__half2*>(&orow_hi[col]) =
            __floats2half2_rn(oacc[nt][2] * inv_hi, oacc[nt][3] * inv_hi);
    }
}

// ---------------------------------------------------------------------------
// Launch. Inputs: 0:x 1:wq 2:wk 3:wv 4:w_proj 5:b_proj 6:w1 7:b1 8:w2 9:b2
//                 10:ln1_g 11:ln1_b 12:ln2_g 13:ln2_b
// ---------------------------------------------------------------------------
extern "C" void kernel_launch(void* const* d_in, const int* in_sizes, int n_in,
                              void* d_out, int out_size)
{
    const float* x      = (const float*)d_in[0];
    const float* wq     = (const float*)d_in[1];
    const float* wk     = (const float*)d_in[2];
    const float* wv     = (const float*)d_in[3];
    const float* w_proj = (const float*)d_in[4];
    const float* b_proj = (const float*)d_in[5];
    const float* w1     = (const float*)d_in[6];
    const float* b1     = (const float*)d_in[7];
    const float* w2     = (const float*)d_in[8];
    const float* b2     = (const float*)d_in[9];
    const float* ln1_g  = (const float*)d_in[10];
    const float* ln1_b  = (const float*)d_in[11];
    const float* ln2_g  = (const float*)d_in[12];
    const float* ln2_b  = (const float*)d_in[13];
    float* out = (float*)d_out;

    __half *h, *ob, *h2, *ffn, *w_qkvT, *w_pT, *w_1T, *w_2T;
    float *qkv;
    cudaGetSymbolAddress((void**)&h,      g_h);
    cudaGetSymbolAddress((void**)&qkv,    g_qkv);
    cudaGetSymbolAddress((void**)&ob,     g_o);
    cudaGetSymbolAddress((void**)&h2,     g_h2);
    cudaGetSymbolAddress((void**)&ffn,    g_ffn);
    cudaGetSymbolAddress((void**)&w_qkvT, g_wqkv);
    cudaGetSymbolAddress((void**)&w_pT,   g_wp);
    cudaGetSymbolAddress((void**)&w_1T,   g_w1);
    cudaGetSymbolAddress((void**)&w_2T,   g_w2);

    static bool attrs_set = false;
    if (!attrs_set) {
        cudaFuncSetAttribute(attn_tc,
            cudaFuncAttributeMaxDynamicSharedMemorySize, ATTN_SMEM_BYTES);
        cudaFuncSetAttribute(gemm_f16<float, false, false, false>,
            cudaFuncAttributeMaxDynamicSharedMemorySize, GSMEM_BYTES);
        cudaFuncSetAttribute(gemm_f16<float, true, false, true>,
            cudaFuncAttributeMaxDynamicSharedMemorySize, GSMEM_BYTES);
        cudaFuncSetAttribute(gemm_f16<__half, true, true, false>,
            cudaFuncAttributeMaxDynamicSharedMemorySize, GSMEM_BYTES);
        attrs_set = true;
    }

    const int M = MROWS;
    dim3 tb(32, 8);

    // Weight prep: fp16 round + transpose to [N][K]
    prep_qkvT<<<dim3(CDIM / 32, QKVN / 32), tb>>>(wq, wk, wv, w_qkvT);
    prep_wT<<<dim3(CDIM / 32, CDIM / 32), tb>>>(w_proj, w_pT, CDIM, CDIM);
    prep_wT<<<dim3(CDIM / 32, FFNDIM / 32), tb>>>(w1, w_1T, CDIM, FFNDIM);
    prep_wT<<<dim3(FFNDIM / 32, CDIM / 32), tb>>>(w2, w_2T, FFNDIM, CDIM);

    // ln1 (fp16 out)
    ln_kernel<<<M, 128>>>(x, ln1_g, ln1_b, h);

    // fused qkv projection (fp32 out for tf32 attention)
    gemm_f16<float, false, false, false>
        <<<dim3(QKVN / FBM, M / FBM), 128, GSMEM_BYTES>>>(
        h, w_qkvT, nullptr, nullptr, qkv, M, QKVN, CDIM);

    // causal attention (fp16 out)
    attn_tc<<<dim3(SEQ / 64, BATCH * NHEAD), 128, ATTN_SMEM_BYTES>>>(qkv, ob);

    // x2 = x + o @ w_proj + b_proj -> out (fp32)
    gemm_f16<float, true, false, true>
        <<<dim3(CDIM / FBM, M / FBM), 128, GSMEM_BYTES>>>(
        ob, w_pT, b_proj, x, out, M, CDIM, CDIM);

    // ln2 (fp16 out)
    ln_kernel<<<M, 128>>>(out, ln2_g, ln2_b, h2);

    // ffn1 = relu(h2 @ w1 + b1) (fp16 out)
    gemm_f16<__half, true, true, false>
        <<<dim3(FFNDIM / FBM, M / FBM), 128, GSMEM_BYTES>>>(
        h2, w_1T, b1, nullptr, ffn, M, FFNDIM, CDIM);

    // out = out + ffn1 @ w2 + b2 (fp32)
    gemm_f16<float, true, false, true>
        <<<dim3(CDIM / FBM, M / FBM), 128, GSMEM_BYTES>>>(
        ffn, w_2T, b2, out, out, M, CDIM, FFNDIM);
}

// round 8
// speedup vs baseline: 6.5139x; 1.1386x over previous
#include <cuda_runtime.h>
#include <cuda_fp16.h>
#include <math.h>
#include <stdint.h>

// Problem constants
#define BATCH 32
#define SEQ   512
#define CDIM  512
#define NHEAD 8
#define DHEAD 64
#define MROWS (BATCH * SEQ)        // 16384
#define FFNDIM (4 * CDIM)          // 2048
#define QKVN  (3 * CDIM)           // 1536

// Scratch (allocation-free rule: __device__ globals)
__device__ __half g_h   [MROWS * CDIM];    // ln1 out (fp16)
__device__ __half g_qkv [MROWS * QKVN];    // fused q|k|v (fp16)
__device__ __half g_o   [MROWS * CDIM];    // attn out (fp16)
__device__ __half g_h2  [MROWS * CDIM];    // ln2 out (fp16)
__device__ __half g_ffn [MROWS * FFNDIM];  // relu(h2@w1+b1) (fp16)
// fp16 weights, TRANSPOSED to [N][K] (K contiguous)
__device__ __half g_wqkv[QKVN * CDIM];
__device__ __half g_wp  [CDIM * CDIM];
__device__ __half g_w1  [FFNDIM * CDIM];
__device__ __half g_w2  [CDIM * FFNDIM];

// ---------------------------------------------------------------------------
// PTX helpers
// ---------------------------------------------------------------------------
__device__ __forceinline__ void mma_f16(float* c, const uint32_t* a, const uint32_t* b) {
    asm volatile(
        "mma.sync.aligned.m16n8k16.row.col.f32.f16.f16.f32 "
        "{%0,%1,%2,%3},{%4,%5,%6,%7},{%8,%9},{%0,%1,%2,%3};"
        : "+f"(c[0]), "+f"(c[1]), "+f"(c[2]), "+f"(c[3])
        : "r"(a[0]), "r"(a[1]), "r"(a[2]), "r"(a[3]), "r"(b[0]), "r"(b[1]));
}
__device__ __forceinline__ uint32_t smem_u32(const void* p) {
    return (uint32_t)__cvta_generic_to_shared(p);
}
__device__ __forceinline__ void cp16(uint32_t dst, const void* src) {
    asm volatile("cp.async.cg.shared.global [%0], [%1], 16;" :: "r"(dst), "l"(src));
}
__device__ __forceinline__ void cp_commit() { asm volatile("cp.async.commit_group;"); }
template<int N> __device__ __forceinline__ void cp_wait() {
    asm volatile("cp.async.wait_group %0;" :: "n"(N));
}
__device__ __forceinline__ void ldmatrix_x4_trans(
    uint32_t& r0, uint32_t& r1, uint32_t& r2, uint32_t& r3, uint32_t addr)
{
    asm volatile("ldmatrix.sync.aligned.m8n8.x4.trans.shared.b16 {%0,%1,%2,%3}, [%4];"
        : "=r"(r0), "=r"(r1), "=r"(r2), "=r"(r3) : "r"(addr));
}

// ---------------------------------------------------------------------------
// Weight prep: tiled transpose W[K][N] -> Wt[N][K] (fp16)
// ---------------------------------------------------------------------------
__global__ void __launch_bounds__(256) prep_wT(
    const float* __restrict__ W, __half* __restrict__ Wt, int K, int N)
{
    __shared__ float sm[32][33];
    const int tx = threadIdx.x, ty = threadIdx.y;
    const int k0 = blockIdx.x * 32, n0 = blockIdx.y * 32;
    #pragma unroll
    for (int i = 0; i < 4; i++)
        sm[ty + 8 * i][tx] = W[(size_t)(k0 + ty + 8 * i) * N + n0 + tx];
    __syncthreads();
    #pragma unroll
    for (int i = 0; i < 4; i++)
        Wt[(size_t)(n0 + ty + 8 * i) * K + k0 + tx] =
            __float2half_rn(sm[tx][ty + 8 * i]);
}

// qkv fused: col n -> (part p, head h, d); source w[(h*C + k)*64 + d]
__global__ void __launch_bounds__(256) prep_qkvT(
    const float* __restrict__ wq, const float* __restrict__ wk,
    const float* __restrict__ wv, __half* __restrict__ Wt)
{
    __shared__ float sm[32][33];
    const int tx = threadIdx.x, ty = threadIdx.y;
    const int k0 = blockIdx.x * 32, n0 = blockIdx.y * 32;
    const int part = n0 >> 9, hh = (n0 >> 6) & 7, d0 = n0 & 32;
    const float* w = (part == 0) ? wq : (part == 1 ? wk : wv);
    #pragma unroll
    for (int i = 0; i < 4; i++)
        sm[ty + 8 * i][tx] =
            w[((size_t)(hh * CDIM + k0 + ty + 8 * i)) * 64 + d0 + tx];
    __syncthreads();
    #pragma unroll
    for (int i = 0; i < 4; i++)
        Wt[(size_t)(n0 + ty + 8 * i) * CDIM + k0 + tx] =
            __float2half_rn(sm[tx][ty + 8 * i]);
}

// ---------------------------------------------------------------------------
// LayerNorm: one block per row (C=512), 128 threads, fp16 output
// ---------------------------------------------------------------------------
__global__ void __launch_bounds__(128) ln_kernel(
    const float* __restrict__ x, const float* __restrict__ g,
    const float* __restrict__ b, __half* __restrict__ out)
{
    const int row = blockIdx.x;
    const int tid = threadIdx.x;
    const float* xr = x + (size_t)row * CDIM;

    float4 v = *reinterpret_cast<const float4*>(&xr[tid * 4]);
    float s  = v.x + v.y + v.z + v.w;
    float ss = v.x*v.x + v.y*v.y + v.z*v.z + v.w*v.w;
    #pragma unroll
    for (int off = 16; off > 0; off >>= 1) {
        s  += __shfl_xor_sync(0xffffffffu, s,  off);
        ss += __shfl_xor_sync(0xffffffffu, ss, off);
    }
    __shared__ float sm[4], sm2[4];
    const int wid = tid >> 5, lane = tid & 31;
    if (lane == 0) { sm[wid] = s; sm2[wid] = ss; }
    __syncthreads();
    s  = sm[0] + sm[1] + sm[2] + sm[3];
    ss = sm2[0] + sm2[1] + sm2[2] + sm2[3];

    const float mu   = s * (1.0f / CDIM);
    const float var  = ss * (1.0f / CDIM) - mu * mu;
    const float rstd = rsqrtf(var + 1e-5f);

    float4 gg = *reinterpret_cast<const float4*>(&g[tid * 4]);
    float4 bb = *reinterpret_cast<const float4*>(&b[tid * 4]);
    __half2 h0 = __floats2half2_rn((v.x - mu) * rstd * gg.x + bb.x,
                                   (v.y - mu) * rstd * gg.y + bb.y);
    __half2 h1 = __floats2half2_rn((v.z - mu) * rstd * gg.z + bb.z,
                                   (v.w - mu) * rstd * gg.w + bb.w);
    __half2* op = reinterpret_cast<__half2*>(out + (size_t)row * CDIM + tid * 4);
    op[0] = h0; op[1] = h1;
}

// ---------------------------------------------------------------------------
// fp16 tensor-core GEMM: C[M,N] = A[M,K] @ Wt[N,K]^T (+bias)(+res)(relu)
// BM=BN=128, BK=64, 128 threads = 4 warps (2x2), warp tile 64x64.
// ---------------------------------------------------------------------------
#define FBM 128
#define FBK 64
#define LDHG 72                             // halves per smem row
#define TILE_H (FBM * LDHG)                 // 9216 halves per tile
#define GSMEM_BYTES (2 * 2 * TILE_H * 2 + 512 + 256)

template<typename OutT, bool BIAS, bool RELU, bool RES>
__global__ void __launch_bounds__(128, 2) gemm_f16(
    const __half* __restrict__ A, const __half* __restrict__ Bw,
    const float* __restrict__ bias, const float* __restrict__ res,
    OutT* __restrict__ C, int M, int N, int K)
{
    extern __shared__ char dsm[];
    __half* As = reinterpret_cast<__half*>(dsm);
    __half* Bs = As + 2 * TILE_H;
    float* bias_s = reinterpret_cast<float*>(Bs + 2 * TILE_H);

    const int tid  = threadIdx.x;
    const int w    = tid >> 5;
    const int lane = tid & 31;
    const int g    = lane >> 2;
    const int tg   = lane & 3;

    const int m0 = blockIdx.y * FBM;
    const int n0 = blockIdx.x * FBM;
    const int wm = (w & 1) * 64;
    const int wn = (w >> 1) * 64;

    if (BIAS) bias_s[tid] = bias[n0 + tid];

    float acc[4][8][4];
    #pragma unroll
    for (int mt = 0; mt < 4; mt++)
        #pragma unroll
        for (int nt = 0; nt < 8; nt++)
            #pragma unroll
            for (int i = 0; i < 4; i++) acc[mt][nt][i] = 0.0f;

    const uint32_t as_base = smem_u32(As);
    const uint32_t bs_base = smem_u32(Bs);

    auto load_tile = [&](int buf, int k0) {
        const uint32_t a_s = as_base + buf * TILE_H * 2;
        const uint32_t b_s = bs_base + buf * TILE_H * 2;
        #pragma unroll
        for (int j = 0; j < 8; j++) {
            int c = tid + 128 * j;
            int row = c >> 3, ch = c & 7;
            cp16(a_s + row * (LDHG * 2) + ch * 16,
                 A + (size_t)(m0 + row) * K + k0 + ch * 8);
            cp16(b_s + row * (LDHG * 2) + ch * 16,
                 Bw + (size_t)(n0 + row) * K + k0 + ch * 8);
        }
        cp_commit();
    };

    const int NIT = K / FBK;
    load_tile(0, 0);
    if (NIT > 1) load_tile(1, FBK);

    for (int it = 0; it < NIT; it++) {
        const int buf = it & 1;
        if (it + 1 < NIT) cp_wait<1>(); else cp_wait<0>();
        __syncthreads();

        const __half* Ab = As + buf * TILE_H;
        const __half* Bb = Bs + buf * TILE_H;

        #pragma unroll
        for (int ks = 0; ks < 4; ks++) {
            const int kb = ks * 16;
            uint32_t af[4][4], bf[8][2];
            #pragma unroll
            for (int mt = 0; mt < 4; mt++) {
                const int mr = wm + mt * 16 + g;
                af[mt][0] = *reinterpret_cast<const uint32_t*>(&Ab[(mr    ) * LDHG + kb + 2 * tg]);
                af[mt][1] = *reinterpret_cast<const uint32_t*>(&Ab[(mr + 8) * LDHG + kb + 2 * tg]);
                af[mt][2] = *reinterpret_cast<const uint32_t*>(&Ab[(mr    ) * LDHG + kb + 2 * tg + 8]);
                af[mt][3] = *reinterpret_cast<const uint32_t*>(&Ab[(mr + 8) * LDHG + kb + 2 * tg + 8]);
            }
            #pragma unroll
            for (int nt = 0; nt < 8; nt++) {
                const int nc = wn + nt * 8 + g;
                bf[nt][0] = *reinterpret_cast<const uint32_t*>(&Bb[nc * LDHG + kb + 2 * tg]);
                bf[nt][1] = *reinterpret_cast<const uint32_t*>(&Bb[nc * LDHG + kb + 2 * tg + 8]);
            }
            #pragma unroll
            for (int mt = 0; mt < 4; mt++)
                #pragma unroll
                for (int nt = 0; nt < 8; nt++)
                    mma_f16(acc[mt][nt], af[mt], bf[nt]);
        }
        __syncthreads();

        if (it + 2 < NIT) load_tile(buf, (it + 2) * FBK);
    }

    // Epilogue
    #pragma unroll
    for (int mt = 0; mt < 4; mt++) {
        #pragma unroll
        for (int nt = 0; nt < 8; nt++) {
            const int col = n0 + wn + nt * 8 + 2 * tg;
            float2 bb = make_float2(0.f, 0.f);
            if (BIAS) {
                bb.x = bias_s[wn + nt * 8 + 2 * tg];
                bb.y = bias_s[wn + nt * 8 + 2 * tg + 1];
            }
            #pragma unroll
            for (int half_i = 0; half_i < 2; half_i++) {
                const int row = m0 + wm + mt * 16 + g + half_i * 8;
                float2 v = make_float2(acc[mt][nt][half_i * 2 + 0],
                                       acc[mt][nt][half_i * 2 + 1]);
                if (BIAS) { v.x += bb.x; v.y += bb.y; }
                if (RES) {
                    float2 rr = *reinterpret_cast<const float2*>(
                        &res[(size_t)row * N + col]);
                    v.x += rr.x; v.y += rr.y;
                }
                if (RELU) { v.x = fmaxf(v.x, 0.f); v.y = fmaxf(v.y, 0.f); }
                if (sizeof(OutT) == 2) {
                    *reinterpret_cast<__half2*>(
                        reinterpret_cast<__half*>(C) + (size_t)row * N + col) =
                        __floats2half2_rn(v.x, v.y);
                } else {
                    *reinterpret_cast<float2*>(
                        reinterpret_cast<float*>(C) + (size_t)row * N + col) = v;
                }
            }
        }
    }
}

// ---------------------------------------------------------------------------
// fp16 tensor-core causal flash attention.
// Block = 128 threads (4 warps), 64-query tile. All operands fp16 in smem
// (stride 72 halves = 144B -> all fragment LDS + ldmatrix conflict-free).
// S via mma.m16n8k16 (fp32 accum); P->fp16 smem; P@V via ldmatrix.x4.trans.
// ---------------------------------------------------------------------------
#define ALH 72
#define AQ_H (64 * ALH)            // 4608 halves
#define AK_H (64 * ALH)
#define AV_H (64 * ALH)
#define AP_H (16 * ALH)            // per warp
#define ATTN_SMEM_BYTES ((AQ_H + 2*AK_H + 2*AV_H + 4*AP_H) * 2)

__global__ void __launch_bounds__(128) attn_f16(
    const __half* __restrict__ qkv, __half* __restrict__ o)
{
    extern __shared__ __half hsm[];
    __half* Qs = hsm;
    __half* Ks = Qs + AQ_H;
    __half* Vs = Ks + 2 * AK_H;
    __half* Ps = Vs + 2 * AV_H;

    const int qt  = (int)gridDim.x - 1 - (int)blockIdx.x;   // heavy first
    const int bh  = blockIdx.y;
    const int b   = bh >> 3;
    const int h   = bh & 7;
    const int tid = threadIdx.x;
    const int w   = tid >> 5;
    const int lane = tid & 31;
    const int g    = lane >> 2;
    const int tg   = lane & 3;
    const int q0  = qt * 64;

    const float scale = 0.04419417382415922f;   // 1/sqrt(512)

    const __half* qbase = qkv + ((size_t)(b * SEQ + q0)) * QKVN + h * DHEAD;
    const __half* kbase = qkv + ((size_t)b * SEQ) * QKVN + 512  + h * DHEAD;
    const __half* vbase = qkv + ((size_t)b * SEQ) * QKVN + 1024 + h * DHEAD;

    // ---- load Q tile (64x64 halves) via cp.async ----
    {
        const uint32_t qs = smem_u32(Qs);
        #pragma unroll
        for (int i = 0; i < 4; i++) {
            int c = tid + i * 128;           // 512 chunks of 8 halves
            int row = c >> 3, ch = c & 7;
            cp16(qs + row * (ALH * 2) + ch * 16,
                 qbase + (size_t)row * QKVN + ch * 8);
        }
        cp_commit();
    }

    // ---- K/V tile loader ----
    auto issue_kv = [&](int buf, int j0) {
        const uint32_t ks = smem_u32(Ks + buf * AK_H);
        const uint32_t vs = smem_u32(Vs + buf * AV_H);
        #pragma unroll
        for (int i = 0; i < 4; i++) {
            int c = tid + i * 128;
            int row = c >> 3, ch = c & 7;
            cp16(ks + row * (ALH * 2) + ch * 16,
                 kbase + (size_t)(j0 + row) * QKVN + ch * 8);
            cp16(vs + row * (ALH * 2) + ch * 16,
                 vbase + (size_t)(j0 + row) * QKVN + ch * 8);
        }
        cp_commit();
    };

    issue_kv(0, 0);

    // finish Q load (group of 2 outstanding: Q, KV0 -> wait for Q group only
    // after issuing KV0 means wait_group<1>; simpler: wait all then sync)
    cp_wait<0>();
    __syncthreads();

    // ---- hoist Q A-fragments: 4 k-steps x 4 regs ----
    uint32_t qf[4][4];
    {
        const int mr = w * 16 + g;
        #pragma unroll
        for (int kb = 0; kb < 4; kb++) {
            qf[kb][0] = *reinterpret_cast<const uint32_t*>(&Qs[(mr    ) * ALH + kb * 16 + 2 * tg]);
            qf[kb][1] = *reinterpret_cast<const uint32_t*>(&Qs[(mr + 8) * ALH + kb * 16 + 2 * tg]);
            qf[kb][2] = *reinterpret_cast<const uint32_t*>(&Qs[(mr    ) * ALH + kb * 16 + 2 * tg + 8]);
            qf[kb][3] = *reinterpret_cast<const uint32_t*>(&Qs[(mr + 8) * ALH + kb * 16 + 2 * tg + 8]);
        }
    }

    float oacc[8][4];
    #pragma unroll
    for (int nt = 0; nt < 8; nt++)
        #pragma unroll
        for (int i = 0; i < 4; i++) oacc[nt][i] = 0.0f;
    float m_lo = -INFINITY, m_hi = -INFINITY;
    float l_lo = 0.0f, l_hi = 0.0f;

    __half* Pw = Ps + w * AP_H;
    const int ntiles = qt + 1;

    for (int it = 0; it < ntiles; it++) {
        if (it + 1 < ntiles) {
            issue_kv((it + 1) & 1, (it + 1) * 64);
            cp_wait<1>();
        } else {
            cp_wait<0>();
        }
        __syncthreads();

        const __half* Kb = Ks + (it & 1) * AK_H;
        const __half* Vb = Vs + (it & 1) * AV_H;

        // ---- S = Q @ K^T ----
        float sacc[8][4];
        #pragma unroll
        for (int nt = 0; nt < 8; nt++)
            #pragma unroll
            for (int i = 0; i < 4; i++) sacc[nt][i] = 0.0f;

        #pragma unroll
        for (int kb = 0; kb < 4; kb++) {
            uint32_t bf[8][2];
            #pragma unroll
            for (int nt = 0; nt < 8; nt++) {
                const int nc = nt * 8 + g;
                bf[nt][0] = *reinterpret_cast<const uint32_t*>(&Kb[nc * ALH + kb * 16 + 2 * tg]);
                bf[nt][1] = *reinterpret_cast<const uint32_t*>(&Kb[nc * ALH + kb * 16 + 2 * tg + 8]);
            }
            #pragma unroll
            for (int nt = 0; nt < 8; nt++)
                mma_f16(sacc[nt], qf[kb], bf[nt]);
        }

        // ---- scale + causal mask (diagonal tile only) ----
        const int j0 = it * 64;
        const bool diag = (it == ntiles - 1) && (j0 == q0);
        const int qr_lo = q0 + w * 16 + g;
        const int qr_hi = qr_lo + 8;
        #pragma unroll
        for (int nt = 0; nt < 8; nt++) {
            const int c0 = j0 + nt * 8 + 2 * tg;
            sacc[nt][0] = (diag && c0     > qr_lo) ? -INFINITY : sacc[nt][0] * scale;
            sacc[nt][1] = (diag && c0 + 1 > qr_lo) ? -INFINITY : sacc[nt][1] * scale;
            sacc[nt][2] = (diag && c0     > qr_hi) ? -INFINITY : sacc[nt][2] * scale;
            sacc[nt][3] = (diag && c0 + 1 > qr_hi) ? -INFINITY : sacc[nt][3] * scale;
        }

        // ---- online softmax ----
        float mx_lo = -INFINITY, mx_hi = -INFINITY;
        #pragma unroll
        for (int nt = 0; nt < 8; nt++) {
            mx_lo = fmaxf(mx_lo, fmaxf(sacc[nt][0], sacc[nt][1]));
            mx_hi = fmaxf(mx_hi, fmaxf(sacc[nt][2], sacc[nt][3]));
        }
        mx_lo = fmaxf(mx_lo, __shfl_xor_sync(0xffffffffu, mx_lo, 1));
        mx_lo = fmaxf(mx_lo, __shfl_xor_sync(0xffffffffu, mx_lo, 2));
        mx_hi = fmaxf(mx_hi, __shfl_xor_sync(0xffffffffu, mx_hi, 1));
        mx_hi = fmaxf(mx_hi, __shfl_xor_sync(0xffffffffu, mx_hi, 2));

        const float mn_lo = fmaxf(m_lo, mx_lo);
        const float mn_hi = fmaxf(m_hi, mx_hi);
        const float c_lo = __expf(m_lo - mn_lo);
        const float c_hi = __expf(m_hi - mn_hi);
        m_lo = mn_lo; m_hi = mn_hi;

        float ts_lo = 0.0f, ts_hi = 0.0f;
        #pragma unroll
        for (int nt = 0; nt < 8; nt++) {
            float p0 = __expf(sacc[nt][0] - m_lo);
            float p1 = __expf(sacc[nt][1] - m_lo);
            float p2 = __expf(sacc[nt][2] - m_hi);
            float p3 = __expf(sacc[nt][3] - m_hi);
            ts_lo += p0 + p1;
            ts_hi += p2 + p3;
            *reinterpret_cast<__half2*>(&Pw[(g    ) * ALH + nt * 8 + 2 * tg]) =
                __floats2half2_rn(p0, p1);
            *reinterpret_cast<__half2*>(&Pw[(g + 8) * ALH + nt * 8 + 2 * tg]) =
                __floats2half2_rn(p2, p3);
        }
        ts_lo += __shfl_xor_sync(0xffffffffu, ts_lo, 1);
        ts_lo += __shfl_xor_sync(0xffffffffu, ts_lo, 2);
        ts_hi += __shfl_xor_sync(0xffffffffu, ts_hi, 1);
        ts_hi += __shfl_xor_sync(0xffffffffu, ts_hi, 2);
        l_lo = l_lo * c_lo + ts_lo;
        l_hi = l_hi * c_hi + ts_hi;

        #pragma unroll
        for (int nt = 0; nt < 8; nt++) {
            oacc[nt][0] *= c_lo; oacc[nt][1] *= c_lo;
            oacc[nt][2] *= c_hi; oacc[nt][3] *= c_hi;
        }
        __syncwarp();

        // ---- O += P @ V  (V B-fragments via ldmatrix.trans) ----
        #pragma unroll
        for (int kt = 0; kt < 4; kt++) {
            uint32_t af[4];
            af[0] = *reinterpret_cast<const uint32_t*>(&Pw[(g    ) * ALH + kt * 16 + 2 * tg]);
            af[1] = *reinterpret_cast<const uint32_t*>(&Pw[(g + 8) * ALH + kt * 16 + 2 * tg]);
            af[2] = *reinterpret_cast<const uint32_t*>(&Pw[(g    ) * ALH + kt * 16 + 2 * tg + 8]);
            af[3] = *reinterpret_cast<const uint32_t*>(&Pw[(g + 8) * ALH + kt * 16 + 2 * tg + 8]);
            #pragma unroll
            for (int nt = 0; nt < 8; nt += 2) {
                // lanes 0-15 -> n-block nt, lanes 16-31 -> n-block nt+1
                const int vrow = kt * 16 + (lane & 15);
                const int vcol = (nt + (lane >> 4)) * 8;
                uint32_t addr = smem_u32(&Vb[vrow * ALH + vcol]);
                uint32_t b0, b1, b2, b3;
                ldmatrix_x4_trans(b0, b1, b2, b3, addr);
                uint32_t bf0[2] = {b0, b1};
                uint32_t bf1[2] = {b2, b3};
                mma_f16(oacc[nt],     af, bf0);
                mma_f16(oacc[nt + 1], af, bf1);
            }
        }
        __syncthreads();
    }

    // ---- finalize + write fp16 ----
    const float inv_lo = 1.0f / l_lo;
    const float inv_hi = 1.0f / l_hi;
    const int qr = q0 + w * 16 + g;
    __half* orow_lo = o + ((size_t)(b * SEQ + qr    )) * CDIM + h * DHEAD;
    __half* orow_hi = o + ((size_t)(b * SEQ + qr + 8)) * CDIM + h * DHEAD;
    #pragma unroll
    for (int nt = 0; nt < 8; nt++) {
        const int col = nt * 8 + 2 * tg;
        *reinterpret_cast<__half2*>(&orow_lo[col]) =
            __floats2half2_rn(oacc[nt][0] * inv_lo, oacc[nt][1] * inv_lo);
        *reinterpret_cast<__half2*>(&orow_hi[col]) =
            __floats2half2_rn(oacc[nt][2] * inv_hi, oacc[nt][3] * inv_hi);
    }
}

// ---------------------------------------------------------------------------
// Launch. Inputs: 0:x 1:wq 2:wk 3:wv 4:w_proj 5:b_proj 6:w1 7:b1 8:w2 9:b2
//                 10:ln1_g 11:ln1_b 12:ln2_g 13:ln2_b
// ---------------------------------------------------------------------------
extern "C" void kernel_launch(void* const* d_in, const int* in_sizes, int n_in,
                              void* d_out, int out_size)
{
    const float* x      = (const float*)d_in[0];
    const float* wq     = (const float*)d_in[1];
    const float* wk     = (const float*)d_in[2];
    const float* wv     = (const float*)d_in[3];
    const float* w_proj = (const float*)d_in[4];
    const float* b_proj = (const float*)d_in[5];
    const float* w1     = (const float*)d_in[6];
    const float* b1     = (const float*)d_in[7];
    const float* w2     = (const float*)d_in[8];
    const float* b2     = (const float*)d_in[9];
    const float* ln1_g  = (const float*)d_in[10];
    const float* ln1_b  = (const float*)d_in[11];
    const float* ln2_g  = (const float*)d_in[12];
    const float* ln2_b  = (const float*)d_in[13];
    float* out = (float*)d_out;

    __half *h, *qkv, *ob, *h2, *ffn, *w_qkvT, *w_pT, *w_1T, *w_2T;
    cudaGetSymbolAddress((void**)&h,      g_h);
    cudaGetSymbolAddress((void**)&qkv,    g_qkv);
    cudaGetSymbolAddress((void**)&ob,     g_o);
    cudaGetSymbolAddress((void**)&h2,     g_h2);
    cudaGetSymbolAddress((void**)&ffn,    g_ffn);
    cudaGetSymbolAddress((void**)&w_qkvT, g_wqkv);
    cudaGetSymbolAddress((void**)&w_pT,   g_wp);
    cudaGetSymbolAddress((void**)&w_1T,   g_w1);
    cudaGetSymbolAddress((void**)&w_2T,   g_w2);

    static bool attrs_set = false;
    if (!attrs_set) {
        cudaFuncSetAttribute(attn_f16,
            cudaFuncAttributeMaxDynamicSharedMemorySize, ATTN_SMEM_BYTES);
        cudaFuncSetAttribute(gemm_f16<__half, false, false, false>,
            cudaFuncAttributeMaxDynamicSharedMemorySize, GSMEM_BYTES);
        cudaFuncSetAttribute(gemm_f16<float, true, false, true>,
            cudaFuncAttributeMaxDynamicSharedMemorySize, GSMEM_BYTES);
        cudaFuncSetAttribute(gemm_f16<__half, true, true, false>,
            cudaFuncAttributeMaxDynamicSharedMemorySize, GSMEM_BYTES);
        attrs_set = true;
    }

    const int M = MROWS;
    dim3 tb(32, 8);

    // Weight prep: fp16 round + transpose to [N][K]
    prep_qkvT<<<dim3(CDIM / 32, QKVN / 32), tb>>>(wq, wk, wv, w_qkvT);
    prep_wT<<<dim3(CDIM / 32, CDIM / 32), tb>>>(w_proj, w_pT, CDIM, CDIM);
    prep_wT<<<dim3(CDIM / 32, FFNDIM / 32), tb>>>(w1, w_1T, CDIM, FFNDIM);
    prep_wT<<<dim3(FFNDIM / 32, CDIM / 32), tb>>>(w2, w_2T, FFNDIM, CDIM);

    // ln1 (fp16 out)
    ln_kernel<<<M, 128>>>(x, ln1_g, ln1_b, h);

    // fused qkv projection (fp16 out)
    gemm_f16<__half, false, false, false>
        <<<dim3(QKVN / FBM, M / FBM), 128, GSMEM_BYTES>>>(
        h, w_qkvT, nullptr, nullptr, qkv, M, QKVN, CDIM);

    // fp16 causal attention
    attn_f16<<<dim3(SEQ / 64, BATCH * NHEAD), 128, ATTN_SMEM_BYTES>>>(qkv, ob);

    // x2 = x + o @ w_proj + b_proj -> out (fp32)
    gemm_f16<float, true, false, true>
        <<<dim3(CDIM / FBM, M / FBM), 128, GSMEM_BYTES>>>(
        ob, w_pT, b_proj, x, out, M, CDIM, CDIM);

    // ln2 (fp16 out)
    ln_kernel<<<M, 128>>>(out, ln2_g, ln2_b, h2);

    // ffn1 = relu(h2 @ w1 + b1) (fp16 out)
    gemm_f16<__half, true, true, false>
        <<<dim3(FFNDIM / FBM, M / FBM), 128, GSMEM_BYTES>>>(
        h2, w_1T, b1, nullptr, ffn, M, FFNDIM, CDIM);

    // out = out + ffn1 @ w2 + b2 (fp32)
    gemm_f16<float, true, false, true>
        <<<dim3(CDIM / FBM, M / FBM), 128, GSMEM_BYTES>>>(
        ffn, w_2T, b2, out, out, M, CDIM, FFNDIM);
}

// round 9
// speedup vs baseline: 6.7621x; 1.0381x over previous
#include <cuda_runtime.h>
#include <cuda_fp16.h>
#include <math.h>
#include <stdint.h>

// Problem constants
#define BATCH 32
#define SEQ   512
#define CDIM  512
#define NHEAD 8
#define DHEAD 64
#define MROWS (BATCH * SEQ)        // 16384
#define FFNDIM (4 * CDIM)          // 2048
#define QKVN  (3 * CDIM)           // 1536

// Scratch (allocation-free rule: __device__ globals)
__device__ __half g_h   [MROWS * CDIM];
__device__ __half g_qkv [MROWS * QKVN];
__device__ __half g_o   [MROWS * CDIM];
__device__ __half g_h2  [MROWS * CDIM];
__device__ __half g_ffn [MROWS * FFNDIM];
// fp16 weights, TRANSPOSED to [N][K] (K contiguous)
__device__ __half g_wqkv[QKVN * CDIM];
__device__ __half g_wp  [CDIM * CDIM];
__device__ __half g_w1  [FFNDIM * CDIM];
__device__ __half g_w2  [CDIM * FFNDIM];

// ---------------------------------------------------------------------------
// PTX helpers
// ---------------------------------------------------------------------------
__device__ __forceinline__ void mma_f16(float* c, const uint32_t* a, const uint32_t* b) {
    asm volatile(
        "mma.sync.aligned.m16n8k16.row.col.f32.f16.f16.f32 "
        "{%0,%1,%2,%3},{%4,%5,%6,%7},{%8,%9},{%0,%1,%2,%3};"
        : "+f"(c[0]), "+f"(c[1]), "+f"(c[2]), "+f"(c[3])
        : "r"(a[0]), "r"(a[1]), "r"(a[2]), "r"(a[3]), "r"(b[0]), "r"(b[1]));
}
__device__ __forceinline__ uint32_t smem_u32(const void* p) {
    return (uint32_t)__cvta_generic_to_shared(p);
}
__device__ __forceinline__ void cp16(uint32_t dst, const void* src) {
    asm volatile("cp.async.cg.shared.global [%0], [%1], 16;" :: "r"(dst), "l"(src));
}
__device__ __forceinline__ void cp_commit() { asm volatile("cp.async.commit_group;"); }
template<int N> __device__ __forceinline__ void cp_wait() {
    asm volatile("cp.async.wait_group %0;" :: "n"(N));
}
__device__ __forceinline__ void ldmx4(
    uint32_t& r0, uint32_t& r1, uint32_t& r2, uint32_t& r3, uint32_t addr)
{
    asm volatile("ldmatrix.sync.aligned.m8n8.x4.shared.b16 {%0,%1,%2,%3}, [%4];"
        : "=r"(r0), "=r"(r1), "=r"(r2), "=r"(r3) : "r"(addr));
}
__device__ __forceinline__ void ldmx4_trans(
    uint32_t& r0, uint32_t& r1, uint32_t& r2, uint32_t& r3, uint32_t addr)
{
    asm volatile("ldmatrix.sync.aligned.m8n8.x4.trans.shared.b16 {%0,%1,%2,%3}, [%4];"
        : "=r"(r0), "=r"(r1), "=r"(r2), "=r"(r3) : "r"(addr));
}

// ---------------------------------------------------------------------------
// Weight prep: tiled transpose W[K][N] -> Wt[N][K] (fp16)
// ---------------------------------------------------------------------------
__global__ void __launch_bounds__(256) prep_wT(
    const float* __restrict__ W, __half* __restrict__ Wt, int K, int N)
{
    __shared__ float sm[32][33];
    const int tx = threadIdx.x, ty = threadIdx.y;
    const int k0 = blockIdx.x * 32, n0 = blockIdx.y * 32;
    #pragma unroll
    for (int i = 0; i < 4; i++)
        sm[ty + 8 * i][tx] = W[(size_t)(k0 + ty + 8 * i) * N + n0 + tx];
    __syncthreads();
    #pragma unroll
    for (int i = 0; i < 4; i++)
        Wt[(size_t)(n0 + ty + 8 * i) * K + k0 + tx] =
            __float2half_rn(sm[tx][ty + 8 * i]);
}

__global__ void __launch_bounds__(256) prep_qkvT(
    const float* __restrict__ wq, const float* __restrict__ wk,
    const float* __restrict__ wv, __half* __restrict__ Wt)
{
    __shared__ float sm[32][33];
    const int tx = threadIdx.x, ty = threadIdx.y;
    const int k0 = blockIdx.x * 32, n0 = blockIdx.y * 32;
    const int part = n0 >> 9, hh = (n0 >> 6) & 7, d0 = n0 & 32;
    const float* w = (part == 0) ? wq : (part == 1 ? wk : wv);
    #pragma unroll
    for (int i = 0; i < 4; i++)
        sm[ty + 8 * i][tx] =
            w[((size_t)(hh * CDIM + k0 + ty + 8 * i)) * 64 + d0 + tx];
    __syncthreads();
    #pragma unroll
    for (int i = 0; i < 4; i++)
        Wt[(size_t)(n0 + ty + 8 * i) * CDIM + k0 + tx] =
            __float2half_rn(sm[tx][ty + 8 * i]);
}

// ---------------------------------------------------------------------------
// LayerNorm: one block per row (C=512), 128 threads, fp16 output
// ---------------------------------------------------------------------------
__global__ void __launch_bounds__(128) ln_kernel(
    const float* __restrict__ x, const float* __restrict__ g,
    const float* __restrict__ b, __half* __restrict__ out)
{
    const int row = blockIdx.x;
    const int tid = threadIdx.x;
    const float* xr = x + (size_t)row * CDIM;

    float4 v = *reinterpret_cast<const float4*>(&xr[tid * 4]);
    float s  = v.x + v.y + v.z + v.w;
    float ss = v.x*v.x + v.y*v.y + v.z*v.z + v.w*v.w;
    #pragma unroll
    for (int off = 16; off > 0; off >>= 1) {
        s  += __shfl_xor_sync(0xffffffffu, s,  off);
        ss += __shfl_xor_sync(0xffffffffu, ss, off);
    }
    __shared__ float sm[4], sm2[4];
    const int wid = tid >> 5, lane = tid & 31;
    if (lane == 0) { sm[wid] = s; sm2[wid] = ss; }
    __syncthreads();
    s  = sm[0] + sm[1] + sm[2] + sm[3];
    ss = sm2[0] + sm2[1] + sm2[2] + sm2[3];

    const float mu   = s * (1.0f / CDIM);
    const float var  = ss * (1.0f / CDIM) - mu * mu;
    const float rstd = rsqrtf(var + 1e-5f);

    float4 gg = *reinterpret_cast<const float4*>(&g[tid * 4]);
    float4 bb = *reinterpret_cast<const float4*>(&b[tid * 4]);
    __half2 h0 = __floats2half2_rn((v.x - mu) * rstd * gg.x + bb.x,
                                   (v.y - mu) * rstd * gg.y + bb.y);
    __half2 h1 = __floats2half2_rn((v.z - mu) * rstd * gg.z + bb.z,
                                   (v.w - mu) * rstd * gg.w + bb.w);
    __half2* op = reinterpret_cast<__half2*>(out + (size_t)row * CDIM + tid * 4);
    op[0] = h0; op[1] = h1;
}

// ---------------------------------------------------------------------------
// fp16 tensor-core GEMM: C[M,N] = A[M,K] @ Wt[N,K]^T (+bias)(+res)(relu)
// BM=BN=128, BK=64, 128 threads = 4 warps (2x2), warp tile 64x64.
// 3-stage cp.async pipeline; ldmatrix.x4 fragment loads.
// ---------------------------------------------------------------------------
#define FBM 128
#define FBK 64
#define LDHG 72                             // halves per smem row (144B)
#define TILE_H (FBM * LDHG)                 // 9216 halves = 18432 B per tile
#define NSTAGE 3
#define GSMEM_BYTES (NSTAGE * 2 * TILE_H * 2 + 1024 + 256)

template<typename OutT, bool BIAS, bool RELU, bool RES>
__global__ void __launch_bounds__(128, 2) gemm_f16(
    const __half* __restrict__ A, const __half* __restrict__ Bw,
    const float* __restrict__ bias, const float* __restrict__ res,
    OutT* __restrict__ C, int M, int N, int K)
{
    extern __shared__ char dsm[];
    __half* As = reinterpret_cast<__half*>(dsm);            // NSTAGE * TILE_H
    __half* Bs = As + NSTAGE * TILE_H;                      // NSTAGE * TILE_H
    float* bias_s = reinterpret_cast<float*>(Bs + NSTAGE * TILE_H);

    const int tid  = threadIdx.x;
    const int w    = tid >> 5;
    const int lane = tid & 31;
    const int g    = lane >> 2;
    const int tg   = lane & 3;

    const int m0 = blockIdx.y * FBM;
    const int n0 = blockIdx.x * FBM;
    const int wm = (w & 1) * 64;
    const int wn = (w >> 1) * 64;

    if (BIAS) bias_s[tid] = bias[n0 + tid];

    float acc[4][8][4];
    #pragma unroll
    for (int mt = 0; mt < 4; mt++)
        #pragma unroll
        for (int nt = 0; nt < 8; nt++)
            #pragma unroll
            for (int i = 0; i < 4; i++) acc[mt][nt][i] = 0.0f;

    const uint32_t as_base = smem_u32(As);
    const uint32_t bs_base = smem_u32(Bs);

    auto load_tile = [&](int buf, int k0) {
        const uint32_t a_s = as_base + buf * TILE_H * 2;
        const uint32_t b_s = bs_base + buf * TILE_H * 2;
        #pragma unroll
        for (int j = 0; j < 8; j++) {
            int c = tid + 128 * j;
            int row = c >> 3, ch = c & 7;
            cp16(a_s + row * (LDHG * 2) + ch * 16,
                 A + (size_t)(m0 + row) * K + k0 + ch * 8);
            cp16(b_s + row * (LDHG * 2) + ch * 16,
                 Bw + (size_t)(n0 + row) * K + k0 + ch * 8);
        }
        cp_commit();
    };

    const int NIT = K / FBK;              // >= 8 for all our shapes
    load_tile(0, 0);
    load_tile(1, FBK);
    load_tile(2, 2 * FBK);

    // ldmatrix lane addressing (constant across iterations)
    const int a_row = lane & 15;                    // m row within 16
    const int a_kof = (lane & 16) ? 8 : 0;          // k half
    const int b_row = (lane & 7) + ((lane & 16) ? 8 : 0);  // n row within 16
    const int b_kof = (lane & 8) ? 8 : 0;           // k half

    for (int it = 0; it < NIT; it++) {
        const int buf = it % NSTAGE;
        if (it + 2 < NIT)      cp_wait<2>();
        else if (it + 1 < NIT) cp_wait<1>();
        else                   cp_wait<0>();
        __syncthreads();

        const __half* Ab = As + buf * TILE_H;
        const __half* Bb = Bs + buf * TILE_H;

        #pragma unroll
        for (int ks = 0; ks < 4; ks++) {
            const int kb = ks * 16;
            uint32_t af[4][4], bf[8][2];
            #pragma unroll
            for (int mt = 0; mt < 4; mt++) {
                uint32_t addr = smem_u32(
                    &Ab[(wm + mt * 16 + a_row) * LDHG + kb + a_kof]);
                ldmx4(af[mt][0], af[mt][1], af[mt][2], af[mt][3], addr);
            }
            #pragma unroll
            for (int p = 0; p < 4; p++) {
                uint32_t addr = smem_u32(
                    &Bb[(wn + p * 16 + b_row) * LDHG + kb + b_kof]);
                ldmx4(bf[2*p][0], bf[2*p][1], bf[2*p+1][0], bf[2*p+1][1], addr);
            }
            #pragma unroll
            for (int mt = 0; mt < 4; mt++)
                #pragma unroll
                for (int nt = 0; nt < 8; nt++)
                    mma_f16(acc[mt][nt], af[mt], bf[nt]);
        }
        __syncthreads();

        if (it + 3 < NIT) load_tile(buf, (it + 3) * FBK);
    }

    // Epilogue
    #pragma unroll
    for (int mt = 0; mt < 4; mt++) {
        #pragma unroll
        for (int nt = 0; nt < 8; nt++) {
            const int col = n0 + wn + nt * 8 + 2 * tg;
            float2 bb = make_float2(0.f, 0.f);
            if (BIAS) {
                bb.x = bias_s[wn + nt * 8 + 2 * tg];
                bb.y = bias_s[wn + nt * 8 + 2 * tg + 1];
            }
            #pragma unroll
            for (int half_i = 0; half_i < 2; half_i++) {
                const int row = m0 + wm + mt * 16 + g + half_i * 8;
                float2 v = make_float2(acc[mt][nt][half_i * 2 + 0],
                                       acc[mt][nt][half_i * 2 + 1]);
                if (BIAS) { v.x += bb.x; v.y += bb.y; }
                if (RES) {
                    float2 rr = *reinterpret_cast<const float2*>(
                        &res[(size_t)row * N + col]);
                    v.x += rr.x; v.y += rr.y;
                }
                if (RELU) { v.x = fmaxf(v.x, 0.f); v.y = fmaxf(v.y, 0.f); }
                if (sizeof(OutT) == 2) {
                    *reinterpret_cast<__half2*>(
                        reinterpret_cast<__half*>(C) + (size_t)row * N + col) =
                        __floats2half2_rn(v.x, v.y);
                } else {
                    *reinterpret_cast<float2*>(
                        reinterpret_cast<float*>(C) + (size_t)row * N + col) = v;
                }
            }
        }
    }
}

// ---------------------------------------------------------------------------
// fp16 tensor-core causal flash attention; ldmatrix fragment loads.
// ---------------------------------------------------------------------------
#define ALH 72
#define AQ_H (64 * ALH)
#define AK_H (64 * ALH)
#define AV_H (64 * ALH)
#define AP_H (16 * ALH)
#define ATTN_SMEM_BYTES ((AQ_H + 2*AK_H + 2*AV_H + 4*AP_H) * 2)

__global__ void __launch_bounds__(128) attn_f16(
    const __half* __restrict__ qkv, __half* __restrict__ o)
{
    extern __shared__ __half hsm[];
    __half* Qs = hsm;
    __half* Ks = Qs + AQ_H;
    __half* Vs = Ks + 2 * AK_H;
    __half* Ps = Vs + 2 * AV_H;

    const int qt  = (int)gridDim.x - 1 - (int)blockIdx.x;
    const int bh  = blockIdx.y;
    const int b   = bh >> 3;
    const int h   = bh & 7;
    const int tid = threadIdx.x;
    const int w   = tid >> 5;
    const int lane = tid & 31;
    const int g    = lane >> 2;
    const int tg   = lane & 3;
    const int q0  = qt * 64;

    const float scale = 0.04419417382415922f;   // 1/sqrt(512)

    const __half* qbase = qkv + ((size_t)(b * SEQ + q0)) * QKVN + h * DHEAD;
    const __half* kbase = qkv + ((size_t)b * SEQ) * QKVN + 512  + h * DHEAD;
    const __half* vbase = qkv + ((size_t)b * SEQ) * QKVN + 1024 + h * DHEAD;

    {
        const uint32_t qs = smem_u32(Qs);
        #pragma unroll
        for (int i = 0; i < 4; i++) {
            int c = tid + i * 128;
            int row = c >> 3, ch = c & 7;
            cp16(qs + row * (ALH * 2) + ch * 16,
                 qbase + (size_t)row * QKVN + ch * 8);
        }
        cp_commit();
    }

    auto issue_kv = [&](int buf, int j0) {
        const uint32_t ks = smem_u32(Ks + buf * AK_H);
        const uint32_t vs = smem_u32(Vs + buf * AV_H);
        #pragma unroll
        for (int i = 0; i < 4; i++) {
            int c = tid + i * 128;
            int row = c >> 3, ch = c & 7;
            cp16(ks + row * (ALH * 2) + ch * 16,
                 kbase + (size_t)(j0 + row) * QKVN + ch * 8);
            cp16(vs + row * (ALH * 2) + ch * 16,
                 vbase + (size_t)(j0 + row) * QKVN + ch * 8);
        }
        cp_commit();
    };

    issue_kv(0, 0);
    cp_wait<0>();
    __syncthreads();

    // ldmatrix lane addressing
    const int a_row = lane & 15;
    const int a_kof = (lane & 16) ? 8 : 0;
    const int b_row = (lane & 7) + ((lane & 16) ? 8 : 0);
    const int b_kof = (lane & 8) ? 8 : 0;

    // hoist Q A-fragments via ldmatrix (4 k-steps)
    uint32_t qf[4][4];
    #pragma unroll
    for (int kb = 0; kb < 4; kb++) {
        uint32_t addr = smem_u32(&Qs[(w * 16 + a_row) * ALH + kb * 16 + a_kof]);
        ldmx4(qf[kb][0], qf[kb][1], qf[kb][2], qf[kb][3], addr);
    }

    float oacc[8][4];
    #pragma unroll
    for (int nt = 0; nt < 8; nt++)
        #pragma unroll
        for (int i = 0; i < 4; i++) oacc[nt][i] = 0.0f;
    float m_lo = -INFINITY, m_hi = -INFINITY;
    float l_lo = 0.0f, l_hi = 0.0f;

    __half* Pw = Ps + w * AP_H;
    const int ntiles = qt + 1;

    for (int it = 0; it < ntiles; it++) {
        if (it + 1 < ntiles) {
            issue_kv((it + 1) & 1, (it + 1) * 64);
            cp_wait<1>();
        } else {
            cp_wait<0>();
        }
        __syncthreads();

        const __half* Kb = Ks + (it & 1) * AK_H;
        const __half* Vb = Vs + (it & 1) * AV_H;

        // ---- S = Q @ K^T ----
        float sacc[8][4];
        #pragma unroll
        for (int nt = 0; nt < 8; nt++)
            #pragma unroll
            for (int i = 0; i < 4; i++) sacc[nt][i] = 0.0f;

        #pragma unroll
        for (int kb = 0; kb < 4; kb++) {
            uint32_t bf[8][2];
            #pragma unroll
            for (int p = 0; p < 4; p++) {
                uint32_t addr = smem_u32(
                    &Kb[(p * 16 + b_row) * ALH + kb * 16 + b_kof]);
                ldmx4(bf[2*p][0], bf[2*p][1], bf[2*p+1][0], bf[2*p+1][1], addr);
            }
            #pragma unroll
            for (int nt = 0; nt < 8; nt++)
                mma_f16(sacc[nt], qf[kb], bf[nt]);
        }

        // ---- scale + causal mask (diagonal tile only) ----
        const int j0 = it * 64;
        const bool diag = (it == ntiles - 1) && (j0 == q0);
        const int qr_lo = q0 + w * 16 + g;
        const int qr_hi = qr_lo + 8;
        #pragma unroll
        for (int nt = 0; nt < 8; nt++) {
            const int c0 = j0 + nt * 8 + 2 * tg;
            sacc[nt][0] = (diag && c0     > qr_lo) ? -INFINITY : sacc[nt][0] * scale;
            sacc[nt][1] = (diag && c0 + 1 > qr_lo) ? -INFINITY : sacc[nt][1] * scale;
            sacc[nt][2] = (diag && c0     > qr_hi) ? -INFINITY : sacc[nt][2] * scale;
            sacc[nt][3] = (diag && c0 + 1 > qr_hi) ? -INFINITY : sacc[nt][3] * scale;
        }

        // ---- online softmax ----
        float mx_lo = -INFINITY, mx_hi = -INFINITY;
        #pragma unroll
        for (int nt = 0; nt < 8; nt++) {
            mx_lo = fmaxf(mx_lo, fmaxf(sacc[nt][0], sacc[nt][1]));
            mx_hi = fmaxf(mx_hi, fmaxf(sacc[nt][2], sacc[nt][3]));
        }
        mx_lo = fmaxf(mx_lo, __shfl_xor_sync(0xffffffffu, mx_lo, 1));
        mx_lo = fmaxf(mx_lo, __shfl_xor_sync(0xffffffffu, mx_lo, 2));
        mx_hi = fmaxf(mx_hi, __shfl_xor_sync(0xffffffffu, mx_hi, 1));
        mx_hi = fmaxf(mx_hi, __shfl_xor_sync(0xffffffffu, mx_hi, 2));

        const float mn_lo = fmaxf(m_lo, mx_lo);
        const float mn_hi = fmaxf(m_hi, mx_hi);
        const float c_lo = __expf(m_lo - mn_lo);
        const float c_hi = __expf(m_hi - mn_hi);
        m_lo = mn_lo; m_hi = mn_hi;

        float ts_lo = 0.0f, ts_hi = 0.0f;
        #pragma unroll
        for (int nt = 0; nt < 8; nt++) {
            float p0 = __expf(sacc[nt][0] - m_lo);
            float p1 = __expf(sacc[nt][1] - m_lo);
            float p2 = __expf(sacc[nt][2] - m_hi);
            float p3 = __expf(sacc[nt][3] - m_hi);
            ts_lo += p0 + p1;
            ts_hi += p2 + p3;
            *reinterpret_cast<__half2*>(&Pw[(g    ) * ALH + nt * 8 + 2 * tg]) =
                __floats2half2_rn(p0, p1);
            *reinterpret_cast<__half2*>(&Pw[(g + 8) * ALH + nt * 8 + 2 * tg]) =
                __floats2half2_rn(p2, p3);
        }
        ts_lo += __shfl_xor_sync(0xffffffffu, ts_lo, 1);
        ts_lo += __shfl_xor_sync(0xffffffffu, ts_lo, 2);
        ts_hi += __shfl_xor_sync(0xffffffffu, ts_hi, 1);
        ts_hi += __shfl_xor_sync(0xffffffffu, ts_hi, 2);
        l_lo = l_lo * c_lo + ts_lo;
        l_hi = l_hi * c_hi + ts_hi;

        #pragma unroll
        for (int nt = 0; nt < 8; nt++) {
            oacc[nt][0] *= c_lo; oacc[nt][1] *= c_lo;
            oacc[nt][2] *= c_hi; oacc[nt][3] *= c_hi;
        }
        __syncwarp();

        // ---- O += P @ V  (P A-frags via ldmatrix, V via ldmatrix.trans) ----
        #pragma unroll
        for (int kt = 0; kt < 4; kt++) {
            uint32_t af[4];
            {
                uint32_t addr = smem_u32(&Pw[a_row * ALH + kt * 16 + a_kof]);
                ldmx4(af[0], af[1], af[2], af[3], addr);
            }
            #pragma unroll
            for (int nt = 0; nt < 8; nt += 2) {
                const int vrow = kt * 16 + (lane & 15);
                const int vcol = (nt + (lane >> 4)) * 8;
                uint32_t addr = smem_u32(&Vb[vrow * ALH + vcol]);
                uint32_t b0, b1, b2, b3;
                ldmx4_trans(b0, b1, b2, b3, addr);
                uint32_t bf0[2] = {b0, b1};
                uint32_t bf1[2] = {b2, b3};
                mma_f16(oacc[nt],     af, bf0);
                mma_f16(oacc[nt + 1], af, bf1);
            }
        }
        __syncthreads();
    }

    // ---- finalize + write fp16 ----
    const float inv_lo = 1.0f / l_lo;
    const float inv_hi = 1.0f / l_hi;
    const int qr = q0 + w * 16 + g;
    __half* orow_lo = o + ((size_t)(b * SEQ + qr    )) * CDIM + h * DHEAD;
    __half* orow_hi = o + ((size_t)(b * SEQ + qr + 8)) * CDIM + h * DHEAD;
    #pragma unroll
    for (int nt = 0; nt < 8; nt++) {
        const int col = nt * 8 + 2 * tg;
        *reinterpret_cast<__half2*>(&orow_lo[col]) =
            __floats2half2_rn(oacc[nt][0] * inv_lo, oacc[nt][1] * inv_lo);
        *reinterpret_cast<__half2*>(&orow_hi[col]) =
            __floats2half2_rn(oacc[nt][2] * inv_hi, oacc[nt][3] * inv_hi);
    }
}

// ---------------------------------------------------------------------------
// Launch. Inputs: 0:x 1:wq 2:wk 3:wv 4:w_proj 5:b_proj 6:w1 7:b1 8:w2 9:b2
//                 10:ln1_g 11:ln1_b 12:ln2_g 13:ln2_b
// ---------------------------------------------------------------------------
extern "C" void kernel_launch(void* const* d_in, const int* in_sizes, int n_in,
                              void* d_out, int out_size)
{
    const float* x      = (const float*)d_in[0];
    const float* wq     = (const float*)d_in[1];
    const float* wk     = (const float*)d_in[2];
    const float* wv     = (const float*)d_in[3];
    const float* w_proj = (const float*)d_in[4];
    const float* b_proj = (const float*)d_in[5];
    const float* w1     = (const float*)d_in[6];
    const float* b1     = (const float*)d_in[7];
    const float* w2     = (const float*)d_in[8];
    const float* b2     = (const float*)d_in[9];
    const float* ln1_g  = (const float*)d_in[10];
    const float* ln1_b  = (const float*)d_in[11];
    const float* ln2_g  = (const float*)d_in[12];
    const float* ln2_b  = (const float*)d_in[13];
    float* out = (float*)d_out;

    __half *h, *qkv, *ob, *h2, *ffn, *w_qkvT, *w_pT, *w_1T, *w_2T;
    cudaGetSymbolAddress((void**)&h,      g_h);
    cudaGetSymbolAddress((void**)&qkv,    g_qkv);
    cudaGetSymbolAddress((void**)&ob,     g_o);
    cudaGetSymbolAddress((void**)&h2,     g_h2);
    cudaGetSymbolAddress((void**)&ffn,    g_ffn);
    cudaGetSymbolAddress((void**)&w_qkvT, g_wqkv);
    cudaGetSymbolAddress((void**)&w_pT,   g_wp);
    cudaGetSymbolAddress((void**)&w_1T,   g_w1);
    cudaGetSymbolAddress((void**)&w_2T,   g_w2);

    static bool attrs_set = false;
    if (!attrs_set) {
        cudaFuncSetAttribute(attn_f16,
            cudaFuncAttributeMaxDynamicSharedMemorySize, ATTN_SMEM_BYTES);
        cudaFuncSetAttribute(gemm_f16<__half, false, false, false>,
            cudaFuncAttributeMaxDynamicSharedMemorySize, GSMEM_BYTES);
        cudaFuncSetAttribute(gemm_f16<float, true, false, true>,
            cudaFuncAttributeMaxDynamicSharedMemorySize, GSMEM_BYTES);
        cudaFuncSetAttribute(gemm_f16<__half, true, true, false>,
            cudaFuncAttributeMaxDynamicSharedMemorySize, GSMEM_BYTES);
        attrs_set = true;
    }

    const int M = MROWS;
    dim3 tb(32, 8);

    // Weight prep: fp16 round + transpose to [N][K]
    prep_qkvT<<<dim3(CDIM / 32, QKVN / 32), tb>>>(wq, wk, wv, w_qkvT);
    prep_wT<<<dim3(CDIM / 32, CDIM / 32), tb>>>(w_proj, w_pT, CDIM, CDIM);
    prep_wT<<<dim3(CDIM / 32, FFNDIM / 32), tb>>>(w1, w_1T, CDIM, FFNDIM);
    prep_wT<<<dim3(FFNDIM / 32, CDIM / 32), tb>>>(w2, w_2T, FFNDIM, CDIM);

    // ln1 (fp16 out)
    ln_kernel<<<M, 128>>>(x, ln1_g, ln1_b, h);

    // fused qkv projection (fp16 out)
    gemm_f16<__half, false, false, false>
        <<<dim3(QKVN / FBM, M / FBM), 128, GSMEM_BYTES>>>(
        h, w_qkvT, nullptr, nullptr, qkv, M, QKVN, CDIM);

    // fp16 causal attention
    attn_f16<<<dim3(SEQ / 64, BATCH * NHEAD), 128, ATTN_SMEM_BYTES>>>(qkv, ob);

    // x2 = x + o @ w_proj + b_proj -> out (fp32)
    gemm_f16<float, true, false, true>
        <<<dim3(CDIM / FBM, M / FBM), 128, GSMEM_BYTES>>>(
        ob, w_pT, b_proj, x, out, M, CDIM, CDIM);

    // ln2 (fp16 out)
    ln_kernel<<<M, 128>>>(out, ln2_g, ln2_b, h2);

    // ffn1 = relu(h2 @ w1 + b1) (fp16 out)
    gemm_f16<__half, true, true, false>
        <<<dim3(FFNDIM / FBM, M / FBM), 128, GSMEM_BYTES>>>(
        h2, w_1T, b1, nullptr, ffn, M, FFNDIM, CDIM);

    // out = out + ffn1 @ w2 + b2 (fp32)
    gemm_f16<float, true, false, true>
        <<<dim3(CDIM / FBM, M / FBM), 128, GSMEM_BYTES>>>(
        ffn, w_2T, b2, out, out, M, CDIM, FFNDIM);
}

// round 10
// speedup vs baseline: 6.9099x; 1.0219x over previous
#include <cuda_runtime.h>
#include <cuda_fp16.h>
#include <math.h>
#include <stdint.h>

// Problem constants
#define BATCH 32
#define SEQ   512
#define CDIM  512
#define NHEAD 8
#define DHEAD 64
#define MROWS (BATCH * SEQ)        // 16384
#define FFNDIM (4 * CDIM)          // 2048
#define QKVN  (3 * CDIM)           // 1536

// Scratch (allocation-free rule: __device__ globals)
__device__ __half g_h   [MROWS * CDIM];
__device__ __half g_qkv [MROWS * QKVN];
__device__ __half g_o   [MROWS * CDIM];
__device__ __half g_h2  [MROWS * CDIM];
__device__ __half g_ffn [MROWS * FFNDIM];
// fp16 weights, TRANSPOSED to [N][K] (K contiguous)
__device__ __half g_wqkv[QKVN * CDIM];
__device__ __half g_wp  [CDIM * CDIM];
__device__ __half g_w1  [FFNDIM * CDIM];
__device__ __half g_w2  [CDIM * FFNDIM];

// ---------------------------------------------------------------------------
// PTX helpers
// ---------------------------------------------------------------------------
__device__ __forceinline__ void mma_f16(float* c, const uint32_t* a, const uint32_t* b) {
    asm volatile(
        "mma.sync.aligned.m16n8k16.row.col.f32.f16.f16.f32 "
        "{%0,%1,%2,%3},{%4,%5,%6,%7},{%8,%9},{%0,%1,%2,%3};"
        : "+f"(c[0]), "+f"(c[1]), "+f"(c[2]), "+f"(c[3])
        : "r"(a[0]), "r"(a[1]), "r"(a[2]), "r"(a[3]), "r"(b[0]), "r"(b[1]));
}
__device__ __forceinline__ uint32_t smem_u32(const void* p) {
    return (uint32_t)__cvta_generic_to_shared(p);
}
__device__ __forceinline__ void cp16(uint32_t dst, const void* src) {
    asm volatile("cp.async.cg.shared.global [%0], [%1], 16;" :: "r"(dst), "l"(src));
}
__device__ __forceinline__ void cp_commit() { asm volatile("cp.async.commit_group;"); }
template<int N> __device__ __forceinline__ void cp_wait() {
    asm volatile("cp.async.wait_group %0;" :: "n"(N));
}
__device__ __forceinline__ void ldmx4(
    uint32_t& r0, uint32_t& r1, uint32_t& r2, uint32_t& r3, uint32_t addr)
{
    asm volatile("ldmatrix.sync.aligned.m8n8.x4.shared.b16 {%0,%1,%2,%3}, [%4];"
        : "=r"(r0), "=r"(r1), "=r"(r2), "=r"(r3) : "r"(addr));
}
__device__ __forceinline__ void ldmx4_trans(
    uint32_t& r0, uint32_t& r1, uint32_t& r2, uint32_t& r3, uint32_t addr)
{
    asm volatile("ldmatrix.sync.aligned.m8n8.x4.trans.shared.b16 {%0,%1,%2,%3}, [%4];"
        : "=r"(r0), "=r"(r1), "=r"(r2), "=r"(r3) : "r"(addr));
}

// ---------------------------------------------------------------------------
// Warp-per-row LayerNorm helper (C = 512)
// ---------------------------------------------------------------------------
__device__ __forceinline__ void ln_row_warp(
    const float* __restrict__ xr, const float* __restrict__ g,
    const float* __restrict__ b, __half* __restrict__ outr, int lane)
{
    float4 v[4];
    float s = 0.f, ss = 0.f;
    #pragma unroll
    for (int i = 0; i < 4; i++) {
        v[i] = *reinterpret_cast<const float4*>(&xr[lane * 4 + i * 128]);
        s  += v[i].x + v[i].y + v[i].z + v[i].w;
        ss += v[i].x*v[i].x + v[i].y*v[i].y + v[i].z*v[i].z + v[i].w*v[i].w;
    }
    #pragma unroll
    for (int off = 16; off > 0; off >>= 1) {
        s  += __shfl_xor_sync(0xffffffffu, s,  off);
        ss += __shfl_xor_sync(0xffffffffu, ss, off);
    }
    const float mu   = s * (1.0f / CDIM);
    const float var  = ss * (1.0f / CDIM) - mu * mu;
    const float rstd = rsqrtf(var + 1e-5f);
    #pragma unroll
    for (int i = 0; i < 4; i++) {
        const int col = lane * 4 + i * 128;
        float4 gg = *reinterpret_cast<const float4*>(&g[col]);
        float4 bb = *reinterpret_cast<const float4*>(&b[col]);
        __half2* op = reinterpret_cast<__half2*>(&outr[col]);
        op[0] = __floats2half2_rn((v[i].x - mu) * rstd * gg.x + bb.x,
                                  (v[i].y - mu) * rstd * gg.y + bb.y);
        op[1] = __floats2half2_rn((v[i].z - mu) * rstd * gg.z + bb.z,
                                  (v[i].w - mu) * rstd * gg.w + bb.w);
    }
}

// ---------------------------------------------------------------------------
// Tiled transpose helper: 32x32 tile of W[K][N] -> Wt[N][K] (fp16)
// 256 threads: tx = tid&31, ty = tid>>5 (8 rows, x4 loop)
// ---------------------------------------------------------------------------
__device__ __forceinline__ void transpose_tile(
    const float* __restrict__ W, __half* __restrict__ Wt,
    int K, int N, int k0, int n0, int tid, float* sm /*32*33*/)
{
    const int tx = tid & 31, ty = tid >> 5;
    #pragma unroll
    for (int i = 0; i < 4; i++)
        sm[(ty + 8 * i) * 33 + tx] = W[(size_t)(k0 + ty + 8 * i) * N + n0 + tx];
    __syncthreads();
    #pragma unroll
    for (int i = 0; i < 4; i++)
        Wt[(size_t)(n0 + ty + 8 * i) * K + k0 + tx] =
            __float2half_rn(sm[tx * 33 + ty + 8 * i]);
}

// ---------------------------------------------------------------------------
// Fused prep: all 4 weight transposes + LN1, one launch, flat grid.
// blocks: [0,768) qkvT | [768,1024) wp | [1024,2048) w1 | [2048,3072) w2
//         [3072,5120) ln1 (8 rows per block, warp-per-row)
// ---------------------------------------------------------------------------
__global__ void __launch_bounds__(256) prep_fused(
    const float* __restrict__ wq, const float* __restrict__ wk,
    const float* __restrict__ wv, const float* __restrict__ w_proj,
    const float* __restrict__ w1, const float* __restrict__ w2,
    __half* __restrict__ wqkvT, __half* __restrict__ wpT,
    __half* __restrict__ w1T, __half* __restrict__ w2T,
    const float* __restrict__ x, const float* __restrict__ ln1_g,
    const float* __restrict__ ln1_b, __half* __restrict__ h)
{
    __shared__ float sm[32 * 33];
    const int bx  = blockIdx.x;
    const int tid = threadIdx.x;

    if (bx < 768) {
        // qkv fused transpose: (16 k-tiles) x (48 n-tiles)
        const int k0 = (bx & 15) * 32, n0 = (bx >> 4) * 32;
        const int part = n0 >> 9, hh = (n0 >> 6) & 7, d0 = n0 & 32;
        const float* w = (part == 0) ? wq : (part == 1 ? wk : wv);
        const int tx = tid & 31, ty = tid >> 5;
        #pragma unroll
        for (int i = 0; i < 4; i++)
            sm[(ty + 8 * i) * 33 + tx] =
                w[((size_t)(hh * CDIM + k0 + ty + 8 * i)) * 64 + d0 + tx];
        __syncthreads();
        #pragma unroll
        for (int i = 0; i < 4; i++)
            wqkvT[(size_t)(n0 + ty + 8 * i) * CDIM + k0 + tx] =
                __float2half_rn(sm[tx * 33 + ty + 8 * i]);
    } else if (bx < 1024) {
        const int idx = bx - 768;                   // 16 x 16
        transpose_tile(w_proj, wpT, CDIM, CDIM,
                       (idx & 15) * 32, (idx >> 4) * 32, tid, sm);
    } else if (bx < 2048) {
        const int idx = bx - 1024;                  // 16 k x 64 n
        transpose_tile(w1, w1T, CDIM, FFNDIM,
                       (idx & 15) * 32, (idx >> 4) * 32, tid, sm);
    } else if (bx < 3072) {
        const int idx = bx - 2048;                  // 64 k x 16 n
        transpose_tile(w2, w2T, FFNDIM, CDIM,
                       (idx & 63) * 32, (idx >> 6) * 32, tid, sm);
    } else {
        const int idx  = bx - 3072;                 // 2048 blocks x 8 rows
        const int warp = tid >> 5, lane = tid & 31;
        const int row  = idx * 8 + warp;
        ln_row_warp(x + (size_t)row * CDIM, ln1_g, ln1_b,
                    h + (size_t)row * CDIM, lane);
    }
}

// ---------------------------------------------------------------------------
// Standalone warp-per-row LayerNorm (LN2): 8 rows per 256-thread block
// ---------------------------------------------------------------------------
__global__ void __launch_bounds__(256) ln_rows(
    const float* __restrict__ x, const float* __restrict__ g,
    const float* __restrict__ b, __half* __restrict__ out)
{
    const int warp = threadIdx.x >> 5, lane = threadIdx.x & 31;
    const int row  = blockIdx.x * 8 + warp;
    ln_row_warp(x + (size_t)row * CDIM, g, b, out + (size_t)row * CDIM, lane);
}

// ---------------------------------------------------------------------------
// fp16 tensor-core GEMM: C[M,N] = A[M,K] @ Wt[N,K]^T (+bias)(+res)(relu)
// BM=BN=128, BK=64, 128 threads = 4 warps (2x2), warp tile 64x64.
// 3-stage cp.async pipeline; ldmatrix.x4 fragment loads.
// ---------------------------------------------------------------------------
#define FBM 128
#define FBK 64
#define LDHG 72                             // halves per smem row (144B)
#define TILE_H (FBM * LDHG)                 // 9216 halves = 18432 B per tile
#define NSTAGE 3
#define GSMEM_BYTES (NSTAGE * 2 * TILE_H * 2 + 1024 + 256)

template<typename OutT, bool BIAS, bool RELU, bool RES>
__global__ void __launch_bounds__(128, 2) gemm_f16(
    const __half* __restrict__ A, const __half* __restrict__ Bw,
    const float* __restrict__ bias, const float* __restrict__ res,
    OutT* __restrict__ C, int M, int N, int K)
{
    extern __shared__ char dsm[];
    __half* As = reinterpret_cast<__half*>(dsm);
    __half* Bs = As + NSTAGE * TILE_H;
    float* bias_s = reinterpret_cast<float*>(Bs + NSTAGE * TILE_H);

    const int tid  = threadIdx.x;
    const int w    = tid >> 5;
    const int lane = tid & 31;
    const int g    = lane >> 2;
    const int tg   = lane & 3;

    const int m0 = blockIdx.y * FBM;
    const int n0 = blockIdx.x * FBM;
    const int wm = (w & 1) * 64;
    const int wn = (w >> 1) * 64;

    if (BIAS) bias_s[tid] = bias[n0 + tid];

    float acc[4][8][4];
    #pragma unroll
    for (int mt = 0; mt < 4; mt++)
        #pragma unroll
        for (int nt = 0; nt < 8; nt++)
            #pragma unroll
            for (int i = 0; i < 4; i++) acc[mt][nt][i] = 0.0f;

    const uint32_t as_base = smem_u32(As);
    const uint32_t bs_base = smem_u32(Bs);

    auto load_tile = [&](int buf, int k0) {
        const uint32_t a_s = as_base + buf * TILE_H * 2;
        const uint32_t b_s = bs_base + buf * TILE_H * 2;
        #pragma unroll
        for (int j = 0; j < 8; j++) {
            int c = tid + 128 * j;
            int row = c >> 3, ch = c & 7;
            cp16(a_s + row * (LDHG * 2) + ch * 16,
                 A + (size_t)(m0 + row) * K + k0 + ch * 8);
            cp16(b_s + row * (LDHG * 2) + ch * 16,
                 Bw + (size_t)(n0 + row) * K + k0 + ch * 8);
        }
        cp_commit();
    };

    const int NIT = K / FBK;
    load_tile(0, 0);
    load_tile(1, FBK);
    load_tile(2, 2 * FBK);

    const int a_row = lane & 15;
    const int a_kof = (lane & 16) ? 8 : 0;
    const int b_row = (lane & 7) + ((lane & 16) ? 8 : 0);
    const int b_kof = (lane & 8) ? 8 : 0;

    for (int it = 0; it < NIT; it++) {
        const int buf = it % NSTAGE;
        if (it + 2 < NIT)      cp_wait<2>();
        else if (it + 1 < NIT) cp_wait<1>();
        else                   cp_wait<0>();
        __syncthreads();

        const __half* Ab = As + buf * TILE_H;
        const __half* Bb = Bs + buf * TILE_H;

        #pragma unroll
        for (int ks = 0; ks < 4; ks++) {
            const int kb = ks * 16;
            uint32_t af[4][4], bf[8][2];
            #pragma unroll
            for (int mt = 0; mt < 4; mt++) {
                uint32_t addr = smem_u32(
                    &Ab[(wm + mt * 16 + a_row) * LDHG + kb + a_kof]);
                ldmx4(af[mt][0], af[mt][1], af[mt][2], af[mt][3], addr);
            }
            #pragma unroll
            for (int p = 0; p < 4; p++) {
                uint32_t addr = smem_u32(
                    &Bb[(wn + p * 16 + b_row) * LDHG + kb + b_kof]);
                ldmx4(bf[2*p][0], bf[2*p][1], bf[2*p+1][0], bf[2*p+1][1], addr);
            }
            #pragma unroll
            for (int mt = 0; mt < 4; mt++)
                #pragma unroll
                for (int nt = 0; nt < 8; nt++)
                    mma_f16(acc[mt][nt], af[mt], bf[nt]);
        }
        __syncthreads();

        if (it + 3 < NIT) load_tile(buf, (it + 3) * FBK);
    }

    // Epilogue
    #pragma unroll
    for (int mt = 0; mt < 4; mt++) {
        #pragma unroll
        for (int nt = 0; nt < 8; nt++) {
            const int col = n0 + wn + nt * 8 + 2 * tg;
            float2 bb = make_float2(0.f, 0.f);
            if (BIAS) {
                bb.x = bias_s[wn + nt * 8 + 2 * tg];
                bb.y = bias_s[wn + nt * 8 + 2 * tg + 1];
            }
            #pragma unroll
            for (int half_i = 0; half_i < 2; half_i++) {
                const int row = m0 + wm + mt * 16 + g + half_i * 8;
                float2 v = make_float2(acc[mt][nt][half_i * 2 + 0],
                                       acc[mt][nt][half_i * 2 + 1]);
                if (BIAS) { v.x += bb.x; v.y += bb.y; }
                if (RES) {
                    float2 rr = *reinterpret_cast<const float2*>(
                        &res[(size_t)row * N + col]);
                    v.x += rr.x; v.y += rr.y;
                }
                if (RELU) { v.x = fmaxf(v.x, 0.f); v.y = fmaxf(v.y, 0.f); }
                if (sizeof(OutT) == 2) {
                    *reinterpret_cast<__half2*>(
                        reinterpret_cast<__half*>(C) + (size_t)row * N + col) =
                        __floats2half2_rn(v.x, v.y);
                } else {
                    *reinterpret_cast<float2*>(
                        reinterpret_cast<float*>(C) + (size_t)row * N + col) = v;
                }
            }
        }
    }
}

// ---------------------------------------------------------------------------
// fp16 tensor-core causal flash attention; ldmatrix fragment loads.
// ---------------------------------------------------------------------------
#define ALH 72
#define AQ_H (64 * ALH)
#define AK_H (64 * ALH)
#define AV_H (64 * ALH)
#define AP_H (16 * ALH)
#define ATTN_SMEM_BYTES ((AQ_H + 2*AK_H + 2*AV_H + 4*AP_H) * 2)

__global__ void __launch_bounds__(128) attn_f16(
    const __half* __restrict__ qkv, __half* __restrict__ o)
{
    extern __shared__ __half hsm[];
    __half* Qs = hsm;
    __half* Ks = Qs + AQ_H;
    __half* Vs = Ks + 2 * AK_H;
    __half* Ps = Vs + 2 * AV_H;

    const int qt  = (int)gridDim.x - 1 - (int)blockIdx.x;
    const int bh  = blockIdx.y;
    const int b   = bh >> 3;
    const int h   = bh & 7;
    const int tid = threadIdx.x;
    const int w   = tid >> 5;
    const int lane = tid & 31;
    const int g    = lane >> 2;
    const int tg   = lane & 3;
    const int q0  = qt * 64;

    const float scale = 0.04419417382415922f;   // 1/sqrt(512)

    const __half* qbase = qkv + ((size_t)(b * SEQ + q0)) * QKVN + h * DHEAD;
    const __half* kbase = qkv + ((size_t)b * SEQ) * QKVN + 512  + h * DHEAD;
    const __half* vbase = qkv + ((size_t)b * SEQ) * QKVN + 1024 + h * DHEAD;

    {
        const uint32_t qs = smem_u32(Qs);
        #pragma unroll
        for (int i = 0; i < 4; i++) {
            int c = tid + i * 128;
            int row = c >> 3, ch = c & 7;
            cp16(qs + row * (ALH * 2) + ch * 16,
                 qbase + (size_t)row * QKVN + ch * 8);
        }
        cp_commit();
    }

    auto issue_kv = [&](int buf, int j0) {
        const uint32_t ks = smem_u32(Ks + buf * AK_H);
        const uint32_t vs = smem_u32(Vs + buf * AV_H);
        #pragma unroll
        for (int i = 0; i < 4; i++) {
            int c = tid + i * 128;
            int row = c >> 3, ch = c & 7;
            cp16(ks + row * (ALH * 2) + ch * 16,
                 kbase + (size_t)(j0 + row) * QKVN + ch * 8);
            cp16(vs + row * (ALH * 2) + ch * 16,
                 vbase + (size_t)(j0 + row) * QKVN + ch * 8);
        }
        cp_commit();
    };

    issue_kv(0, 0);
    cp_wait<0>();
    __syncthreads();

    const int a_row = lane & 15;
    const int a_kof = (lane & 16) ? 8 : 0;
    const int b_row = (lane & 7) + ((lane & 16) ? 8 : 0);
    const int b_kof = (lane & 8) ? 8 : 0;

    uint32_t qf[4][4];
    #pragma unroll
    for (int kb = 0; kb < 4; kb++) {
        uint32_t addr = smem_u32(&Qs[(w * 16 + a_row) * ALH + kb * 16 + a_kof]);
        ldmx4(qf[kb][0], qf[kb][1], qf[kb][2], qf[kb][3], addr);
    }

    float oacc[8][4];
    #pragma unroll
    for (int nt = 0; nt < 8; nt++)
        #pragma unroll
        for (int i = 0; i < 4; i++) oacc[nt][i] = 0.0f;
    float m_lo = -INFINITY, m_hi = -INFINITY;
    float l_lo = 0.0f, l_hi = 0.0f;

    __half* Pw = Ps + w * AP_H;
    const int ntiles = qt + 1;

    for (int it = 0; it < ntiles; it++) {
        if (it + 1 < ntiles) {
            issue_kv((it + 1) & 1, (it + 1) * 64);
            cp_wait<1>();
        } else {
            cp_wait<0>();
        }
        __syncthreads();

        const __half* Kb = Ks + (it & 1) * AK_H;
        const __half* Vb = Vs + (it & 1) * AV_H;

        float sacc[8][4];
        #pragma unroll
        for (int nt = 0; nt < 8; nt++)
            #pragma unroll
            for (int i = 0; i < 4; i++) sacc[nt][i] = 0.0f;

        #pragma unroll
        for (int kb = 0; kb < 4; kb++) {
            uint32_t bf[8][2];
            #pragma unroll
            for (int p = 0; p < 4; p++) {
                uint32_t addr = smem_u32(
                    &Kb[(p * 16 + b_row) * ALH + kb * 16 + b_kof]);
                ldmx4(bf[2*p][0], bf[2*p][1], bf[2*p+1][0], bf[2*p+1][1], addr);
            }
            #pragma unroll
            for (int nt = 0; nt < 8; nt++)
                mma_f16(sacc[nt], qf[kb], bf[nt]);
        }

        const int j0 = it * 64;
        const bool diag = (it == ntiles - 1) && (j0 == q0);
        const int qr_lo = q0 + w * 16 + g;
        const int qr_hi = qr_lo + 8;
        #pragma unroll
        for (int nt = 0; nt < 8; nt++) {
            const int c0 = j0 + nt * 8 + 2 * tg;
            sacc[nt][0] = (diag && c0     > qr_lo) ? -INFINITY : sacc[nt][0] * scale;
            sacc[nt][1] = (diag && c0 + 1 > qr_lo) ? -INFINITY : sacc[nt][1] * scale;
            sacc[nt][2] = (diag && c0     > qr_hi) ? -INFINITY : sacc[nt][2] * scale;
            sacc[nt][3] = (diag && c0 + 1 > qr_hi) ? -INFINITY : sacc[nt][3] * scale;
        }

        float mx_lo = -INFINITY, mx_hi = -INFINITY;
        #pragma unroll
        for (int nt = 0; nt < 8; nt++) {
            mx_lo = fmaxf(mx_lo, fmaxf(sacc[nt][0], sacc[nt][1]));
            mx_hi = fmaxf(mx_hi, fmaxf(sacc[nt][2], sacc[nt][3]));
        }
        mx_lo = fmaxf(mx_lo, __shfl_xor_sync(0xffffffffu, mx_lo, 1));
        mx_lo = fmaxf(mx_lo, __shfl_xor_sync(0xffffffffu, mx_lo, 2));
        mx_hi = fmaxf(mx_hi, __shfl_xor_sync(0xffffffffu, mx_hi, 1));
        mx_hi = fmaxf(mx_hi, __shfl_xor_sync(0xffffffffu, mx_hi, 2));

        const float mn_lo = fmaxf(m_lo, mx_lo);
        const float mn_hi = fmaxf(m_hi, mx_hi);
        const float c_lo = __expf(m_lo - mn_lo);
        const float c_hi = __expf(m_hi - mn_hi);
        m_lo = mn_lo; m_hi = mn_hi;

        float ts_lo = 0.0f, ts_hi = 0.0f;
        #pragma unroll
        for (int nt = 0; nt < 8; nt++) {
            float p0 = __expf(sacc[nt][0] - m_lo);
            float p1 = __expf(sacc[nt][1] - m_lo);
            float p2 = __expf(sacc[nt][2] - m_hi);
            float p3 = __expf(sacc[nt][3] - m_hi);
            ts_lo += p0 + p1;
            ts_hi += p2 + p3;
            *reinterpret_cast<__half2*>(&Pw[(g    ) * ALH + nt * 8 + 2 * tg]) =
                __floats2half2_rn(p0, p1);
            *reinterpret_cast<__half2*>(&Pw[(g + 8) * ALH + nt * 8 + 2 * tg]) =
                __floats2half2_rn(p2, p3);
        }
        ts_lo += __shfl_xor_sync(0xffffffffu, ts_lo, 1);
        ts_lo += __shfl_xor_sync(0xffffffffu, ts_lo, 2);
        ts_hi += __shfl_xor_sync(0xffffffffu, ts_hi, 1);
        ts_hi += __shfl_xor_sync(0xffffffffu, ts_hi, 2);
        l_lo = l_lo * c_lo + ts_lo;
        l_hi = l_hi * c_hi + ts_hi;

        #pragma unroll
        for (int nt = 0; nt < 8; nt++) {
            oacc[nt][0] *= c_lo; oacc[nt][1] *= c_lo;
            oacc[nt][2] *= c_hi; oacc[nt][3] *= c_hi;
        }
        __syncwarp();

        #pragma unroll
        for (int kt = 0; kt < 4; kt++) {
            uint32_t af[4];
            {
                uint32_t addr = smem_u32(&Pw[a_row * ALH + kt * 16 + a_kof]);
                ldmx4(af[0], af[1], af[2], af[3], addr);
            }
            #pragma unroll
            for (int nt = 0; nt < 8; nt += 2) {
                const int vrow = kt * 16 + (lane & 15);
                const int vcol = (nt + (lane >> 4)) * 8;
                uint32_t addr = smem_u32(&Vb[vrow * ALH + vcol]);
                uint32_t b0, b1, b2, b3;
                ldmx4_trans(b0, b1, b2, b3, addr);
                uint32_t bf0[2] = {b0, b1};
                uint32_t bf1[2] = {b2, b3};
                mma_f16(oacc[nt],     af, bf0);
                mma_f16(oacc[nt + 1], af, bf1);
            }
        }
        __syncthreads();
    }

    const float inv_lo = 1.0f / l_lo;
    const float inv_hi = 1.0f / l_hi;
    const int qr = q0 + w * 16 + g;
    __half* orow_lo = o + ((size_t)(b * SEQ + qr    )) * CDIM + h * DHEAD;
    __half* orow_hi = o + ((size_t)(b * SEQ + qr + 8)) * CDIM + h * DHEAD;
    #pragma unroll
    for (int nt = 0; nt < 8; nt++) {
        const int col = nt * 8 + 2 * tg;
        *reinterpret_cast<__half2*>(&orow_lo[col]) =
            __floats2half2_rn(oacc[nt][0] * inv_lo, oacc[nt][1] * inv_lo);
        *reinterpret_cast<__half2*>(&orow_hi[col]) =
            __floats2half2_rn(oacc[nt][2] * inv_hi, oacc[nt][3] * inv_hi);
    }
}

// ---------------------------------------------------------------------------
// Launch. Inputs: 0:x 1:wq 2:wk 3:wv 4:w_proj 5:b_proj 6:w1 7:b1 8:w2 9:b2
//                 10:ln1_g 11:ln1_b 12:ln2_g 13:ln2_b
// ---------------------------------------------------------------------------
extern "C" void kernel_launch(void* const* d_in, const int* in_sizes, int n_in,
                              void* d_out, int out_size)
{
    const float* x      = (const float*)d_in[0];
    const float* wq     = (const float*)d_in[1];
    const float* wk     = (const float*)d_in[2];
    const float* wv     = (const float*)d_in[3];
    const float* w_proj = (const float*)d_in[4];
    const float* b_proj = (const float*)d_in[5];
    const float* w1     = (const float*)d_in[6];
    const float* b1     = (const float*)d_in[7];
    const float* w2     = (const float*)d_in[8];
    const float* b2     = (const float*)d_in[9];
    const float* ln1_g  = (const float*)d_in[10];
    const float* ln1_b  = (const float*)d_in[11];
    const float* ln2_g  = (const float*)d_in[12];
    const float* ln2_b  = (const float*)d_in[13];
    float* out = (float*)d_out;

    __half *h, *qkv, *ob, *h2, *ffn, *w_qkvT, *w_pT, *w_1T, *w_2T;
    cudaGetSymbolAddress((void**)&h,      g_h);
    cudaGetSymbolAddress((void**)&qkv,    g_qkv);
    cudaGetSymbolAddress((void**)&ob,     g_o);
    cudaGetSymbolAddress((void**)&h2,     g_h2);
    cudaGetSymbolAddress((void**)&ffn,    g_ffn);
    cudaGetSymbolAddress((void**)&w_qkvT, g_wqkv);
    cudaGetSymbolAddress((void**)&w_pT,   g_wp);
    cudaGetSymbolAddress((void**)&w_1T,   g_w1);
    cudaGetSymbolAddress((void**)&w_2T,   g_w2);

    static bool attrs_set = false;
    if (!attrs_set) {
        cudaFuncSetAttribute(attn_f16,
            cudaFuncAttributeMaxDynamicSharedMemorySize, ATTN_SMEM_BYTES);
        cudaFuncSetAttribute(gemm_f16<__half, false, false, false>,
            cudaFuncAttributeMaxDynamicSharedMemorySize, GSMEM_BYTES);
        cudaFuncSetAttribute(gemm_f16<float, true, false, true>,
            cudaFuncAttributeMaxDynamicSharedMemorySize, GSMEM_BYTES);
        cudaFuncSetAttribute(gemm_f16<__half, true, true, false>,
            cudaFuncAttributeMaxDynamicSharedMemorySize, GSMEM_BYTES);
        attrs_set = true;
    }

    const int M = MROWS;

    // Fused: all weight transposes + ln1 (one launch, concurrent)
    prep_fused<<<5120, 256>>>(wq, wk, wv, w_proj, w1, w2,
                              w_qkvT, w_pT, w_1T, w_2T,
                              x, ln1_g, ln1_b, h);

    // fused qkv projection (fp16 out)
    gemm_f16<__half, false, false, false>
        <<<dim3(QKVN / FBM, M / FBM), 128, GSMEM_BYTES>>>(
        h, w_qkvT, nullptr, nullptr, qkv, M, QKVN, CDIM);

    // fp16 causal attention
    attn_f16<<<dim3(SEQ / 64, BATCH * NHEAD), 128, ATTN_SMEM_BYTES>>>(qkv, ob);

    // x2 = x + o @ w_proj + b_proj -> out (fp32)
    gemm_f16<float, true, false, true>
        <<<dim3(CDIM / FBM, M / FBM), 128, GSMEM_BYTES>>>(
        ob, w_pT, b_proj, x, out, M, CDIM, CDIM);

    // ln2 (fp16 out, warp-per-row)
    ln_rows<<<MROWS / 8, 256>>>(out, ln2_g, ln2_b, h2);

    // ffn1 = relu(h2 @ w1 + b1) (fp16 out)
    gemm_f16<__half, true, true, false>
        <<<dim3(FFNDIM / FBM, M / FBM), 128, GSMEM_BYTES>>>(
        h2, w_1T, b1, nullptr, ffn, M, FFNDIM, CDIM);

    // out = out + ffn1 @ w2 + b2 (fp32)
    gemm_f16<float, true, false, true>
        <<<dim3(CDIM / FBM, M / FBM), 128, GSMEM_BYTES>>>(
        ffn, w_2T, b2, out, out, M, CDIM, FFNDIM);
}